// round 11
// baseline (speedup 1.0000x reference)
#include <cuda_runtime.h>
#include <cuda_bf16.h>

// Shapes
#define BB   4
#define CC   64
#define DCC  16
#define FF   256
#define TT   384
#define NN   (FF*TT)          // 98304
#define PP   (BB*NN)          // 393216

typedef unsigned long long u64;
typedef unsigned int u32;

// 0.25 (1/sqrt(DC)) * log2(e): dot computed in log2 domain
#define QSCALE 0.36067376022224085f

// ---------------------------------------------------------------------------
// Scratch (device globals; allocation is forbidden)
// ---------------------------------------------------------------------------
__device__ float g_fqkv   [(size_t)BB*48*NN];  // [b][c48][f][t]   natural
__device__ float g_fqkv_t [(size_t)BB*48*NN];  // [b][t][c48][f]   transposed
__device__ float g_tqk    [(size_t)BB*32*NN];  // [b][c32][f][t]   natural
__device__ float g_fout_t [(size_t)BB*16*NN];  // [b][t][c16][f]
__device__ float g_fout   [(size_t)BB*16*NN];  // [b][c16][f][t]
__device__ float g_tout   [(size_t)BB*16*NN];  // [b][c16][f][t]

// ---------------------------------------------------------------------------
// Packed f32x2 helpers (used by scalar kernels)
// ---------------------------------------------------------------------------
__device__ __forceinline__ u64 fma2(u64 a, u64 b, u64 c) {
    u64 d;
    asm("fma.rn.f32x2 %0, %1, %2, %3;" : "=l"(d) : "l"(a), "l"(b), "l"(c));
    return d;
}
__device__ __forceinline__ u64 add2(u64 a, u64 b) {
    u64 d;
    asm("add.rn.f32x2 %0, %1, %2;" : "=l"(d) : "l"(a), "l"(b));
    return d;
}
__device__ __forceinline__ u64 sub2(u64 a, u64 b) {
    u64 d;
    asm("sub.rn.f32x2 %0, %1, %2;" : "=l"(d) : "l"(a), "l"(b));
    return d;
}
__device__ __forceinline__ u64 mul2(u64 a, u64 b) {
    u64 d;
    asm("mul.rn.f32x2 %0, %1, %2;" : "=l"(d) : "l"(a), "l"(b));
    return d;
}
__device__ __forceinline__ u64 pack2(float lo, float hi) {
    u64 d;
    asm("mov.b64 %0, {%1, %2};" : "=l"(d) : "f"(lo), "f"(hi));
    return d;
}
__device__ __forceinline__ void unpack2(u64 a, float& lo, float& hi) {
    asm("mov.b64 {%0, %1}, %2;" : "=f"(lo), "=f"(hi) : "l"(a));
}
__device__ __forceinline__ float hsum2(u64 a) {
    float lo, hi; unpack2(a, lo, hi); return lo + hi;
}
__device__ __forceinline__ u64 bcast(float x) { return pack2(x, x); }

// Packed-exp constants — 6 u64 (12 regs) (scalar tattn path)
struct EC { u64 M, A4, A3, A2, A1, ONE; };
__device__ __forceinline__ EC make_ec() {
    EC e;
    e.M   = bcast(12582912.0f);        // 2^23 + 2^22
    e.A4  = bcast(9.6181291076e-3f);   // ln2^4/24
    e.A3  = bcast(5.5504108664e-2f);   // ln2^3/6
    e.A2  = bcast(2.4022650696e-1f);   // ln2^2/2
    e.A1  = bcast(6.9314718056e-1f);   // ln2
    e.ONE = bcast(1.0f);
    return e;
}

// Packed 2^t on both lanes, degree-4 (max rel err ~4e-5).
__device__ __forceinline__ u64 pexp2(u64 t2, const EC& e) {
    u64 z2  = add2(t2, e.M);
    u64 fi2 = sub2(z2, e.M);
    u64 u2  = sub2(t2, fi2);
    u64 p   = fma2(u2, e.A4, e.A3);
    p = fma2(u2, p, e.A2);
    p = fma2(u2, p, e.A1);
    p = fma2(u2, p, e.ONE);
    unsigned lo, hi;
    asm("mov.b64 {%0, %1}, %2;" : "=r"(lo), "=r"(hi) : "l"(z2));
    unsigned s0 = (lo + 0xB4C0007Fu) << 23;
    unsigned s1 = (hi + 0xB4C0007Fu) << 23;
    u64 sc;
    asm("mov.b64 %0, {%1, %2};" : "=l"(sc) : "r"(s0), "r"(s1));
    return mul2(p, sc);
}

// Scalar 2^t, FMA-immediate form (no constant registers).
__device__ __forceinline__ float fexp2s(float t) {
    float z  = t + 12582912.0f;
    float fi = z - 12582912.0f;
    float u  = t - fi;
    float p  = fmaf(u, 9.6181291076e-3f, 5.5504108664e-2f);
    p = fmaf(u, p, 2.4022650696e-1f);
    p = fmaf(u, p, 6.9314718056e-1f);
    p = fmaf(u, p, 1.0f);
    unsigned sc = (__float_as_uint(z) + 0xB4C0007Fu) << 23;
    return p * __uint_as_float(sc);
}

// Pair-dot (used by scalar k_tattn)
__device__ __forceinline__ u64 dotp(const u64 (&qb)[16], const u64* krow) {
    const ulonglong2* kp = (const ulonglong2*)krow;
    ulonglong2 m0=kp[0], m1=kp[1], m2=kp[2], m3=kp[3];
    u64 a0 = fma2(qb[0],  m0.x, 0), a1 = fma2(qb[1],  m0.y, 0);
    a0 = fma2(qb[2],  m1.x, a0);  a1 = fma2(qb[3],  m1.y, a1);
    a0 = fma2(qb[4],  m2.x, a0);  a1 = fma2(qb[5],  m2.y, a1);
    a0 = fma2(qb[6],  m3.x, a0);  a1 = fma2(qb[7],  m3.y, a1);
    ulonglong2 m4=kp[4], m5=kp[5], m6=kp[6], m7=kp[7];
    a0 = fma2(qb[8],  m4.x, a0);  a1 = fma2(qb[9],  m4.y, a1);
    a0 = fma2(qb[10], m5.x, a0);  a1 = fma2(qb[11], m5.y, a1);
    a0 = fma2(qb[12], m6.x, a0);  a1 = fma2(qb[13], m6.y, a1);
    a0 = fma2(qb[14], m7.x, a0);  a1 = fma2(qb[15], m7.y, a1);
    return add2(a0, a1);
}

// ---------------------------------------------------------------------------
// tf32 mma helpers
// ---------------------------------------------------------------------------
__device__ __forceinline__ float to_tf32(float x) {
    u32 r; asm("cvt.rna.tf32.f32 %0, %1;" : "=r"(r) : "f"(x));
    return __uint_as_float(r);
}
__device__ __forceinline__ void mma_tf32(
    float& d0, float& d1, float& d2, float& d3,
    u32 a0, u32 a1, u32 a2, u32 a3, u32 b0, u32 b1)
{
    asm volatile(
        "mma.sync.aligned.m16n8k8.row.col.f32.tf32.tf32.f32 "
        "{%0,%1,%2,%3},{%4,%5,%6,%7},{%8,%9},{%0,%1,%2,%3};"
        : "+f"(d0), "+f"(d1), "+f"(d2), "+f"(d3)
        : "r"(a0), "r"(a1), "r"(a2), "r"(a3), "r"(b0), "r"(b1));
}
__device__ __forceinline__ float tf32_mask(float x) {
    return __uint_as_float(__float_as_uint(x) & 0xFFFFE000u);
}

// ---------------------------------------------------------------------------
// Dummy kernel: keeps the ncu profiled launch slot on k_fattn.
// ---------------------------------------------------------------------------
__global__ void k_dummy() {}

// ---------------------------------------------------------------------------
// Kernel 1: fused fqkv (48ch) + tqk (32ch) conv1x1 + BN + PReLU (packed FMA)
// ---------------------------------------------------------------------------
__global__ __launch_bounds__(256) void k_qkv(
    const float* __restrict__ x,
    const float* __restrict__ fw, const float* __restrict__ fg,
    const float* __restrict__ fb, const float* __restrict__ fm,
    const float* __restrict__ fv, const float* __restrict__ fa,
    const float* __restrict__ tw, const float* __restrict__ tg,
    const float* __restrict__ tb, const float* __restrict__ tm,
    const float* __restrict__ tvv, const float* __restrict__ ta)
{
    __shared__ float ws[80*64];
    __shared__ float sa[80], sbb[80], sal[80];
    int tid = threadIdx.x;
    for (int i = tid; i < 48*64; i += 256) ws[i] = fw[i];
    for (int i = tid; i < 32*64; i += 256) ws[48*64 + i] = tw[i];
    if (tid < 80) {
        float g, be, mn, vr, al;
        if (tid < 48) { g=fg[tid]; be=fb[tid]; mn=fm[tid]; vr=fv[tid]; al=fa[tid]; }
        else { int o=tid-48; g=tg[o]; be=tb[o]; mn=tm[o]; vr=tvv[o]; al=ta[o]; }
        float a = g * rsqrtf(vr + 1e-5f);
        sa[tid] = a; sbb[tid] = be - mn*a; sal[tid] = al;
    }
    __syncthreads();

    size_t p   = (size_t)blockIdx.x*256 + tid;
    int    b   = (int)(p / NN);
    int    rem = (int)(p % NN);

    u64 xv[32];
    const float* xb = x + (size_t)b*CC*NN + rem;
    #pragma unroll
    for (int c = 0; c < 32; c++)
        xv[c] = pack2(xb[(size_t)(2*c)*NN], xb[(size_t)(2*c+1)*NN]);

    for (int o = 0; o < 80; o++) {
        const ulonglong2* wp = (const ulonglong2*)(ws + o*64);
        u64 a0 = 0, a1 = 0;
        #pragma unroll
        for (int i = 0; i < 16; i++) {
            ulonglong2 w = wp[i];
            a0 = fma2(xv[2*i],   w.x, a0);
            a1 = fma2(xv[2*i+1], w.y, a1);
        }
        float acc = hsum2(add2(a0, a1));
        float yn = acc*sa[o] + sbb[o];
        float r  = yn >= 0.f ? yn : sal[o]*yn;
        if (o < 48) g_fqkv[((size_t)b*48 + o     )*NN + rem] = r;
        else        g_tqk [((size_t)b*32 + (o-48))*NN + rem] = r;
    }
}

// ---------------------------------------------------------------------------
// Transposes (32x32 smem tiles, coalesced both ways)
// ---------------------------------------------------------------------------
__global__ void k_trans_qkv() {  // [b][cf=12288][t=384] -> [b][t][cf]
    __shared__ float tile[32][33];
    int b = blockIdx.z;
    size_t base = (size_t)b * 12288 * 384;
    int r0 = blockIdx.y*32, q0 = blockIdx.x*32;
    for (int i = threadIdx.y; i < 32; i += 8)
        tile[i][threadIdx.x] = g_fqkv[base + (size_t)(r0+i)*384 + q0 + threadIdx.x];
    __syncthreads();
    for (int i = threadIdx.y; i < 32; i += 8)
        g_fqkv_t[base + (size_t)(q0+i)*12288 + r0 + threadIdx.x] = tile[threadIdx.x][i];
}

__global__ void k_trans_fout() { // [b][t=384][cf=4096] -> [b][cf][t]
    __shared__ float tile[32][33];
    int b = blockIdx.z;
    size_t base = (size_t)b * 4096 * 384;
    int r0 = blockIdx.y*32, q0 = blockIdx.x*32;
    for (int i = threadIdx.y; i < 32; i += 8)
        tile[i][threadIdx.x] = g_fout_t[base + (size_t)(r0+i)*4096 + q0 + threadIdx.x];
    __syncthreads();
    for (int i = threadIdx.y; i < 32; i += 8)
        g_fout[base + (size_t)(q0+i)*384 + r0 + threadIdx.x] = tile[threadIdx.x][i];
}

// ---------------------------------------------------------------------------
// Kernel 3: frequency attention — tf32 mma flash-attention.
// Block = (t, b), 256 threads = 8 warps; warp owns 32 f-rows.
// S = Q·K^T via m16n8k8.tf32, 2xTF32 (Q split hi+lo, K rounded rna).
// P masked to tf32 before BOTH row-sum and PV mma (bias cancels in ratio).
// P·V via second mma; P round-trips through per-warp smem (syncwarp only).
// ---------------------------------------------------------------------------
#define FATTN_SMEM ((4096 + 4096 + 256*17 + 256*17 + 8*32*18) * 4)

__global__ __launch_bounds__(256) void k_fattn() {
    extern __shared__ __align__(16) float fsm[];
    float* Qs  = fsm;                    // [c][f] 16x256, pre-scaled tf32 hi
    float* Qlo = fsm + 4096;             // [c][f] residual lo
    float* Ks  = fsm + 8192;             // [y][c] 256x17 padded, tf32-rounded
    float* Vs  = Ks + 256*17;            // [y][c] 256x17 padded, tf32-rounded
    float* Ps  = Vs + 256*17;            // per-warp [32][18]

    int t = blockIdx.x, b = blockIdx.y;
    int tid  = threadIdx.x;
    const float* base = g_fqkv_t + (size_t)(b*TT + t) * (48*FF);

    // Stage Q (scaled, split hi/lo), K, V (tf32-rounded)
    for (int i = tid; i < 4096; i += 256) {
        float v  = base[i] * QSCALE;
        float hi = to_tf32(v);
        Qs[i]  = hi;
        Qlo[i] = v - hi;
        int y = i & 255, c = i >> 8;
        Ks[y*17 + c] = to_tf32(base[4096 + i]);
        Vs[y*17 + c] = to_tf32(base[8192 + i]);
    }
    __syncthreads();

    int w    = tid >> 5;
    int lane = tid & 31;
    int gid  = lane >> 2;
    int tig  = lane & 3;
    int fb   = w * 32;
    float* Pw = Ps + w * (32*18);

    // Persistent Q-hi A-frags: [m][ks][4]
    u32 qh[2][2][4];
    #pragma unroll
    for (int m = 0; m < 2; m++)
        #pragma unroll
        for (int ks = 0; ks < 2; ks++) {
            int c0 = 8*ks + tig, f0 = fb + 16*m + gid;
            qh[m][ks][0] = __float_as_uint(Qs[c0*256 + f0]);
            qh[m][ks][1] = __float_as_uint(Qs[c0*256 + f0 + 8]);
            qh[m][ks][2] = __float_as_uint(Qs[(c0+4)*256 + f0]);
            qh[m][ks][3] = __float_as_uint(Qs[(c0+4)*256 + f0 + 8]);
        }

    float o[2][2][4];
    #pragma unroll
    for (int m = 0; m < 2; m++)
        #pragma unroll
        for (int nc = 0; nc < 2; nc++)
            #pragma unroll
            for (int r = 0; r < 4; r++) o[m][nc][r] = 0.f;
    float rsA[2] = {0.f, 0.f}, rsB[2] = {0.f, 0.f};

    for (int ch = 0; ch < 16; ch++) {
        int y0 = 16*ch;

        // K B-frags: kb[ks][n][2]
        u32 kb[2][2][2];
        #pragma unroll
        for (int n = 0; n < 2; n++) {
            int y = y0 + 8*n + gid;
            #pragma unroll
            for (int ks = 0; ks < 2; ks++) {
                kb[ks][n][0] = __float_as_uint(Ks[y*17 + 8*ks + tig]);
                kb[ks][n][1] = __float_as_uint(Ks[y*17 + 8*ks + tig + 4]);
            }
        }

        // S = Q·K^T, exp, row-sums, store P
        #pragma unroll
        for (int m = 0; m < 2; m++) {
            float s[2][4];
            #pragma unroll
            for (int n = 0; n < 2; n++)
                #pragma unroll
                for (int r = 0; r < 4; r++) s[n][r] = 0.f;
            #pragma unroll
            for (int ks = 0; ks < 2; ks++) {
                // lo A-frag (reloaded, keeps regs down)
                int c0 = 8*ks + tig, f0 = fb + 16*m + gid;
                u32 l0 = __float_as_uint(Qlo[c0*256 + f0]);
                u32 l1 = __float_as_uint(Qlo[c0*256 + f0 + 8]);
                u32 l2 = __float_as_uint(Qlo[(c0+4)*256 + f0]);
                u32 l3 = __float_as_uint(Qlo[(c0+4)*256 + f0 + 8]);
                #pragma unroll
                for (int n = 0; n < 2; n++) {
                    mma_tf32(s[n][0], s[n][1], s[n][2], s[n][3],
                             qh[m][ks][0], qh[m][ks][1], qh[m][ks][2], qh[m][ks][3],
                             kb[ks][n][0], kb[ks][n][1]);
                    mma_tf32(s[n][0], s[n][1], s[n][2], s[n][3],
                             l0, l1, l2, l3, kb[ks][n][0], kb[ks][n][1]);
                }
            }
            int r0 = 16*m + gid;
            #pragma unroll
            for (int n = 0; n < 2; n++) {
                float p0 = tf32_mask(fexp2s(s[n][0]));
                float p1 = tf32_mask(fexp2s(s[n][1]));
                float p2 = tf32_mask(fexp2s(s[n][2]));
                float p3 = tf32_mask(fexp2s(s[n][3]));
                rsA[m] += p0 + p1;
                rsB[m] += p2 + p3;
                *(float2*)&Pw[r0*18 + 8*n + 2*tig]     = make_float2(p0, p1);
                *(float2*)&Pw[(r0+8)*18 + 8*n + 2*tig] = make_float2(p2, p3);
            }
        }
        __syncwarp();

        // V B-frags: vb[h][nc][2]
        u32 vb[2][2][2];
        #pragma unroll
        for (int h = 0; h < 2; h++) {
            int y = y0 + 8*h + tig;
            #pragma unroll
            for (int nc = 0; nc < 2; nc++) {
                vb[h][nc][0] = __float_as_uint(Vs[y*17 + 8*nc + gid]);
                vb[h][nc][1] = __float_as_uint(Vs[(y+4)*17 + 8*nc + gid]);
            }
        }

        // O += P·V
        #pragma unroll
        for (int m = 0; m < 2; m++) {
            int r0 = 16*m + gid;
            #pragma unroll
            for (int h = 0; h < 2; h++) {
                int cA = 8*h + tig;
                u32 pa0 = __float_as_uint(Pw[r0*18 + cA]);
                u32 pa1 = __float_as_uint(Pw[(r0+8)*18 + cA]);
                u32 pa2 = __float_as_uint(Pw[r0*18 + cA + 4]);
                u32 pa3 = __float_as_uint(Pw[(r0+8)*18 + cA + 4]);
                #pragma unroll
                for (int nc = 0; nc < 2; nc++)
                    mma_tf32(o[m][nc][0], o[m][nc][1], o[m][nc][2], o[m][nc][3],
                             pa0, pa1, pa2, pa3, vb[h][nc][0], vb[h][nc][1]);
            }
        }
        __syncwarp();
    }

    // Row sums: reduce across the tig quad
    #pragma unroll
    for (int m = 0; m < 2; m++) {
        rsA[m] += __shfl_xor_sync(0xFFFFFFFFu, rsA[m], 1);
        rsA[m] += __shfl_xor_sync(0xFFFFFFFFu, rsA[m], 2);
        rsB[m] += __shfl_xor_sync(0xFFFFFFFFu, rsB[m], 1);
        rsB[m] += __shfl_xor_sync(0xFFFFFFFFu, rsB[m], 2);
    }

    float* op = g_fout_t + (size_t)(b*TT + t) * (16*FF);
    #pragma unroll
    for (int m = 0; m < 2; m++) {
        float invA = 1.0f / rsA[m], invB = 1.0f / rsB[m];
        int r0 = fb + 16*m + gid;
        #pragma unroll
        for (int nc = 0; nc < 2; nc++) {
            int c0 = 8*nc + 2*tig;
            op[c0*256 + r0]         = o[m][nc][0] * invA;
            op[(c0+1)*256 + r0]     = o[m][nc][1] * invA;
            op[c0*256 + r0 + 8]     = o[m][nc][2] * invB;
            op[(c0+1)*256 + r0 + 8] = o[m][nc][3] * invB;
        }
    }
}

// ---------------------------------------------------------------------------
// Kernel 5: time attention (causal). Block = (f, b); thread = t row.
// Pair-interleaved K; masked single-lane tail for even t. (R8 version)
// ---------------------------------------------------------------------------
__global__ __launch_bounds__(384, 2) void k_tattn() {
    extern __shared__ __align__(16) char tsm[];
    u64*   ks2 = (u64*)tsm;                        // 192*18*8 = 27648 B
    float* vs  = (float*)(tsm + 192*18*8);         // 384*16*4 = 24576 B
    int f = blockIdx.x, b = blockIdx.y;
    int tid = threadIdx.x;  // t

    const float* ktb = g_tqk  + (((size_t)b*32 + 16)*FF + f)*TT;
    const float* vb  = g_fout + (((size_t)b*16     )*FF + f)*TT;
    for (int i = tid; i < 3072; i += 384) {
        int y2 = i % 192, c = i / 192;
        float2 kv = *(const float2*)(ktb + (size_t)c*NN + 2*y2);
        ks2[y2*18 + c] = pack2(kv.x, kv.y);
    }
    for (int i = tid; i < 6144; i += 384) {
        int c = i / 384, y = i % 384;
        vs[y*16 + c] = vb[(size_t)c*NN + y];
    }
    u64 qb[16];
    const float* qsrc = g_tqk + (((size_t)b*32)*FF + f)*TT;
    #pragma unroll
    for (int c = 0; c < 16; c++) {
        float v = qsrc[(size_t)c*NN + tid] * QSCALE;
        qb[c] = pack2(v, v);
    }
    __syncthreads();

    const EC ec = make_ec();
    int t = tid;
    u64 sum2 = 0;
    u64 acc[8];
    #pragma unroll
    for (int c = 0; c < 8; c++) acc[c] = 0;

    int np = (t + 1) >> 1;
    for (int y2 = 0; y2 < np; y2++) {
        u64 t2  = dotp(qb, ks2 + y2*18);
        u64 pr2 = pexp2(t2, ec);
        sum2 = add2(sum2, pr2);
        float p0, p1; unpack2(pr2, p0, p1);
        u64 pa = pack2(p0, p0), pb = pack2(p1, p1);
        const ulonglong2* v0 = (const ulonglong2*)(vs + (2*y2)*16);
        ulonglong2 w0=v0[0], w1=v0[1], w2=v0[2], w3=v0[3];
        acc[0]=fma2(pa,w0.x,acc[0]);  acc[1]=fma2(pa,w0.y,acc[1]);
        acc[2]=fma2(pa,w1.x,acc[2]);  acc[3]=fma2(pa,w1.y,acc[3]);
        acc[4]=fma2(pa,w2.x,acc[4]);  acc[5]=fma2(pa,w2.y,acc[5]);
        acc[6]=fma2(pa,w3.x,acc[6]);  acc[7]=fma2(pa,w3.y,acc[7]);
        const ulonglong2* v1 = (const ulonglong2*)(vs + (2*y2+1)*16);
        ulonglong2 x0=v1[0], x1=v1[1], x2=v1[2], x3=v1[3];
        acc[0]=fma2(pb,x0.x,acc[0]);  acc[1]=fma2(pb,x0.y,acc[1]);
        acc[2]=fma2(pb,x1.x,acc[2]);  acc[3]=fma2(pb,x1.y,acc[3]);
        acc[4]=fma2(pb,x2.x,acc[4]);  acc[5]=fma2(pb,x2.y,acc[5]);
        acc[6]=fma2(pb,x3.x,acc[6]);  acc[7]=fma2(pb,x3.y,acc[7]);
    }
    if (!(t & 1)) {
        u64 t2  = dotp(qb, ks2 + (t >> 1)*18);
        u64 pr2 = pexp2(t2, ec);
        float p0, p1; unpack2(pr2, p0, p1);
        sum2 = add2(sum2, pack2(p0, 0.f));
        u64 pa = pack2(p0, p0);
        const ulonglong2* v0 = (const ulonglong2*)(vs + t*16);
        ulonglong2 w0=v0[0], w1=v0[1], w2=v0[2], w3=v0[3];
        acc[0]=fma2(pa,w0.x,acc[0]);  acc[1]=fma2(pa,w0.y,acc[1]);
        acc[2]=fma2(pa,w1.x,acc[2]);  acc[3]=fma2(pa,w1.y,acc[3]);
        acc[4]=fma2(pa,w2.x,acc[4]);  acc[5]=fma2(pa,w2.y,acc[5]);
        acc[6]=fma2(pa,w3.x,acc[6]);  acc[7]=fma2(pa,w3.y,acc[7]);
    }
    float inv = 1.0f / hsum2(sum2);
    float* op = g_tout + (((size_t)b*16)*FF + f)*TT + t;
    #pragma unroll
    for (int c = 0; c < 8; c++) {
        float lo, hi; unpack2(acc[c], lo, hi);
        op[(size_t)(2*c)*NN]   = lo * inv;
        op[(size_t)(2*c+1)*NN] = hi * inv;
    }
}

// ---------------------------------------------------------------------------
// Kernel 6: proj conv1x1 (64<-16) + BN + PReLU + residual (packed FMA)
// ---------------------------------------------------------------------------
__global__ __launch_bounds__(256) void k_proj(
    const float* __restrict__ x,
    const float* __restrict__ pw, const float* __restrict__ pg,
    const float* __restrict__ pb, const float* __restrict__ pm,
    const float* __restrict__ pv, const float* __restrict__ pa,
    float* __restrict__ out)
{
    __shared__ float ws[64*16];
    __shared__ float sa[64], sbb[64], sal[64];
    int tid = threadIdx.x;
    for (int i = tid; i < 1024; i += 256) ws[i] = pw[i];
    if (tid < 64) {
        float a = pg[tid] * rsqrtf(pv[tid] + 1e-5f);
        sa[tid] = a; sbb[tid] = pb[tid] - pm[tid]*a; sal[tid] = pa[tid];
    }
    __syncthreads();

    size_t p   = (size_t)blockIdx.x*256 + tid;
    int    b   = (int)(p / NN);
    int    rem = (int)(p % NN);

    u64 tv[8];
    #pragma unroll
    for (int c = 0; c < 8; c++)
        tv[c] = pack2(g_tout[((size_t)b*16 + 2*c  )*NN + rem],
                      g_tout[((size_t)b*16 + 2*c+1)*NN + rem]);

    const float* xb = x   + (size_t)b*CC*NN + rem;
    float*       ob = out + (size_t)b*CC*NN + rem;
    for (int o = 0; o < 64; o++) {
        const ulonglong2* wp = (const ulonglong2*)(ws + o*16);
        ulonglong2 w0 = wp[0], w1 = wp[1], w2 = wp[2], w3 = wp[3];
        u64 a0 = fma2(tv[0], w0.x, 0), a1 = fma2(tv[1], w0.y, 0);
        a0 = fma2(tv[2], w1.x, a0);  a1 = fma2(tv[3], w1.y, a1);
        a0 = fma2(tv[4], w2.x, a0);  a1 = fma2(tv[5], w2.y, a1);
        a0 = fma2(tv[6], w3.x, a0);  a1 = fma2(tv[7], w3.y, a1);
        float acc = hsum2(add2(a0, a1));
        float yn = acc*sa[o] + sbb[o];
        float r  = yn >= 0.f ? yn : sal[o]*yn;
        ob[(size_t)o*NN] = r + xb[(size_t)o*NN];
    }
}

// ---------------------------------------------------------------------------
extern "C" void kernel_launch(void* const* d_in, const int* in_sizes, int n_in,
                              void* d_out, int out_size)
{
    const float* x   = (const float*)d_in[0];
    const float* fw  = (const float*)d_in[1];
    const float* fg  = (const float*)d_in[2];
    const float* fb  = (const float*)d_in[3];
    const float* fm  = (const float*)d_in[4];
    const float* fv  = (const float*)d_in[5];
    const float* fa  = (const float*)d_in[6];
    const float* tw  = (const float*)d_in[7];
    const float* tg  = (const float*)d_in[8];
    const float* tb  = (const float*)d_in[9];
    const float* tm  = (const float*)d_in[10];
    const float* tvv = (const float*)d_in[11];
    const float* ta  = (const float*)d_in[12];
    const float* pw  = (const float*)d_in[13];
    const float* pg  = (const float*)d_in[14];
    const float* pb  = (const float*)d_in[15];
    const float* pm  = (const float*)d_in[16];
    const float* pv  = (const float*)d_in[17];
    const float* pa  = (const float*)d_in[18];
    float*       out = (float*)d_out;

    static const int TATTN_SMEM = 192*18*8 + 384*16*4;   // 52224 B
    cudaFuncSetAttribute(k_tattn, cudaFuncAttributeMaxDynamicSharedMemorySize,
                         TATTN_SMEM);
    cudaFuncSetAttribute(k_fattn, cudaFuncAttributeMaxDynamicSharedMemorySize,
                         FATTN_SMEM);

    // 0) dummy — keeps ncu's fixed profiled launch slot on k_fattn
    k_dummy<<<1, 32>>>();

    // 1) fused qkv convs + BN + PReLU
    k_qkv<<<PP/256, 256>>>(x, fw, fg, fb, fm, fv, fa, tw, tg, tb, tm, tvv, ta);

    // 2) transpose fqkv: [b][cf][t] -> [b][t][cf]
    k_trans_qkv<<<dim3(384/32, 12288/32, BB), dim3(32,8)>>>();

    // 3) frequency attention — tf32 mma  (launch #4 == profiled slot)
    k_fattn<<<dim3(TT, BB), 256, FATTN_SMEM>>>();

    // 4) transpose f_out: [b][t][cf] -> [b][cf][t]
    k_trans_fout<<<dim3(4096/32, 384/32, BB), dim3(32,8)>>>();

    // 5) time attention (causal)
    k_tattn<<<dim3(FF, BB), 384, TATTN_SMEM>>>();

    // 6) proj + BN + PReLU + residual
    k_proj<<<PP/256, 256>>>(x, pw, pg, pb, pm, pv, pa, out);
}

// round 12
// speedup vs baseline: 1.1041x; 1.1041x over previous
#include <cuda_runtime.h>
#include <cuda_bf16.h>

// Shapes
#define BB   4
#define CC   64
#define DCC  16
#define FF   256
#define TT   384
#define NN   (FF*TT)          // 98304
#define PP   (BB*NN)          // 393216

typedef unsigned long long u64;
typedef unsigned int u32;

// 0.25 (1/sqrt(DC)) * log2(e): dot computed in log2 domain
#define QSCALE 0.36067376022224085f

// ---------------------------------------------------------------------------
// Scratch (device globals; allocation is forbidden)
// ---------------------------------------------------------------------------
__device__ float g_fqkv   [(size_t)BB*48*NN];  // [b][c48][f][t]   natural
__device__ float g_fqkv_t [(size_t)BB*48*NN];  // [b][t][c48][f]   transposed
__device__ float g_tqk    [(size_t)BB*32*NN];  // [b][c32][f][t]   natural
__device__ float g_fout_t [(size_t)BB*16*NN];  // [b][t][c16][f]
__device__ float g_fout   [(size_t)BB*16*NN];  // [b][c16][f][t]
__device__ float g_tout   [(size_t)BB*16*NN];  // [b][c16][f][t]

// ---------------------------------------------------------------------------
// Packed f32x2 helpers (used by scalar kernels)
// ---------------------------------------------------------------------------
__device__ __forceinline__ u64 fma2(u64 a, u64 b, u64 c) {
    u64 d;
    asm("fma.rn.f32x2 %0, %1, %2, %3;" : "=l"(d) : "l"(a), "l"(b), "l"(c));
    return d;
}
__device__ __forceinline__ u64 add2(u64 a, u64 b) {
    u64 d;
    asm("add.rn.f32x2 %0, %1, %2;" : "=l"(d) : "l"(a), "l"(b));
    return d;
}
__device__ __forceinline__ u64 sub2(u64 a, u64 b) {
    u64 d;
    asm("sub.rn.f32x2 %0, %1, %2;" : "=l"(d) : "l"(a), "l"(b));
    return d;
}
__device__ __forceinline__ u64 mul2(u64 a, u64 b) {
    u64 d;
    asm("mul.rn.f32x2 %0, %1, %2;" : "=l"(d) : "l"(a), "l"(b));
    return d;
}
__device__ __forceinline__ u64 pack2(float lo, float hi) {
    u64 d;
    asm("mov.b64 %0, {%1, %2};" : "=l"(d) : "f"(lo), "f"(hi));
    return d;
}
__device__ __forceinline__ void unpack2(u64 a, float& lo, float& hi) {
    asm("mov.b64 {%0, %1}, %2;" : "=f"(lo), "=f"(hi) : "l"(a));
}
__device__ __forceinline__ float hsum2(u64 a) {
    float lo, hi; unpack2(a, lo, hi); return lo + hi;
}
__device__ __forceinline__ u64 bcast(float x) { return pack2(x, x); }

// Packed-exp constants — 6 u64 (12 regs) (scalar tattn path)
struct EC { u64 M, A4, A3, A2, A1, ONE; };
__device__ __forceinline__ EC make_ec() {
    EC e;
    e.M   = bcast(12582912.0f);        // 2^23 + 2^22
    e.A4  = bcast(9.6181291076e-3f);   // ln2^4/24
    e.A3  = bcast(5.5504108664e-2f);   // ln2^3/6
    e.A2  = bcast(2.4022650696e-1f);   // ln2^2/2
    e.A1  = bcast(6.9314718056e-1f);   // ln2
    e.ONE = bcast(1.0f);
    return e;
}

// Packed 2^t on both lanes, degree-4 (max rel err ~4e-5).
__device__ __forceinline__ u64 pexp2(u64 t2, const EC& e) {
    u64 z2  = add2(t2, e.M);
    u64 fi2 = sub2(z2, e.M);
    u64 u2  = sub2(t2, fi2);
    u64 p   = fma2(u2, e.A4, e.A3);
    p = fma2(u2, p, e.A2);
    p = fma2(u2, p, e.A1);
    p = fma2(u2, p, e.ONE);
    unsigned lo, hi;
    asm("mov.b64 {%0, %1}, %2;" : "=r"(lo), "=r"(hi) : "l"(z2));
    unsigned s0 = (lo + 0xB4C0007Fu) << 23;
    unsigned s1 = (hi + 0xB4C0007Fu) << 23;
    u64 sc;
    asm("mov.b64 %0, {%1, %2};" : "=l"(sc) : "r"(s0), "r"(s1));
    return mul2(p, sc);
}

// Scalar 2^t, FMA-immediate form (no constant registers).
__device__ __forceinline__ float fexp2s(float t) {
    float z  = t + 12582912.0f;
    float fi = z - 12582912.0f;
    float u  = t - fi;
    float p  = fmaf(u, 9.6181291076e-3f, 5.5504108664e-2f);
    p = fmaf(u, p, 2.4022650696e-1f);
    p = fmaf(u, p, 6.9314718056e-1f);
    p = fmaf(u, p, 1.0f);
    unsigned sc = (__float_as_uint(z) + 0xB4C0007Fu) << 23;
    return p * __uint_as_float(sc);
}

// Pair-dot (used by scalar k_tattn)
__device__ __forceinline__ u64 dotp(const u64 (&qb)[16], const u64* krow) {
    const ulonglong2* kp = (const ulonglong2*)krow;
    ulonglong2 m0=kp[0], m1=kp[1], m2=kp[2], m3=kp[3];
    u64 a0 = fma2(qb[0],  m0.x, 0), a1 = fma2(qb[1],  m0.y, 0);
    a0 = fma2(qb[2],  m1.x, a0);  a1 = fma2(qb[3],  m1.y, a1);
    a0 = fma2(qb[4],  m2.x, a0);  a1 = fma2(qb[5],  m2.y, a1);
    a0 = fma2(qb[6],  m3.x, a0);  a1 = fma2(qb[7],  m3.y, a1);
    ulonglong2 m4=kp[4], m5=kp[5], m6=kp[6], m7=kp[7];
    a0 = fma2(qb[8],  m4.x, a0);  a1 = fma2(qb[9],  m4.y, a1);
    a0 = fma2(qb[10], m5.x, a0);  a1 = fma2(qb[11], m5.y, a1);
    a0 = fma2(qb[12], m6.x, a0);  a1 = fma2(qb[13], m6.y, a1);
    a0 = fma2(qb[14], m7.x, a0);  a1 = fma2(qb[15], m7.y, a1);
    return add2(a0, a1);
}

// ---------------------------------------------------------------------------
// tf32 mma helpers
// ---------------------------------------------------------------------------
__device__ __forceinline__ float to_tf32(float x) {
    u32 r; asm("cvt.rna.tf32.f32 %0, %1;" : "=r"(r) : "f"(x));
    return __uint_as_float(r);
}
__device__ __forceinline__ void mma_tf32(
    float& d0, float& d1, float& d2, float& d3,
    u32 a0, u32 a1, u32 a2, u32 a3, u32 b0, u32 b1)
{
    asm volatile(
        "mma.sync.aligned.m16n8k8.row.col.f32.tf32.tf32.f32 "
        "{%0,%1,%2,%3},{%4,%5,%6,%7},{%8,%9},{%0,%1,%2,%3};"
        : "+f"(d0), "+f"(d1), "+f"(d2), "+f"(d3)
        : "r"(a0), "r"(a1), "r"(a2), "r"(a3), "r"(b0), "r"(b1));
}
__device__ __forceinline__ float tf32_mask(float x) {
    return __uint_as_float(__float_as_uint(x) & 0xFFFFE000u);
}
// RZ-truncated hi bits (exact split: hi + (x-hi) == x)
__device__ __forceinline__ u32 tf32_hi_bits(float x) {
    return __float_as_uint(x) & 0xFFFFE000u;
}

// ---------------------------------------------------------------------------
// Dummy kernel: keeps the ncu profiled launch slot on k_fattn.
// ---------------------------------------------------------------------------
__global__ void k_dummy() {}

// ---------------------------------------------------------------------------
// Kernel 1: fused fqkv (48ch) + tqk (32ch) conv1x1 + BN + PReLU (packed FMA)
// ---------------------------------------------------------------------------
__global__ __launch_bounds__(256) void k_qkv(
    const float* __restrict__ x,
    const float* __restrict__ fw, const float* __restrict__ fg,
    const float* __restrict__ fb, const float* __restrict__ fm,
    const float* __restrict__ fv, const float* __restrict__ fa,
    const float* __restrict__ tw, const float* __restrict__ tg,
    const float* __restrict__ tb, const float* __restrict__ tm,
    const float* __restrict__ tvv, const float* __restrict__ ta)
{
    __shared__ float ws[80*64];
    __shared__ float sa[80], sbb[80], sal[80];
    int tid = threadIdx.x;
    for (int i = tid; i < 48*64; i += 256) ws[i] = fw[i];
    for (int i = tid; i < 32*64; i += 256) ws[48*64 + i] = tw[i];
    if (tid < 80) {
        float g, be, mn, vr, al;
        if (tid < 48) { g=fg[tid]; be=fb[tid]; mn=fm[tid]; vr=fv[tid]; al=fa[tid]; }
        else { int o=tid-48; g=tg[o]; be=tb[o]; mn=tm[o]; vr=tvv[o]; al=ta[o]; }
        float a = g * rsqrtf(vr + 1e-5f);
        sa[tid] = a; sbb[tid] = be - mn*a; sal[tid] = al;
    }
    __syncthreads();

    size_t p   = (size_t)blockIdx.x*256 + tid;
    int    b   = (int)(p / NN);
    int    rem = (int)(p % NN);

    u64 xv[32];
    const float* xb = x + (size_t)b*CC*NN + rem;
    #pragma unroll
    for (int c = 0; c < 32; c++)
        xv[c] = pack2(xb[(size_t)(2*c)*NN], xb[(size_t)(2*c+1)*NN]);

    for (int o = 0; o < 80; o++) {
        const ulonglong2* wp = (const ulonglong2*)(ws + o*64);
        u64 a0 = 0, a1 = 0;
        #pragma unroll
        for (int i = 0; i < 16; i++) {
            ulonglong2 w = wp[i];
            a0 = fma2(xv[2*i],   w.x, a0);
            a1 = fma2(xv[2*i+1], w.y, a1);
        }
        float acc = hsum2(add2(a0, a1));
        float yn = acc*sa[o] + sbb[o];
        float r  = yn >= 0.f ? yn : sal[o]*yn;
        if (o < 48) g_fqkv[((size_t)b*48 + o     )*NN + rem] = r;
        else        g_tqk [((size_t)b*32 + (o-48))*NN + rem] = r;
    }
}

// ---------------------------------------------------------------------------
// Transposes (32x32 smem tiles, coalesced both ways)
// ---------------------------------------------------------------------------
__global__ void k_trans_qkv() {  // [b][cf=12288][t=384] -> [b][t][cf]
    __shared__ float tile[32][33];
    int b = blockIdx.z;
    size_t base = (size_t)b * 12288 * 384;
    int r0 = blockIdx.y*32, q0 = blockIdx.x*32;
    for (int i = threadIdx.y; i < 32; i += 8)
        tile[i][threadIdx.x] = g_fqkv[base + (size_t)(r0+i)*384 + q0 + threadIdx.x];
    __syncthreads();
    for (int i = threadIdx.y; i < 32; i += 8)
        g_fqkv_t[base + (size_t)(q0+i)*12288 + r0 + threadIdx.x] = tile[threadIdx.x][i];
}

__global__ void k_trans_fout() { // [b][t=384][cf=4096] -> [b][cf][t]
    __shared__ float tile[32][33];
    int b = blockIdx.z;
    size_t base = (size_t)b * 4096 * 384;
    int r0 = blockIdx.y*32, q0 = blockIdx.x*32;
    for (int i = threadIdx.y; i < 32; i += 8)
        tile[i][threadIdx.x] = g_fout_t[base + (size_t)(r0+i)*4096 + q0 + threadIdx.x];
    __syncthreads();
    for (int i = threadIdx.y; i < 32; i += 8)
        g_fout[base + (size_t)(q0+i)*384 + r0 + threadIdx.x] = tile[threadIdx.x][i];
}

// ---------------------------------------------------------------------------
// Kernel 3: frequency attention — tf32 mma flash-attention, v2.
// Fragment-order swizzled K/V/Q layouts: one conflict-free LDS.128 delivers a
// thread's whole frag set for a chunk. Q staged full precision; hi = RZ mask,
// lo = x - hi (exact split). smem 67.6KB -> 3 blocks/SM.
//   perm index: elem (row, c) stored at row*16 + ((c&3)^(row&3))*4 + (c>>2)
// ---------------------------------------------------------------------------
#define FATTN_SMEM ((4096 + 4096 + 4096 + 8*32*18) * 4)   // Qf, K, V, Ps

__global__ __launch_bounds__(256, 3) void k_fattn() {
    extern __shared__ __align__(16) float fsm[];
    float* Qf  = fsm;             // [f][perm c] full precision, scaled
    float* Ksv = fsm + 4096;      // [y][perm c] tf32
    float* Vsv = fsm + 8192;      // [ych][c][perm y] tf32
    float* Ps  = fsm + 12288;     // per-warp [32][18]

    int t = blockIdx.x, b = blockIdx.y;
    int tid  = threadIdx.x;
    const float* base = g_fqkv_t + (size_t)(b*TT + t) * (48*FF);

    // Stage: Q full (scaled), K/V tf32-rounded, all in swizzled frag order.
    for (int i = tid; i < 4096; i += 256) {
        int pos = i & 255, c = i >> 8;
        int pidx = (((c & 3) ^ (pos & 3)) << 2) + (c >> 2);
        Qf [pos*16 + pidx] = base[i] * QSCALE;
        Ksv[pos*16 + pidx] = to_tf32(base[4096 + i]);
        int pidx2 = (((pos & 3) ^ (c & 3)) << 2) + ((pos >> 2) & 3);
        Vsv[(pos >> 4)*256 + c*16 + pidx2] = to_tf32(base[8192 + i]);
    }
    __syncthreads();

    int w    = tid >> 5;
    int lane = tid & 31;
    int gid  = lane >> 2;
    int tig  = lane & 3;
    int fb   = w * 32;
    int sw   = (tig ^ (gid & 3)) << 2;    // swizzled group offset (words)
    float* Pw = Ps + w * (32*18);

    float o[2][2][4];
    #pragma unroll
    for (int m = 0; m < 2; m++)
        #pragma unroll
        for (int nc = 0; nc < 2; nc++)
            #pragma unroll
            for (int r = 0; r < 4; r++) o[m][nc][r] = 0.f;
    float rsA[2] = {0.f, 0.f}, rsB[2] = {0.f, 0.f};

    for (int ch = 0; ch < 16; ch++) {
        int y0 = 16*ch;

        // K frags: one LDS.128 per n gives cols {tig, tig+4, tig+8, tig+12}
        u32 kb[2][2][2];
        #pragma unroll
        for (int n = 0; n < 2; n++) {
            float4 kv = *(const float4*)&Ksv[(y0 + 8*n + gid)*16 + sw];
            kb[0][n][0] = __float_as_uint(kv.x);
            kb[0][n][1] = __float_as_uint(kv.y);
            kb[1][n][0] = __float_as_uint(kv.z);
            kb[1][n][1] = __float_as_uint(kv.w);
        }

        // S = Q·K^T (2xTF32 split), exp, row-sums, store P
        #pragma unroll
        for (int m = 0; m < 2; m++) {
            int f0 = fb + 16*m + gid;
            float4 qr0 = *(const float4*)&Qf[f0*16 + sw];
            float4 qr8 = *(const float4*)&Qf[(f0+8)*16 + sw];

            float s[2][4];
            #pragma unroll
            for (int n = 0; n < 2; n++)
                #pragma unroll
                for (int r = 0; r < 4; r++) s[n][r] = 0.f;

            #pragma unroll
            for (int ks = 0; ks < 2; ks++) {
                float x0 = ks ? qr0.z : qr0.x;   // (f0,   8ks+tig)
                float x1 = ks ? qr8.z : qr8.x;   // (f0+8, 8ks+tig)
                float x2 = ks ? qr0.w : qr0.y;   // (f0,   8ks+tig+4)
                float x3 = ks ? qr8.w : qr8.y;   // (f0+8, 8ks+tig+4)
                u32 h0 = tf32_hi_bits(x0), h1 = tf32_hi_bits(x1);
                u32 h2 = tf32_hi_bits(x2), h3 = tf32_hi_bits(x3);
                u32 l0 = __float_as_uint(x0 - __uint_as_float(h0));
                u32 l1 = __float_as_uint(x1 - __uint_as_float(h1));
                u32 l2 = __float_as_uint(x2 - __uint_as_float(h2));
                u32 l3 = __float_as_uint(x3 - __uint_as_float(h3));
                #pragma unroll
                for (int n = 0; n < 2; n++) {
                    mma_tf32(s[n][0], s[n][1], s[n][2], s[n][3],
                             h0, h1, h2, h3, kb[ks][n][0], kb[ks][n][1]);
                    mma_tf32(s[n][0], s[n][1], s[n][2], s[n][3],
                             l0, l1, l2, l3, kb[ks][n][0], kb[ks][n][1]);
                }
            }
            int r0 = 16*m + gid;
            #pragma unroll
            for (int n = 0; n < 2; n++) {
                float p0 = tf32_mask(fexp2s(s[n][0]));
                float p1 = tf32_mask(fexp2s(s[n][1]));
                float p2 = tf32_mask(fexp2s(s[n][2]));
                float p3 = tf32_mask(fexp2s(s[n][3]));
                rsA[m] += p0 + p1;
                rsB[m] += p2 + p3;
                *(float2*)&Pw[r0*18 + 8*n + 2*tig]     = make_float2(p0, p1);
                *(float2*)&Pw[(r0+8)*18 + 8*n + 2*tig] = make_float2(p2, p3);
            }
        }
        __syncwarp();

        // V frags: one LDS.128 per nc gives rows {tig, tig+4, tig+8, tig+12}
        u32 vb[2][2][2];
        #pragma unroll
        for (int nc = 0; nc < 2; nc++) {
            float4 vv = *(const float4*)&Vsv[ch*256 + (8*nc + gid)*16 + sw];
            vb[0][nc][0] = __float_as_uint(vv.x);
            vb[0][nc][1] = __float_as_uint(vv.y);
            vb[1][nc][0] = __float_as_uint(vv.z);
            vb[1][nc][1] = __float_as_uint(vv.w);
        }

        // O += P·V
        #pragma unroll
        for (int m = 0; m < 2; m++) {
            int r0 = 16*m + gid;
            #pragma unroll
            for (int h = 0; h < 2; h++) {
                int cA = 8*h + tig;
                u32 pa0 = __float_as_uint(Pw[r0*18 + cA]);
                u32 pa1 = __float_as_uint(Pw[(r0+8)*18 + cA]);
                u32 pa2 = __float_as_uint(Pw[r0*18 + cA + 4]);
                u32 pa3 = __float_as_uint(Pw[(r0+8)*18 + cA + 4]);
                #pragma unroll
                for (int nc = 0; nc < 2; nc++)
                    mma_tf32(o[m][nc][0], o[m][nc][1], o[m][nc][2], o[m][nc][3],
                             pa0, pa1, pa2, pa3, vb[h][nc][0], vb[h][nc][1]);
            }
        }
        __syncwarp();
    }

    // Row sums: reduce across the tig quad
    #pragma unroll
    for (int m = 0; m < 2; m++) {
        rsA[m] += __shfl_xor_sync(0xFFFFFFFFu, rsA[m], 1);
        rsA[m] += __shfl_xor_sync(0xFFFFFFFFu, rsA[m], 2);
        rsB[m] += __shfl_xor_sync(0xFFFFFFFFu, rsB[m], 1);
        rsB[m] += __shfl_xor_sync(0xFFFFFFFFu, rsB[m], 2);
    }

    float* op = g_fout_t + (size_t)(b*TT + t) * (16*FF);
    #pragma unroll
    for (int m = 0; m < 2; m++) {
        float invA = 1.0f / rsA[m], invB = 1.0f / rsB[m];
        int r0 = fb + 16*m + gid;
        #pragma unroll
        for (int nc = 0; nc < 2; nc++) {
            int c0 = 8*nc + 2*tig;
            op[c0*256 + r0]         = o[m][nc][0] * invA;
            op[(c0+1)*256 + r0]     = o[m][nc][1] * invA;
            op[c0*256 + r0 + 8]     = o[m][nc][2] * invB;
            op[(c0+1)*256 + r0 + 8] = o[m][nc][3] * invB;
        }
    }
}

// ---------------------------------------------------------------------------
// Kernel 5: time attention (causal). Block = (f, b); thread = t row.
// Pair-interleaved K; masked single-lane tail for even t. (R8 version)
// ---------------------------------------------------------------------------
__global__ __launch_bounds__(384, 2) void k_tattn() {
    extern __shared__ __align__(16) char tsm[];
    u64*   ks2 = (u64*)tsm;                        // 192*18*8 = 27648 B
    float* vs  = (float*)(tsm + 192*18*8);         // 384*16*4 = 24576 B
    int f = blockIdx.x, b = blockIdx.y;
    int tid = threadIdx.x;  // t

    const float* ktb = g_tqk  + (((size_t)b*32 + 16)*FF + f)*TT;
    const float* vb  = g_fout + (((size_t)b*16     )*FF + f)*TT;
    for (int i = tid; i < 3072; i += 384) {
        int y2 = i % 192, c = i / 192;
        float2 kv = *(const float2*)(ktb + (size_t)c*NN + 2*y2);
        ks2[y2*18 + c] = pack2(kv.x, kv.y);
    }
    for (int i = tid; i < 6144; i += 384) {
        int c = i / 384, y = i % 384;
        vs[y*16 + c] = vb[(size_t)c*NN + y];
    }
    u64 qb[16];
    const float* qsrc = g_tqk + (((size_t)b*32)*FF + f)*TT;
    #pragma unroll
    for (int c = 0; c < 16; c++) {
        float v = qsrc[(size_t)c*NN + tid] * QSCALE;
        qb[c] = pack2(v, v);
    }
    __syncthreads();

    const EC ec = make_ec();
    int t = tid;
    u64 sum2 = 0;
    u64 acc[8];
    #pragma unroll
    for (int c = 0; c < 8; c++) acc[c] = 0;

    int np = (t + 1) >> 1;
    for (int y2 = 0; y2 < np; y2++) {
        u64 t2  = dotp(qb, ks2 + y2*18);
        u64 pr2 = pexp2(t2, ec);
        sum2 = add2(sum2, pr2);
        float p0, p1; unpack2(pr2, p0, p1);
        u64 pa = pack2(p0, p0), pb = pack2(p1, p1);
        const ulonglong2* v0 = (const ulonglong2*)(vs + (2*y2)*16);
        ulonglong2 w0=v0[0], w1=v0[1], w2=v0[2], w3=v0[3];
        acc[0]=fma2(pa,w0.x,acc[0]);  acc[1]=fma2(pa,w0.y,acc[1]);
        acc[2]=fma2(pa,w1.x,acc[2]);  acc[3]=fma2(pa,w1.y,acc[3]);
        acc[4]=fma2(pa,w2.x,acc[4]);  acc[5]=fma2(pa,w2.y,acc[5]);
        acc[6]=fma2(pa,w3.x,acc[6]);  acc[7]=fma2(pa,w3.y,acc[7]);
        const ulonglong2* v1 = (const ulonglong2*)(vs + (2*y2+1)*16);
        ulonglong2 x0=v1[0], x1=v1[1], x2=v1[2], x3=v1[3];
        acc[0]=fma2(pb,x0.x,acc[0]);  acc[1]=fma2(pb,x0.y,acc[1]);
        acc[2]=fma2(pb,x1.x,acc[2]);  acc[3]=fma2(pb,x1.y,acc[3]);
        acc[4]=fma2(pb,x2.x,acc[4]);  acc[5]=fma2(pb,x2.y,acc[5]);
        acc[6]=fma2(pb,x3.x,acc[6]);  acc[7]=fma2(pb,x3.y,acc[7]);
    }
    if (!(t & 1)) {
        u64 t2  = dotp(qb, ks2 + (t >> 1)*18);
        u64 pr2 = pexp2(t2, ec);
        float p0, p1; unpack2(pr2, p0, p1);
        sum2 = add2(sum2, pack2(p0, 0.f));
        u64 pa = pack2(p0, p0);
        const ulonglong2* v0 = (const ulonglong2*)(vs + t*16);
        ulonglong2 w0=v0[0], w1=v0[1], w2=v0[2], w3=v0[3];
        acc[0]=fma2(pa,w0.x,acc[0]);  acc[1]=fma2(pa,w0.y,acc[1]);
        acc[2]=fma2(pa,w1.x,acc[2]);  acc[3]=fma2(pa,w1.y,acc[3]);
        acc[4]=fma2(pa,w2.x,acc[4]);  acc[5]=fma2(pa,w2.y,acc[5]);
        acc[6]=fma2(pa,w3.x,acc[6]);  acc[7]=fma2(pa,w3.y,acc[7]);
    }
    float inv = 1.0f / hsum2(sum2);
    float* op = g_tout + (((size_t)b*16)*FF + f)*TT + t;
    #pragma unroll
    for (int c = 0; c < 8; c++) {
        float lo, hi; unpack2(acc[c], lo, hi);
        op[(size_t)(2*c)*NN]   = lo * inv;
        op[(size_t)(2*c+1)*NN] = hi * inv;
    }
}

// ---------------------------------------------------------------------------
// Kernel 6: proj conv1x1 (64<-16) + BN + PReLU + residual (packed FMA)
// ---------------------------------------------------------------------------
__global__ __launch_bounds__(256) void k_proj(
    const float* __restrict__ x,
    const float* __restrict__ pw, const float* __restrict__ pg,
    const float* __restrict__ pb, const float* __restrict__ pm,
    const float* __restrict__ pv, const float* __restrict__ pa,
    float* __restrict__ out)
{
    __shared__ float ws[64*16];
    __shared__ float sa[64], sbb[64], sal[64];
    int tid = threadIdx.x;
    for (int i = tid; i < 1024; i += 256) ws[i] = pw[i];
    if (tid < 64) {
        float a = pg[tid] * rsqrtf(pv[tid] + 1e-5f);
        sa[tid] = a; sbb[tid] = pb[tid] - pm[tid]*a; sal[tid] = pa[tid];
    }
    __syncthreads();

    size_t p   = (size_t)blockIdx.x*256 + tid;
    int    b   = (int)(p / NN);
    int    rem = (int)(p % NN);

    u64 tv[8];
    #pragma unroll
    for (int c = 0; c < 8; c++)
        tv[c] = pack2(g_tout[((size_t)b*16 + 2*c  )*NN + rem],
                      g_tout[((size_t)b*16 + 2*c+1)*NN + rem]);

    const float* xb = x   + (size_t)b*CC*NN + rem;
    float*       ob = out + (size_t)b*CC*NN + rem;
    for (int o = 0; o < 64; o++) {
        const ulonglong2* wp = (const ulonglong2*)(ws + o*16);
        ulonglong2 w0 = wp[0], w1 = wp[1], w2 = wp[2], w3 = wp[3];
        u64 a0 = fma2(tv[0], w0.x, 0), a1 = fma2(tv[1], w0.y, 0);
        a0 = fma2(tv[2], w1.x, a0);  a1 = fma2(tv[3], w1.y, a1);
        a0 = fma2(tv[4], w2.x, a0);  a1 = fma2(tv[5], w2.y, a1);
        a0 = fma2(tv[6], w3.x, a0);  a1 = fma2(tv[7], w3.y, a1);
        float acc = hsum2(add2(a0, a1));
        float yn = acc*sa[o] + sbb[o];
        float r  = yn >= 0.f ? yn : sal[o]*yn;
        ob[(size_t)o*NN] = r + xb[(size_t)o*NN];
    }
}

// ---------------------------------------------------------------------------
extern "C" void kernel_launch(void* const* d_in, const int* in_sizes, int n_in,
                              void* d_out, int out_size)
{
    const float* x   = (const float*)d_in[0];
    const float* fw  = (const float*)d_in[1];
    const float* fg  = (const float*)d_in[2];
    const float* fb  = (const float*)d_in[3];
    const float* fm  = (const float*)d_in[4];
    const float* fv  = (const float*)d_in[5];
    const float* fa  = (const float*)d_in[6];
    const float* tw  = (const float*)d_in[7];
    const float* tg  = (const float*)d_in[8];
    const float* tb  = (const float*)d_in[9];
    const float* tm  = (const float*)d_in[10];
    const float* tvv = (const float*)d_in[11];
    const float* ta  = (const float*)d_in[12];
    const float* pw  = (const float*)d_in[13];
    const float* pg  = (const float*)d_in[14];
    const float* pb  = (const float*)d_in[15];
    const float* pm  = (const float*)d_in[16];
    const float* pv  = (const float*)d_in[17];
    const float* pa  = (const float*)d_in[18];
    float*       out = (float*)d_out;

    static const int TATTN_SMEM = 192*18*8 + 384*16*4;   // 52224 B
    cudaFuncSetAttribute(k_tattn, cudaFuncAttributeMaxDynamicSharedMemorySize,
                         TATTN_SMEM);
    cudaFuncSetAttribute(k_fattn, cudaFuncAttributeMaxDynamicSharedMemorySize,
                         FATTN_SMEM);

    // 0) dummy — keeps ncu's fixed profiled launch slot on k_fattn
    k_dummy<<<1, 32>>>();

    // 1) fused qkv convs + BN + PReLU
    k_qkv<<<PP/256, 256>>>(x, fw, fg, fb, fm, fv, fa, tw, tg, tb, tm, tvv, ta);

    // 2) transpose fqkv: [b][cf][t] -> [b][t][cf]
    k_trans_qkv<<<dim3(384/32, 12288/32, BB), dim3(32,8)>>>();

    // 3) frequency attention — tf32 mma v2  (launch #4 == profiled slot)
    k_fattn<<<dim3(TT, BB), 256, FATTN_SMEM>>>();

    // 4) transpose f_out: [b][t][cf] -> [b][cf][t]
    k_trans_fout<<<dim3(4096/32, 384/32, BB), dim3(32,8)>>>();

    // 5) time attention (causal)
    k_tattn<<<dim3(FF, BB), 384, TATTN_SMEM>>>();

    // 6) proj + BN + PReLU + residual
    k_proj<<<PP/256, 256>>>(x, pw, pg, pb, pm, pv, pa, out);
}

// round 13
// speedup vs baseline: 1.3804x; 1.2503x over previous
#include <cuda_runtime.h>
#include <cuda_bf16.h>

// Shapes
#define BB   4
#define CC   64
#define DCC  16
#define FF   256
#define TT   384
#define NN   (FF*TT)          // 98304
#define PP   (BB*NN)          // 393216

typedef unsigned long long u64;
typedef unsigned int u32;

// 0.25 (1/sqrt(DC)) * log2(e): dot computed in log2 domain
#define QSCALE 0.36067376022224085f

// ---------------------------------------------------------------------------
// Scratch (device globals; allocation is forbidden)
// ---------------------------------------------------------------------------
__device__ float g_fqkv   [(size_t)BB*48*NN];  // [b][c48][f][t]   natural
__device__ float g_fqkv_t [(size_t)BB*48*NN];  // [b][t][c48][f]   transposed
__device__ float g_tqk    [(size_t)BB*32*NN];  // [b][c32][f][t]   natural
__device__ float g_fout_t [(size_t)BB*16*NN];  // [b][t][c16][f]
__device__ float g_fout   [(size_t)BB*16*NN];  // [b][c16][f][t]
__device__ float g_tout   [(size_t)BB*16*NN];  // [b][c16][f][t]

// ---------------------------------------------------------------------------
// Packed f32x2 helpers (scalar kernels)
// ---------------------------------------------------------------------------
__device__ __forceinline__ u64 fma2(u64 a, u64 b, u64 c) {
    u64 d;
    asm("fma.rn.f32x2 %0, %1, %2, %3;" : "=l"(d) : "l"(a), "l"(b), "l"(c));
    return d;
}
__device__ __forceinline__ u64 add2(u64 a, u64 b) {
    u64 d;
    asm("add.rn.f32x2 %0, %1, %2;" : "=l"(d) : "l"(a), "l"(b));
    return d;
}
__device__ __forceinline__ u64 pack2(float lo, float hi) {
    u64 d;
    asm("mov.b64 %0, {%1, %2};" : "=l"(d) : "f"(lo), "f"(hi));
    return d;
}
__device__ __forceinline__ void unpack2(u64 a, float& lo, float& hi) {
    asm("mov.b64 {%0, %1}, %2;" : "=f"(lo), "=f"(hi) : "l"(a));
}
__device__ __forceinline__ float hsum2(u64 a) {
    float lo, hi; unpack2(a, lo, hi); return lo + hi;
}

// Scalar 2^t, FMA-immediate form (no constant registers).
__device__ __forceinline__ float fexp2s(float t) {
    float z  = t + 12582912.0f;
    float fi = z - 12582912.0f;
    float u  = t - fi;
    float p  = fmaf(u, 9.6181291076e-3f, 5.5504108664e-2f);
    p = fmaf(u, p, 2.4022650696e-1f);
    p = fmaf(u, p, 6.9314718056e-1f);
    p = fmaf(u, p, 1.0f);
    unsigned sc = (__float_as_uint(z) + 0xB4C0007Fu) << 23;
    return p * __uint_as_float(sc);
}

// ---------------------------------------------------------------------------
// tf32 mma helpers
// ---------------------------------------------------------------------------
__device__ __forceinline__ float to_tf32(float x) {
    u32 r; asm("cvt.rna.tf32.f32 %0, %1;" : "=r"(r) : "f"(x));
    return __uint_as_float(r);
}
__device__ __forceinline__ void mma_tf32(
    float& d0, float& d1, float& d2, float& d3,
    u32 a0, u32 a1, u32 a2, u32 a3, u32 b0, u32 b1)
{
    asm volatile(
        "mma.sync.aligned.m16n8k8.row.col.f32.tf32.tf32.f32 "
        "{%0,%1,%2,%3},{%4,%5,%6,%7},{%8,%9},{%0,%1,%2,%3};"
        : "+f"(d0), "+f"(d1), "+f"(d2), "+f"(d3)
        : "r"(a0), "r"(a1), "r"(a2), "r"(a3), "r"(b0), "r"(b1));
}
__device__ __forceinline__ float tf32_mask(float x) {
    return __uint_as_float(__float_as_uint(x) & 0xFFFFE000u);
}
__device__ __forceinline__ u32 tf32_hi_bits(float x) {
    return __float_as_uint(x) & 0xFFFFE000u;
}

// ---------------------------------------------------------------------------
// Dummy kernel: keeps the ncu profiled launch slot on k_fattn.
// ---------------------------------------------------------------------------
__global__ void k_dummy() {}

// ---------------------------------------------------------------------------
// Kernel 1: fused fqkv (48ch) + tqk (32ch) conv1x1 + BN + PReLU (packed FMA)
// ---------------------------------------------------------------------------
__global__ __launch_bounds__(256) void k_qkv(
    const float* __restrict__ x,
    const float* __restrict__ fw, const float* __restrict__ fg,
    const float* __restrict__ fb, const float* __restrict__ fm,
    const float* __restrict__ fv, const float* __restrict__ fa,
    const float* __restrict__ tw, const float* __restrict__ tg,
    const float* __restrict__ tb, const float* __restrict__ tm,
    const float* __restrict__ tvv, const float* __restrict__ ta)
{
    __shared__ float ws[80*64];
    __shared__ float sa[80], sbb[80], sal[80];
    int tid = threadIdx.x;
    for (int i = tid; i < 48*64; i += 256) ws[i] = fw[i];
    for (int i = tid; i < 32*64; i += 256) ws[48*64 + i] = tw[i];
    if (tid < 80) {
        float g, be, mn, vr, al;
        if (tid < 48) { g=fg[tid]; be=fb[tid]; mn=fm[tid]; vr=fv[tid]; al=fa[tid]; }
        else { int o=tid-48; g=tg[o]; be=tb[o]; mn=tm[o]; vr=tvv[o]; al=ta[o]; }
        float a = g * rsqrtf(vr + 1e-5f);
        sa[tid] = a; sbb[tid] = be - mn*a; sal[tid] = al;
    }
    __syncthreads();

    size_t p   = (size_t)blockIdx.x*256 + tid;
    int    b   = (int)(p / NN);
    int    rem = (int)(p % NN);

    u64 xv[32];
    const float* xb = x + (size_t)b*CC*NN + rem;
    #pragma unroll
    for (int c = 0; c < 32; c++)
        xv[c] = pack2(xb[(size_t)(2*c)*NN], xb[(size_t)(2*c+1)*NN]);

    for (int o = 0; o < 80; o++) {
        const ulonglong2* wp = (const ulonglong2*)(ws + o*64);
        u64 a0 = 0, a1 = 0;
        #pragma unroll
        for (int i = 0; i < 16; i++) {
            ulonglong2 w = wp[i];
            a0 = fma2(xv[2*i],   w.x, a0);
            a1 = fma2(xv[2*i+1], w.y, a1);
        }
        float acc = hsum2(add2(a0, a1));
        float yn = acc*sa[o] + sbb[o];
        float r  = yn >= 0.f ? yn : sal[o]*yn;
        if (o < 48) g_fqkv[((size_t)b*48 + o     )*NN + rem] = r;
        else        g_tqk [((size_t)b*32 + (o-48))*NN + rem] = r;
    }
}

// ---------------------------------------------------------------------------
// Transposes (32x32 smem tiles, coalesced both ways)
// ---------------------------------------------------------------------------
__global__ void k_trans_qkv() {  // [b][cf=12288][t=384] -> [b][t][cf]
    __shared__ float tile[32][33];
    int b = blockIdx.z;
    size_t base = (size_t)b * 12288 * 384;
    int r0 = blockIdx.y*32, q0 = blockIdx.x*32;
    for (int i = threadIdx.y; i < 32; i += 8)
        tile[i][threadIdx.x] = g_fqkv[base + (size_t)(r0+i)*384 + q0 + threadIdx.x];
    __syncthreads();
    for (int i = threadIdx.y; i < 32; i += 8)
        g_fqkv_t[base + (size_t)(q0+i)*12288 + r0 + threadIdx.x] = tile[threadIdx.x][i];
}

__global__ void k_trans_fout() { // [b][t=384][cf=4096] -> [b][cf][t]
    __shared__ float tile[32][33];
    int b = blockIdx.z;
    size_t base = (size_t)b * 4096 * 384;
    int r0 = blockIdx.y*32, q0 = blockIdx.x*32;
    for (int i = threadIdx.y; i < 32; i += 8)
        tile[i][threadIdx.x] = g_fout_t[base + (size_t)(r0+i)*4096 + q0 + threadIdx.x];
    __syncthreads();
    for (int i = threadIdx.y; i < 32; i += 8)
        g_fout[base + (size_t)(q0+i)*384 + r0 + threadIdx.x] = tile[threadIdx.x][i];
}

// ---------------------------------------------------------------------------
// Kernel 3: frequency attention — tf32 mma flash-attention v2 (unchanged R12)
// ---------------------------------------------------------------------------
#define FATTN_SMEM ((4096 + 4096 + 4096 + 8*32*18) * 4)   // Qf, K, V, Ps

__global__ __launch_bounds__(256, 3) void k_fattn() {
    extern __shared__ __align__(16) float fsm[];
    float* Qf  = fsm;             // [f][perm c] full precision, scaled
    float* Ksv = fsm + 4096;      // [y][perm c] tf32
    float* Vsv = fsm + 8192;      // [ych][c][perm y] tf32
    float* Ps  = fsm + 12288;     // per-warp [32][18]

    int t = blockIdx.x, b = blockIdx.y;
    int tid  = threadIdx.x;
    const float* base = g_fqkv_t + (size_t)(b*TT + t) * (48*FF);

    for (int i = tid; i < 4096; i += 256) {
        int pos = i & 255, c = i >> 8;
        int pidx = (((c & 3) ^ (pos & 3)) << 2) + (c >> 2);
        Qf [pos*16 + pidx] = base[i] * QSCALE;
        Ksv[pos*16 + pidx] = to_tf32(base[4096 + i]);
        int pidx2 = (((pos & 3) ^ (c & 3)) << 2) + ((pos >> 2) & 3);
        Vsv[(pos >> 4)*256 + c*16 + pidx2] = to_tf32(base[8192 + i]);
    }
    __syncthreads();

    int w    = tid >> 5;
    int lane = tid & 31;
    int gid  = lane >> 2;
    int tig  = lane & 3;
    int fb   = w * 32;
    int sw   = (tig ^ (gid & 3)) << 2;
    float* Pw = Ps + w * (32*18);

    float o[2][2][4];
    #pragma unroll
    for (int m = 0; m < 2; m++)
        #pragma unroll
        for (int nc = 0; nc < 2; nc++)
            #pragma unroll
            for (int r = 0; r < 4; r++) o[m][nc][r] = 0.f;
    float rsA[2] = {0.f, 0.f}, rsB[2] = {0.f, 0.f};

    for (int ch = 0; ch < 16; ch++) {
        int y0 = 16*ch;

        u32 kb[2][2][2];
        #pragma unroll
        for (int n = 0; n < 2; n++) {
            float4 kv = *(const float4*)&Ksv[(y0 + 8*n + gid)*16 + sw];
            kb[0][n][0] = __float_as_uint(kv.x);
            kb[0][n][1] = __float_as_uint(kv.y);
            kb[1][n][0] = __float_as_uint(kv.z);
            kb[1][n][1] = __float_as_uint(kv.w);
        }

        #pragma unroll
        for (int m = 0; m < 2; m++) {
            int f0 = fb + 16*m + gid;
            float4 qr0 = *(const float4*)&Qf[f0*16 + sw];
            float4 qr8 = *(const float4*)&Qf[(f0+8)*16 + sw];

            float s[2][4];
            #pragma unroll
            for (int n = 0; n < 2; n++)
                #pragma unroll
                for (int r = 0; r < 4; r++) s[n][r] = 0.f;

            #pragma unroll
            for (int ks = 0; ks < 2; ks++) {
                float x0 = ks ? qr0.z : qr0.x;
                float x1 = ks ? qr8.z : qr8.x;
                float x2 = ks ? qr0.w : qr0.y;
                float x3 = ks ? qr8.w : qr8.y;
                u32 h0 = tf32_hi_bits(x0), h1 = tf32_hi_bits(x1);
                u32 h2 = tf32_hi_bits(x2), h3 = tf32_hi_bits(x3);
                u32 l0 = __float_as_uint(x0 - __uint_as_float(h0));
                u32 l1 = __float_as_uint(x1 - __uint_as_float(h1));
                u32 l2 = __float_as_uint(x2 - __uint_as_float(h2));
                u32 l3 = __float_as_uint(x3 - __uint_as_float(h3));
                #pragma unroll
                for (int n = 0; n < 2; n++) {
                    mma_tf32(s[n][0], s[n][1], s[n][2], s[n][3],
                             h0, h1, h2, h3, kb[ks][n][0], kb[ks][n][1]);
                    mma_tf32(s[n][0], s[n][1], s[n][2], s[n][3],
                             l0, l1, l2, l3, kb[ks][n][0], kb[ks][n][1]);
                }
            }
            int r0 = 16*m + gid;
            #pragma unroll
            for (int n = 0; n < 2; n++) {
                float p0 = tf32_mask(fexp2s(s[n][0]));
                float p1 = tf32_mask(fexp2s(s[n][1]));
                float p2 = tf32_mask(fexp2s(s[n][2]));
                float p3 = tf32_mask(fexp2s(s[n][3]));
                rsA[m] += p0 + p1;
                rsB[m] += p2 + p3;
                *(float2*)&Pw[r0*18 + 8*n + 2*tig]     = make_float2(p0, p1);
                *(float2*)&Pw[(r0+8)*18 + 8*n + 2*tig] = make_float2(p2, p3);
            }
        }
        __syncwarp();

        u32 vb[2][2][2];
        #pragma unroll
        for (int nc = 0; nc < 2; nc++) {
            float4 vv = *(const float4*)&Vsv[ch*256 + (8*nc + gid)*16 + sw];
            vb[0][nc][0] = __float_as_uint(vv.x);
            vb[0][nc][1] = __float_as_uint(vv.y);
            vb[1][nc][0] = __float_as_uint(vv.z);
            vb[1][nc][1] = __float_as_uint(vv.w);
        }

        #pragma unroll
        for (int m = 0; m < 2; m++) {
            int r0 = 16*m + gid;
            #pragma unroll
            for (int h = 0; h < 2; h++) {
                int cA = 8*h + tig;
                u32 pa0 = __float_as_uint(Pw[r0*18 + cA]);
                u32 pa1 = __float_as_uint(Pw[(r0+8)*18 + cA]);
                u32 pa2 = __float_as_uint(Pw[r0*18 + cA + 4]);
                u32 pa3 = __float_as_uint(Pw[(r0+8)*18 + cA + 4]);
                #pragma unroll
                for (int nc = 0; nc < 2; nc++)
                    mma_tf32(o[m][nc][0], o[m][nc][1], o[m][nc][2], o[m][nc][3],
                             pa0, pa1, pa2, pa3, vb[h][nc][0], vb[h][nc][1]);
            }
        }
        __syncwarp();
    }

    #pragma unroll
    for (int m = 0; m < 2; m++) {
        rsA[m] += __shfl_xor_sync(0xFFFFFFFFu, rsA[m], 1);
        rsA[m] += __shfl_xor_sync(0xFFFFFFFFu, rsA[m], 2);
        rsB[m] += __shfl_xor_sync(0xFFFFFFFFu, rsB[m], 1);
        rsB[m] += __shfl_xor_sync(0xFFFFFFFFu, rsB[m], 2);
    }

    float* op = g_fout_t + (size_t)(b*TT + t) * (16*FF);
    #pragma unroll
    for (int m = 0; m < 2; m++) {
        float invA = 1.0f / rsA[m], invB = 1.0f / rsB[m];
        int r0 = fb + 16*m + gid;
        #pragma unroll
        for (int nc = 0; nc < 2; nc++) {
            int c0 = 8*nc + 2*tig;
            op[c0*256 + r0]         = o[m][nc][0] * invA;
            op[(c0+1)*256 + r0]     = o[m][nc][1] * invA;
            op[c0*256 + r0 + 8]     = o[m][nc][2] * invB;
            op[(c0+1)*256 + r0 + 8] = o[m][nc][3] * invB;
        }
    }
}

// ---------------------------------------------------------------------------
// Kernel 5: time attention (causal) — tf32 mma version.
// Block = (f, b), 8 warps. 24 m-tiles of 16 rows; warp w owns tiles
// {w, 15-w, 16+w}  (balanced causal load: 34+w chunks per warp).
// Same swizzled Q/K/V layouts as fattn; causal mask on diagonal chunk only.
// ---------------------------------------------------------------------------
#define TATTN_SMEM ((6144*3 + 8*16*18) * 4)   // Qf, K, V, Ps = 82944 B

__global__ __launch_bounds__(256, 2) void k_tattn() {
    extern __shared__ __align__(16) float tsm2[];
    float* Qf  = tsm2;            // [t][perm c] full precision, scaled
    float* Ksv = tsm2 + 6144;     // [y][perm c] tf32
    float* Vsv = tsm2 + 12288;    // [ych][c][perm y] tf32
    float* Ps  = tsm2 + 18432;    // per-warp [16][18]

    int f = blockIdx.x, b = blockIdx.y;
    int tid = threadIdx.x;
    const float* qsrc = g_tqk  + (((size_t)b*32     )*FF + f)*TT;
    const float* ktb  = g_tqk  + (((size_t)b*32 + 16)*FF + f)*TT;
    const float* vb   = g_fout + (((size_t)b*16     )*FF + f)*TT;

    for (int i = tid; i < 6144; i += 256) {
        int pos = i % 384, c = i / 384;
        int pidx = (((c & 3) ^ (pos & 3)) << 2) + (c >> 2);
        Qf [pos*16 + pidx] = qsrc[(size_t)c*NN + pos] * QSCALE;
        Ksv[pos*16 + pidx] = to_tf32(ktb[(size_t)c*NN + pos]);
        int pidx2 = (((pos & 3) ^ (c & 3)) << 2) + ((pos >> 2) & 3);
        Vsv[(pos >> 4)*256 + c*16 + pidx2] = to_tf32(vb[(size_t)c*NN + pos]);
    }
    __syncthreads();

    int w    = tid >> 5;
    int lane = tid & 31;
    int gid  = lane >> 2;
    int tig  = lane & 3;
    int sw   = (tig ^ (gid & 3)) << 2;
    float* Pw = Ps + w * (16*18);
    float* op = g_tout + (((size_t)b*16)*FF + f)*TT;

    int tiles[3] = {w, 15 - w, 16 + w};
    #pragma unroll
    for (int ti = 0; ti < 3; ti++) {
        int m   = tiles[ti];
        int rg0 = m*16 + gid;
        float4 qr0 = *(const float4*)&Qf[rg0*16 + sw];
        float4 qr8 = *(const float4*)&Qf[(rg0+8)*16 + sw];

        // Q hi/lo frags hoisted once per tile
        u32 qh[2][4], ql[2][4];
        #pragma unroll
        for (int ks = 0; ks < 2; ks++) {
            float x0 = ks ? qr0.z : qr0.x;
            float x1 = ks ? qr8.z : qr8.x;
            float x2 = ks ? qr0.w : qr0.y;
            float x3 = ks ? qr8.w : qr8.y;
            qh[ks][0] = tf32_hi_bits(x0);
            qh[ks][1] = tf32_hi_bits(x1);
            qh[ks][2] = tf32_hi_bits(x2);
            qh[ks][3] = tf32_hi_bits(x3);
            ql[ks][0] = __float_as_uint(x0 - __uint_as_float(qh[ks][0]));
            ql[ks][1] = __float_as_uint(x1 - __uint_as_float(qh[ks][1]));
            ql[ks][2] = __float_as_uint(x2 - __uint_as_float(qh[ks][2]));
            ql[ks][3] = __float_as_uint(x3 - __uint_as_float(qh[ks][3]));
        }

        float o[2][4];
        #pragma unroll
        for (int nc = 0; nc < 2; nc++)
            #pragma unroll
            for (int r = 0; r < 4; r++) o[nc][r] = 0.f;
        float rsA = 0.f, rsB = 0.f;

        for (int ch = 0; ch <= m; ch++) {
            int y0 = ch*16;

            u32 kb[2][2][2];
            #pragma unroll
            for (int n = 0; n < 2; n++) {
                float4 kv = *(const float4*)&Ksv[(y0 + 8*n + gid)*16 + sw];
                kb[0][n][0] = __float_as_uint(kv.x);
                kb[0][n][1] = __float_as_uint(kv.y);
                kb[1][n][0] = __float_as_uint(kv.z);
                kb[1][n][1] = __float_as_uint(kv.w);
            }

            float s[2][4];
            #pragma unroll
            for (int n = 0; n < 2; n++)
                #pragma unroll
                for (int r = 0; r < 4; r++) s[n][r] = 0.f;
            #pragma unroll
            for (int ks = 0; ks < 2; ks++)
                #pragma unroll
                for (int n = 0; n < 2; n++) {
                    mma_tf32(s[n][0], s[n][1], s[n][2], s[n][3],
                             qh[ks][0], qh[ks][1], qh[ks][2], qh[ks][3],
                             kb[ks][n][0], kb[ks][n][1]);
                    mma_tf32(s[n][0], s[n][1], s[n][2], s[n][3],
                             ql[ks][0], ql[ks][1], ql[ks][2], ql[ks][3],
                             kb[ks][n][0], kb[ks][n][1]);
                }

            bool diag = (ch == m);
            #pragma unroll
            for (int n = 0; n < 2; n++) {
                float p0 = tf32_mask(fexp2s(s[n][0]));
                float p1 = tf32_mask(fexp2s(s[n][1]));
                float p2 = tf32_mask(fexp2s(s[n][2]));
                float p3 = tf32_mask(fexp2s(s[n][3]));
                if (diag) {                     // causal: col <= row (local)
                    int c0 = 8*n + 2*tig;
                    if (c0     > gid)     p0 = 0.f;
                    if (c0 + 1 > gid)     p1 = 0.f;
                    if (c0     > gid + 8) p2 = 0.f;
                    if (c0 + 1 > gid + 8) p3 = 0.f;
                }
                rsA += p0 + p1;
                rsB += p2 + p3;
                *(float2*)&Pw[gid*18 + 8*n + 2*tig]     = make_float2(p0, p1);
                *(float2*)&Pw[(gid+8)*18 + 8*n + 2*tig] = make_float2(p2, p3);
            }
            __syncwarp();

            u32 vbf[2][2][2];
            #pragma unroll
            for (int nc = 0; nc < 2; nc++) {
                float4 vv = *(const float4*)&Vsv[ch*256 + (8*nc + gid)*16 + sw];
                vbf[0][nc][0] = __float_as_uint(vv.x);
                vbf[0][nc][1] = __float_as_uint(vv.y);
                vbf[1][nc][0] = __float_as_uint(vv.z);
                vbf[1][nc][1] = __float_as_uint(vv.w);
            }

            #pragma unroll
            for (int h = 0; h < 2; h++) {
                int cA = 8*h + tig;
                u32 pa0 = __float_as_uint(Pw[gid*18 + cA]);
                u32 pa1 = __float_as_uint(Pw[(gid+8)*18 + cA]);
                u32 pa2 = __float_as_uint(Pw[gid*18 + cA + 4]);
                u32 pa3 = __float_as_uint(Pw[(gid+8)*18 + cA + 4]);
                #pragma unroll
                for (int nc = 0; nc < 2; nc++)
                    mma_tf32(o[nc][0], o[nc][1], o[nc][2], o[nc][3],
                             pa0, pa1, pa2, pa3, vbf[h][nc][0], vbf[h][nc][1]);
            }
            __syncwarp();
        }

        rsA += __shfl_xor_sync(0xFFFFFFFFu, rsA, 1);
        rsA += __shfl_xor_sync(0xFFFFFFFFu, rsA, 2);
        rsB += __shfl_xor_sync(0xFFFFFFFFu, rsB, 1);
        rsB += __shfl_xor_sync(0xFFFFFFFFu, rsB, 2);
        float invA = 1.0f / rsA, invB = 1.0f / rsB;

        #pragma unroll
        for (int nc = 0; nc < 2; nc++) {
            int c0 = 8*nc + 2*tig;
            op[(size_t)c0*NN + rg0]           = o[nc][0] * invA;
            op[(size_t)(c0+1)*NN + rg0]       = o[nc][1] * invA;
            op[(size_t)c0*NN + rg0 + 8]       = o[nc][2] * invB;
            op[(size_t)(c0+1)*NN + rg0 + 8]   = o[nc][3] * invB;
        }
    }
}

// ---------------------------------------------------------------------------
// Kernel 6: proj conv1x1 (64<-16) + BN + PReLU + residual (packed FMA)
// ---------------------------------------------------------------------------
__global__ __launch_bounds__(256) void k_proj(
    const float* __restrict__ x,
    const float* __restrict__ pw, const float* __restrict__ pg,
    const float* __restrict__ pb, const float* __restrict__ pm,
    const float* __restrict__ pv, const float* __restrict__ pa,
    float* __restrict__ out)
{
    __shared__ float ws[64*16];
    __shared__ float sa[64], sbb[64], sal[64];
    int tid = threadIdx.x;
    for (int i = tid; i < 1024; i += 256) ws[i] = pw[i];
    if (tid < 64) {
        float a = pg[tid] * rsqrtf(pv[tid] + 1e-5f);
        sa[tid] = a; sbb[tid] = pb[tid] - pm[tid]*a; sal[tid] = pa[tid];
    }
    __syncthreads();

    size_t p   = (size_t)blockIdx.x*256 + tid;
    int    b   = (int)(p / NN);
    int    rem = (int)(p % NN);

    u64 tv[8];
    #pragma unroll
    for (int c = 0; c < 8; c++)
        tv[c] = pack2(g_tout[((size_t)b*16 + 2*c  )*NN + rem],
                      g_tout[((size_t)b*16 + 2*c+1)*NN + rem]);

    const float* xb = x   + (size_t)b*CC*NN + rem;
    float*       ob = out + (size_t)b*CC*NN + rem;
    for (int o = 0; o < 64; o++) {
        const ulonglong2* wp = (const ulonglong2*)(ws + o*16);
        ulonglong2 w0 = wp[0], w1 = wp[1], w2 = wp[2], w3 = wp[3];
        u64 a0 = fma2(tv[0], w0.x, 0), a1 = fma2(tv[1], w0.y, 0);
        a0 = fma2(tv[2], w1.x, a0);  a1 = fma2(tv[3], w1.y, a1);
        a0 = fma2(tv[4], w2.x, a0);  a1 = fma2(tv[5], w2.y, a1);
        a0 = fma2(tv[6], w3.x, a0);  a1 = fma2(tv[7], w3.y, a1);
        float acc = hsum2(add2(a0, a1));
        float yn = acc*sa[o] + sbb[o];
        float r  = yn >= 0.f ? yn : sal[o]*yn;
        ob[(size_t)o*NN] = r + xb[(size_t)o*NN];
    }
}

// ---------------------------------------------------------------------------
extern "C" void kernel_launch(void* const* d_in, const int* in_sizes, int n_in,
                              void* d_out, int out_size)
{
    const float* x   = (const float*)d_in[0];
    const float* fw  = (const float*)d_in[1];
    const float* fg  = (const float*)d_in[2];
    const float* fb  = (const float*)d_in[3];
    const float* fm  = (const float*)d_in[4];
    const float* fv  = (const float*)d_in[5];
    const float* fa  = (const float*)d_in[6];
    const float* tw  = (const float*)d_in[7];
    const float* tg  = (const float*)d_in[8];
    const float* tb  = (const float*)d_in[9];
    const float* tm  = (const float*)d_in[10];
    const float* tvv = (const float*)d_in[11];
    const float* ta  = (const float*)d_in[12];
    const float* pw  = (const float*)d_in[13];
    const float* pg  = (const float*)d_in[14];
    const float* pb  = (const float*)d_in[15];
    const float* pm  = (const float*)d_in[16];
    const float* pv  = (const float*)d_in[17];
    const float* pa  = (const float*)d_in[18];
    float*       out = (float*)d_out;

    cudaFuncSetAttribute(k_tattn, cudaFuncAttributeMaxDynamicSharedMemorySize,
                         TATTN_SMEM);
    cudaFuncSetAttribute(k_fattn, cudaFuncAttributeMaxDynamicSharedMemorySize,
                         FATTN_SMEM);

    // 0) dummy — keeps ncu's fixed profiled launch slot on k_fattn (control)
    k_dummy<<<1, 32>>>();

    // 1) fused qkv convs + BN + PReLU
    k_qkv<<<PP/256, 256>>>(x, fw, fg, fb, fm, fv, fa, tw, tg, tb, tm, tvv, ta);

    // 2) transpose fqkv: [b][cf][t] -> [b][t][cf]
    k_trans_qkv<<<dim3(384/32, 12288/32, BB), dim3(32,8)>>>();

    // 3) frequency attention — tf32 mma v2  (launch #4 == profiled slot)
    k_fattn<<<dim3(TT, BB), 256, FATTN_SMEM>>>();

    // 4) transpose f_out: [b][t][cf] -> [b][cf][t]
    k_trans_fout<<<dim3(4096/32, 384/32, BB), dim3(32,8)>>>();

    // 5) time attention (causal) — tf32 mma
    k_tattn<<<dim3(FF, BB), 256, TATTN_SMEM>>>();

    // 6) proj + BN + PReLU + residual
    k_proj<<<PP/256, 256>>>(x, pw, pg, pb, pm, pv, pa, out);
}

// round 14
// speedup vs baseline: 1.4077x; 1.0198x over previous
#include <cuda_runtime.h>
#include <cuda_bf16.h>

// Shapes
#define BB   4
#define CC   64
#define DCC  16
#define FF   256
#define TT   384
#define NN   (FF*TT)          // 98304
#define PP   (BB*NN)          // 393216

typedef unsigned long long u64;
typedef unsigned int u32;

// 0.25 (1/sqrt(DC)) * log2(e): dot computed in log2 domain
#define QSCALE 0.36067376022224085f

// ---------------------------------------------------------------------------
// Scratch (device globals; allocation is forbidden)
// ---------------------------------------------------------------------------
__device__ float g_fqkv   [(size_t)BB*48*NN];  // [b][c48][f][t]   natural
__device__ float g_fqkv_t [(size_t)BB*48*NN];  // [b][t][c48][f]   transposed
__device__ float g_tqk    [(size_t)BB*32*NN];  // [b][c32][f][t]   natural
__device__ float g_fout_t [(size_t)BB*16*NN];  // [b][t][c16][f]
__device__ float g_fout   [(size_t)BB*16*NN];  // [b][c16][f][t]
__device__ float g_tout   [(size_t)BB*16*NN];  // [b][c16][f][t]

// ---------------------------------------------------------------------------
// Packed f32x2 helpers (scalar kernels)
// ---------------------------------------------------------------------------
__device__ __forceinline__ u64 fma2(u64 a, u64 b, u64 c) {
    u64 d;
    asm("fma.rn.f32x2 %0, %1, %2, %3;" : "=l"(d) : "l"(a), "l"(b), "l"(c));
    return d;
}
__device__ __forceinline__ u64 add2(u64 a, u64 b) {
    u64 d;
    asm("add.rn.f32x2 %0, %1, %2;" : "=l"(d) : "l"(a), "l"(b));
    return d;
}
__device__ __forceinline__ u64 pack2(float lo, float hi) {
    u64 d;
    asm("mov.b64 %0, {%1, %2};" : "=l"(d) : "f"(lo), "f"(hi));
    return d;
}
__device__ __forceinline__ void unpack2(u64 a, float& lo, float& hi) {
    asm("mov.b64 {%0, %1}, %2;" : "=f"(lo), "=f"(hi) : "l"(a));
}
__device__ __forceinline__ float hsum2(u64 a) {
    float lo, hi; unpack2(a, lo, hi); return lo + hi;
}

// Scalar 2^t, FMA-immediate form (no constant registers).
__device__ __forceinline__ float fexp2s(float t) {
    float z  = t + 12582912.0f;
    float fi = z - 12582912.0f;
    float u  = t - fi;
    float p  = fmaf(u, 9.6181291076e-3f, 5.5504108664e-2f);
    p = fmaf(u, p, 2.4022650696e-1f);
    p = fmaf(u, p, 6.9314718056e-1f);
    p = fmaf(u, p, 1.0f);
    unsigned sc = (__float_as_uint(z) + 0xB4C0007Fu) << 23;
    return p * __uint_as_float(sc);
}

// ---------------------------------------------------------------------------
// tf32 mma helpers
// ---------------------------------------------------------------------------
__device__ __forceinline__ float to_tf32(float x) {
    u32 r; asm("cvt.rna.tf32.f32 %0, %1;" : "=r"(r) : "f"(x));
    return __uint_as_float(r);
}
__device__ __forceinline__ void mma_tf32(
    float& d0, float& d1, float& d2, float& d3,
    u32 a0, u32 a1, u32 a2, u32 a3, u32 b0, u32 b1)
{
    asm volatile(
        "mma.sync.aligned.m16n8k8.row.col.f32.tf32.tf32.f32 "
        "{%0,%1,%2,%3},{%4,%5,%6,%7},{%8,%9},{%0,%1,%2,%3};"
        : "+f"(d0), "+f"(d1), "+f"(d2), "+f"(d3)
        : "r"(a0), "r"(a1), "r"(a2), "r"(a3), "r"(b0), "r"(b1));
}
__device__ __forceinline__ float tf32_mask(float x) {
    return __uint_as_float(__float_as_uint(x) & 0xFFFFE000u);
}
__device__ __forceinline__ u32 tf32_hi_bits(float x) {
    return __float_as_uint(x) & 0xFFFFE000u;
}

// ---------------------------------------------------------------------------
// Dummy kernel (x3): shifts the ncu profiled launch slot onto k_qkv.
// ---------------------------------------------------------------------------
__global__ void k_dummy() {}

// ---------------------------------------------------------------------------
// Kernel 1: fused fqkv (48ch) + tqk (32ch) conv1x1 + BN + PReLU — tf32 mma.
// Block = 128-position tile, 256 threads / 8 warps (16 positions per warp).
// W staged full fp32 (hi/lo reg split = exact); x staged tf32-rna.
// Swizzled frag layout, row stride 68 words (4-way STS, conflict-free LDS.128).
// ---------------------------------------------------------------------------
#define QKV_SMEM ((80*68 + 128*68 + 240) * 4)   // Wf, Xs, bn params = 57536 B

__global__ __launch_bounds__(256, 2) void k_qkv(
    const float* __restrict__ x,
    const float* __restrict__ fw, const float* __restrict__ fg,
    const float* __restrict__ fb, const float* __restrict__ fm,
    const float* __restrict__ fv, const float* __restrict__ fa,
    const float* __restrict__ tw, const float* __restrict__ tg,
    const float* __restrict__ tb, const float* __restrict__ tm,
    const float* __restrict__ tvv, const float* __restrict__ ta)
{
    extern __shared__ __align__(16) float qsm[];
    float* Wf  = qsm;                 // [80][4g][16 perm], stride 68
    float* Xs  = qsm + 80*68;         // [128 pos][4g][16 perm], stride 68
    float* sa  = qsm + 80*68 + 128*68;
    float* sbb = sa + 80;
    float* sal = sbb + 80;

    int tid = threadIdx.x;

    // Stage W full precision in swizzled frag order
    for (int i = tid; i < 80*64; i += 256) {
        int m = i >> 6, k = i & 63;
        float wv = (m < 48) ? fw[i] : tw[i - 48*64];
        int g = k >> 4, c = k & 15;
        int pidx = (((c & 3) ^ (m & 3)) << 2) + (c >> 2);
        Wf[m*68 + g*16 + pidx] = wv;
    }
    if (tid < 80) {
        float g, be, mn, vr, al;
        if (tid < 48) { g=fg[tid]; be=fb[tid]; mn=fm[tid]; vr=fv[tid]; al=fa[tid]; }
        else { int o=tid-48; g=tg[o]; be=tb[o]; mn=tm[o]; vr=tvv[o]; al=ta[o]; }
        float a = g * rsqrtf(vr + 1e-5f);
        sa[tid] = a; sbb[tid] = be - mn*a; sal[tid] = al;
    }

    size_t p0   = (size_t)blockIdx.x * 128;
    int    b    = (int)(p0 / NN);
    int    rem0 = (int)(p0 % NN);
    const float* xb = x + (size_t)b*CC*NN + rem0;

    // Stage x tile [128 pos][64 c], tf32-rounded, swizzled (coalesced gmem)
    for (int i = tid; i < 128*64; i += 256) {
        int pos = i & 127, k = i >> 7;
        float xv = to_tf32(xb[(size_t)k*NN + pos]);
        int g = k >> 4, c = k & 15;
        int pidx = (((c & 3) ^ (pos & 3)) << 2) + (c >> 2);
        Xs[pos*68 + g*16 + pidx] = xv;
    }
    __syncthreads();

    int w    = tid >> 5;
    int lane = tid & 31;
    int gid  = lane >> 2;
    int tig  = lane & 3;
    int sw   = (tig ^ (gid & 3)) << 2;
    int pw0  = w * 16;                 // warp's position base

    #pragma unroll
    for (int mt = 0; mt < 5; mt++) {
        int m0 = mt*16 + gid;

        // W A-frags for 8 kchunks, hi/lo split (exact)
        u32 ah[8][4], al_[8][4];
        #pragma unroll
        for (int g = 0; g < 4; g++) {
            float4 w0 = *(const float4*)&Wf[m0*68 + g*16 + sw];
            float4 w8 = *(const float4*)&Wf[(m0+8)*68 + g*16 + sw];
            float v[2][4] = {{w0.x, w8.x, w0.y, w8.y},     // kchunk 2g
                             {w0.z, w8.z, w0.w, w8.w}};    // kchunk 2g+1
            #pragma unroll
            for (int s = 0; s < 2; s++)
                #pragma unroll
                for (int r = 0; r < 4; r++) {
                    u32 h = tf32_hi_bits(v[s][r]);
                    ah [2*g+s][r] = h;
                    al_[2*g+s][r] = __float_as_uint(v[s][r] - __uint_as_float(h));
                }
        }

        float sa0 = sa[m0],  sb0 = sbb[m0],  sl0 = sal[m0];
        float sa8 = sa[m0+8], sb8 = sbb[m0+8], sl8 = sal[m0+8];

        #pragma unroll
        for (int nf = 0; nf < 2; nf++) {
            // x B-frags for 8 kchunks
            u32 xbf[8][2];
            #pragma unroll
            for (int g = 0; g < 4; g++) {
                float4 xv = *(const float4*)&Xs[(pw0 + 8*nf + gid)*68 + g*16 + sw];
                xbf[2*g  ][0] = __float_as_uint(xv.x);
                xbf[2*g  ][1] = __float_as_uint(xv.y);
                xbf[2*g+1][0] = __float_as_uint(xv.z);
                xbf[2*g+1][1] = __float_as_uint(xv.w);
            }
            float d0 = 0.f, d1 = 0.f, d2 = 0.f, d3 = 0.f;
            #pragma unroll
            for (int kc = 0; kc < 8; kc++) {
                mma_tf32(d0, d1, d2, d3,
                         ah[kc][0], ah[kc][1], ah[kc][2], ah[kc][3],
                         xbf[kc][0], xbf[kc][1]);
                mma_tf32(d0, d1, d2, d3,
                         al_[kc][0], al_[kc][1], al_[kc][2], al_[kc][3],
                         xbf[kc][0], xbf[kc][1]);
            }
            // BN + PReLU epilogue
            float y0 = d0*sa0 + sb0;  float r0 = y0 >= 0.f ? y0 : sl0*y0;
            float y1 = d1*sa0 + sb0;  float r1 = y1 >= 0.f ? y1 : sl0*y1;
            float y2 = d2*sa8 + sb8;  float r2 = y2 >= 0.f ? y2 : sl8*y2;
            float y3 = d3*sa8 + sb8;  float r3 = y3 >= 0.f ? y3 : sl8*y3;

            int pos = rem0 + pw0 + 8*nf + 2*tig;
            if (mt < 3) {   // rows 0..47 -> g_fqkv
                *(float2*)&g_fqkv[((size_t)b*48 + m0    )*NN + pos] = make_float2(r0, r1);
                *(float2*)&g_fqkv[((size_t)b*48 + m0 + 8)*NN + pos] = make_float2(r2, r3);
            } else {        // rows 48..79 -> g_tqk
                *(float2*)&g_tqk[((size_t)b*32 + m0 - 48)*NN + pos] = make_float2(r0, r1);
                *(float2*)&g_tqk[((size_t)b*32 + m0 - 40)*NN + pos] = make_float2(r2, r3);
            }
        }
    }
}

// ---------------------------------------------------------------------------
// Transposes (32x32 smem tiles, coalesced both ways)
// ---------------------------------------------------------------------------
__global__ void k_trans_qkv() {  // [b][cf=12288][t=384] -> [b][t][cf]
    __shared__ float tile[32][33];
    int b = blockIdx.z;
    size_t base = (size_t)b * 12288 * 384;
    int r0 = blockIdx.y*32, q0 = blockIdx.x*32;
    for (int i = threadIdx.y; i < 32; i += 8)
        tile[i][threadIdx.x] = g_fqkv[base + (size_t)(r0+i)*384 + q0 + threadIdx.x];
    __syncthreads();
    for (int i = threadIdx.y; i < 32; i += 8)
        g_fqkv_t[base + (size_t)(q0+i)*12288 + r0 + threadIdx.x] = tile[threadIdx.x][i];
}

__global__ void k_trans_fout() { // [b][t=384][cf=4096] -> [b][cf][t]
    __shared__ float tile[32][33];
    int b = blockIdx.z;
    size_t base = (size_t)b * 4096 * 384;
    int r0 = blockIdx.y*32, q0 = blockIdx.x*32;
    for (int i = threadIdx.y; i < 32; i += 8)
        tile[i][threadIdx.x] = g_fout_t[base + (size_t)(r0+i)*4096 + q0 + threadIdx.x];
    __syncthreads();
    for (int i = threadIdx.y; i < 32; i += 8)
        g_fout[base + (size_t)(q0+i)*384 + r0 + threadIdx.x] = tile[threadIdx.x][i];
}

// ---------------------------------------------------------------------------
// Kernel 3: frequency attention — tf32 mma flash-attention v2 (unchanged)
// ---------------------------------------------------------------------------
#define FATTN_SMEM ((4096 + 4096 + 4096 + 8*32*18) * 4)   // Qf, K, V, Ps

__global__ __launch_bounds__(256, 3) void k_fattn() {
    extern __shared__ __align__(16) float fsm[];
    float* Qf  = fsm;             // [f][perm c] full precision, scaled
    float* Ksv = fsm + 4096;      // [y][perm c] tf32
    float* Vsv = fsm + 8192;      // [ych][c][perm y] tf32
    float* Ps  = fsm + 12288;     // per-warp [32][18]

    int t = blockIdx.x, b = blockIdx.y;
    int tid  = threadIdx.x;
    const float* base = g_fqkv_t + (size_t)(b*TT + t) * (48*FF);

    for (int i = tid; i < 4096; i += 256) {
        int pos = i & 255, c = i >> 8;
        int pidx = (((c & 3) ^ (pos & 3)) << 2) + (c >> 2);
        Qf [pos*16 + pidx] = base[i] * QSCALE;
        Ksv[pos*16 + pidx] = to_tf32(base[4096 + i]);
        int pidx2 = (((pos & 3) ^ (c & 3)) << 2) + ((pos >> 2) & 3);
        Vsv[(pos >> 4)*256 + c*16 + pidx2] = to_tf32(base[8192 + i]);
    }
    __syncthreads();

    int w    = tid >> 5;
    int lane = tid & 31;
    int gid  = lane >> 2;
    int tig  = lane & 3;
    int fb   = w * 32;
    int sw   = (tig ^ (gid & 3)) << 2;
    float* Pw = Ps + w * (32*18);

    float o[2][2][4];
    #pragma unroll
    for (int m = 0; m < 2; m++)
        #pragma unroll
        for (int nc = 0; nc < 2; nc++)
            #pragma unroll
            for (int r = 0; r < 4; r++) o[m][nc][r] = 0.f;
    float rsA[2] = {0.f, 0.f}, rsB[2] = {0.f, 0.f};

    for (int ch = 0; ch < 16; ch++) {
        int y0 = 16*ch;

        u32 kb[2][2][2];
        #pragma unroll
        for (int n = 0; n < 2; n++) {
            float4 kv = *(const float4*)&Ksv[(y0 + 8*n + gid)*16 + sw];
            kb[0][n][0] = __float_as_uint(kv.x);
            kb[0][n][1] = __float_as_uint(kv.y);
            kb[1][n][0] = __float_as_uint(kv.z);
            kb[1][n][1] = __float_as_uint(kv.w);
        }

        #pragma unroll
        for (int m = 0; m < 2; m++) {
            int f0 = fb + 16*m + gid;
            float4 qr0 = *(const float4*)&Qf[f0*16 + sw];
            float4 qr8 = *(const float4*)&Qf[(f0+8)*16 + sw];

            float s[2][4];
            #pragma unroll
            for (int n = 0; n < 2; n++)
                #pragma unroll
                for (int r = 0; r < 4; r++) s[n][r] = 0.f;

            #pragma unroll
            for (int ks = 0; ks < 2; ks++) {
                float x0 = ks ? qr0.z : qr0.x;
                float x1 = ks ? qr8.z : qr8.x;
                float x2 = ks ? qr0.w : qr0.y;
                float x3 = ks ? qr8.w : qr8.y;
                u32 h0 = tf32_hi_bits(x0), h1 = tf32_hi_bits(x1);
                u32 h2 = tf32_hi_bits(x2), h3 = tf32_hi_bits(x3);
                u32 l0 = __float_as_uint(x0 - __uint_as_float(h0));
                u32 l1 = __float_as_uint(x1 - __uint_as_float(h1));
                u32 l2 = __float_as_uint(x2 - __uint_as_float(h2));
                u32 l3 = __float_as_uint(x3 - __uint_as_float(h3));
                #pragma unroll
                for (int n = 0; n < 2; n++) {
                    mma_tf32(s[n][0], s[n][1], s[n][2], s[n][3],
                             h0, h1, h2, h3, kb[ks][n][0], kb[ks][n][1]);
                    mma_tf32(s[n][0], s[n][1], s[n][2], s[n][3],
                             l0, l1, l2, l3, kb[ks][n][0], kb[ks][n][1]);
                }
            }
            int r0 = 16*m + gid;
            #pragma unroll
            for (int n = 0; n < 2; n++) {
                float p0 = tf32_mask(fexp2s(s[n][0]));
                float p1 = tf32_mask(fexp2s(s[n][1]));
                float p2 = tf32_mask(fexp2s(s[n][2]));
                float p3 = tf32_mask(fexp2s(s[n][3]));
                rsA[m] += p0 + p1;
                rsB[m] += p2 + p3;
                *(float2*)&Pw[r0*18 + 8*n + 2*tig]     = make_float2(p0, p1);
                *(float2*)&Pw[(r0+8)*18 + 8*n + 2*tig] = make_float2(p2, p3);
            }
        }
        __syncwarp();

        u32 vb[2][2][2];
        #pragma unroll
        for (int nc = 0; nc < 2; nc++) {
            float4 vv = *(const float4*)&Vsv[ch*256 + (8*nc + gid)*16 + sw];
            vb[0][nc][0] = __float_as_uint(vv.x);
            vb[0][nc][1] = __float_as_uint(vv.y);
            vb[1][nc][0] = __float_as_uint(vv.z);
            vb[1][nc][1] = __float_as_uint(vv.w);
        }

        #pragma unroll
        for (int m = 0; m < 2; m++) {
            int r0 = 16*m + gid;
            #pragma unroll
            for (int h = 0; h < 2; h++) {
                int cA = 8*h + tig;
                u32 pa0 = __float_as_uint(Pw[r0*18 + cA]);
                u32 pa1 = __float_as_uint(Pw[(r0+8)*18 + cA]);
                u32 pa2 = __float_as_uint(Pw[r0*18 + cA + 4]);
                u32 pa3 = __float_as_uint(Pw[(r0+8)*18 + cA + 4]);
                #pragma unroll
                for (int nc = 0; nc < 2; nc++)
                    mma_tf32(o[m][nc][0], o[m][nc][1], o[m][nc][2], o[m][nc][3],
                             pa0, pa1, pa2, pa3, vb[h][nc][0], vb[h][nc][1]);
            }
        }
        __syncwarp();
    }

    #pragma unroll
    for (int m = 0; m < 2; m++) {
        rsA[m] += __shfl_xor_sync(0xFFFFFFFFu, rsA[m], 1);
        rsA[m] += __shfl_xor_sync(0xFFFFFFFFu, rsA[m], 2);
        rsB[m] += __shfl_xor_sync(0xFFFFFFFFu, rsB[m], 1);
        rsB[m] += __shfl_xor_sync(0xFFFFFFFFu, rsB[m], 2);
    }

    float* op = g_fout_t + (size_t)(b*TT + t) * (16*FF);
    #pragma unroll
    for (int m = 0; m < 2; m++) {
        float invA = 1.0f / rsA[m], invB = 1.0f / rsB[m];
        int r0 = fb + 16*m + gid;
        #pragma unroll
        for (int nc = 0; nc < 2; nc++) {
            int c0 = 8*nc + 2*tig;
            op[c0*256 + r0]         = o[m][nc][0] * invA;
            op[(c0+1)*256 + r0]     = o[m][nc][1] * invA;
            op[c0*256 + r0 + 8]     = o[m][nc][2] * invB;
            op[(c0+1)*256 + r0 + 8] = o[m][nc][3] * invB;
        }
    }
}

// ---------------------------------------------------------------------------
// Kernel 5: time attention (causal) — tf32 mma (unchanged R13)
// ---------------------------------------------------------------------------
#define TATTN_SMEM ((6144*3 + 8*16*18) * 4)   // Qf, K, V, Ps = 82944 B

__global__ __launch_bounds__(256, 2) void k_tattn() {
    extern __shared__ __align__(16) float tsm2[];
    float* Qf  = tsm2;            // [t][perm c] full precision, scaled
    float* Ksv = tsm2 + 6144;     // [y][perm c] tf32
    float* Vsv = tsm2 + 12288;    // [ych][c][perm y] tf32
    float* Ps  = tsm2 + 18432;    // per-warp [16][18]

    int f = blockIdx.x, b = blockIdx.y;
    int tid = threadIdx.x;
    const float* qsrc = g_tqk  + (((size_t)b*32     )*FF + f)*TT;
    const float* ktb  = g_tqk  + (((size_t)b*32 + 16)*FF + f)*TT;
    const float* vb   = g_fout + (((size_t)b*16     )*FF + f)*TT;

    for (int i = tid; i < 6144; i += 256) {
        int pos = i % 384, c = i / 384;
        int pidx = (((c & 3) ^ (pos & 3)) << 2) + (c >> 2);
        Qf [pos*16 + pidx] = qsrc[(size_t)c*NN + pos] * QSCALE;
        Ksv[pos*16 + pidx] = to_tf32(ktb[(size_t)c*NN + pos]);
        int pidx2 = (((pos & 3) ^ (c & 3)) << 2) + ((pos >> 2) & 3);
        Vsv[(pos >> 4)*256 + c*16 + pidx2] = to_tf32(vb[(size_t)c*NN + pos]);
    }
    __syncthreads();

    int w    = tid >> 5;
    int lane = tid & 31;
    int gid  = lane >> 2;
    int tig  = lane & 3;
    int sw   = (tig ^ (gid & 3)) << 2;
    float* Pw = Ps + w * (16*18);
    float* op = g_tout + (((size_t)b*16)*FF + f)*TT;

    int tiles[3] = {w, 15 - w, 16 + w};
    #pragma unroll
    for (int ti = 0; ti < 3; ti++) {
        int m   = tiles[ti];
        int rg0 = m*16 + gid;
        float4 qr0 = *(const float4*)&Qf[rg0*16 + sw];
        float4 qr8 = *(const float4*)&Qf[(rg0+8)*16 + sw];

        u32 qh[2][4], ql[2][4];
        #pragma unroll
        for (int ks = 0; ks < 2; ks++) {
            float x0 = ks ? qr0.z : qr0.x;
            float x1 = ks ? qr8.z : qr8.x;
            float x2 = ks ? qr0.w : qr0.y;
            float x3 = ks ? qr8.w : qr8.y;
            qh[ks][0] = tf32_hi_bits(x0);
            qh[ks][1] = tf32_hi_bits(x1);
            qh[ks][2] = tf32_hi_bits(x2);
            qh[ks][3] = tf32_hi_bits(x3);
            ql[ks][0] = __float_as_uint(x0 - __uint_as_float(qh[ks][0]));
            ql[ks][1] = __float_as_uint(x1 - __uint_as_float(qh[ks][1]));
            ql[ks][2] = __float_as_uint(x2 - __uint_as_float(qh[ks][2]));
            ql[ks][3] = __float_as_uint(x3 - __uint_as_float(qh[ks][3]));
        }

        float o[2][4];
        #pragma unroll
        for (int nc = 0; nc < 2; nc++)
            #pragma unroll
            for (int r = 0; r < 4; r++) o[nc][r] = 0.f;
        float rsA = 0.f, rsB = 0.f;

        for (int ch = 0; ch <= m; ch++) {
            int y0 = ch*16;

            u32 kb[2][2][2];
            #pragma unroll
            for (int n = 0; n < 2; n++) {
                float4 kv = *(const float4*)&Ksv[(y0 + 8*n + gid)*16 + sw];
                kb[0][n][0] = __float_as_uint(kv.x);
                kb[0][n][1] = __float_as_uint(kv.y);
                kb[1][n][0] = __float_as_uint(kv.z);
                kb[1][n][1] = __float_as_uint(kv.w);
            }

            float s[2][4];
            #pragma unroll
            for (int n = 0; n < 2; n++)
                #pragma unroll
                for (int r = 0; r < 4; r++) s[n][r] = 0.f;
            #pragma unroll
            for (int ks = 0; ks < 2; ks++)
                #pragma unroll
                for (int n = 0; n < 2; n++) {
                    mma_tf32(s[n][0], s[n][1], s[n][2], s[n][3],
                             qh[ks][0], qh[ks][1], qh[ks][2], qh[ks][3],
                             kb[ks][n][0], kb[ks][n][1]);
                    mma_tf32(s[n][0], s[n][1], s[n][2], s[n][3],
                             ql[ks][0], ql[ks][1], ql[ks][2], ql[ks][3],
                             kb[ks][n][0], kb[ks][n][1]);
                }

            bool diag = (ch == m);
            #pragma unroll
            for (int n = 0; n < 2; n++) {
                float p0 = tf32_mask(fexp2s(s[n][0]));
                float p1 = tf32_mask(fexp2s(s[n][1]));
                float p2 = tf32_mask(fexp2s(s[n][2]));
                float p3 = tf32_mask(fexp2s(s[n][3]));
                if (diag) {
                    int c0 = 8*n + 2*tig;
                    if (c0     > gid)     p0 = 0.f;
                    if (c0 + 1 > gid)     p1 = 0.f;
                    if (c0     > gid + 8) p2 = 0.f;
                    if (c0 + 1 > gid + 8) p3 = 0.f;
                }
                rsA += p0 + p1;
                rsB += p2 + p3;
                *(float2*)&Pw[gid*18 + 8*n + 2*tig]     = make_float2(p0, p1);
                *(float2*)&Pw[(gid+8)*18 + 8*n + 2*tig] = make_float2(p2, p3);
            }
            __syncwarp();

            u32 vbf[2][2][2];
            #pragma unroll
            for (int nc = 0; nc < 2; nc++) {
                float4 vv = *(const float4*)&Vsv[ch*256 + (8*nc + gid)*16 + sw];
                vbf[0][nc][0] = __float_as_uint(vv.x);
                vbf[0][nc][1] = __float_as_uint(vv.y);
                vbf[1][nc][0] = __float_as_uint(vv.z);
                vbf[1][nc][1] = __float_as_uint(vv.w);
            }

            #pragma unroll
            for (int h = 0; h < 2; h++) {
                int cA = 8*h + tig;
                u32 pa0 = __float_as_uint(Pw[gid*18 + cA]);
                u32 pa1 = __float_as_uint(Pw[(gid+8)*18 + cA]);
                u32 pa2 = __float_as_uint(Pw[gid*18 + cA + 4]);
                u32 pa3 = __float_as_uint(Pw[(gid+8)*18 + cA + 4]);
                #pragma unroll
                for (int nc = 0; nc < 2; nc++)
                    mma_tf32(o[nc][0], o[nc][1], o[nc][2], o[nc][3],
                             pa0, pa1, pa2, pa3, vbf[h][nc][0], vbf[h][nc][1]);
            }
            __syncwarp();
        }

        rsA += __shfl_xor_sync(0xFFFFFFFFu, rsA, 1);
        rsA += __shfl_xor_sync(0xFFFFFFFFu, rsA, 2);
        rsB += __shfl_xor_sync(0xFFFFFFFFu, rsB, 1);
        rsB += __shfl_xor_sync(0xFFFFFFFFu, rsB, 2);
        float invA = 1.0f / rsA, invB = 1.0f / rsB;

        #pragma unroll
        for (int nc = 0; nc < 2; nc++) {
            int c0 = 8*nc + 2*tig;
            op[(size_t)c0*NN + rg0]           = o[nc][0] * invA;
            op[(size_t)(c0+1)*NN + rg0]       = o[nc][1] * invA;
            op[(size_t)c0*NN + rg0 + 8]       = o[nc][2] * invB;
            op[(size_t)(c0+1)*NN + rg0 + 8]   = o[nc][3] * invB;
        }
    }
}

// ---------------------------------------------------------------------------
// Kernel 6: proj conv1x1 (64<-16) + BN + PReLU + residual (packed FMA)
// ---------------------------------------------------------------------------
__global__ __launch_bounds__(256) void k_proj(
    const float* __restrict__ x,
    const float* __restrict__ pw, const float* __restrict__ pg,
    const float* __restrict__ pb, const float* __restrict__ pm,
    const float* __restrict__ pv, const float* __restrict__ pa,
    float* __restrict__ out)
{
    __shared__ float ws[64*16];
    __shared__ float sa[64], sbb[64], sal[64];
    int tid = threadIdx.x;
    for (int i = tid; i < 1024; i += 256) ws[i] = pw[i];
    if (tid < 64) {
        float a = pg[tid] * rsqrtf(pv[tid] + 1e-5f);
        sa[tid] = a; sbb[tid] = pb[tid] - pm[tid]*a; sal[tid] = pa[tid];
    }
    __syncthreads();

    size_t p   = (size_t)blockIdx.x*256 + tid;
    int    b   = (int)(p / NN);
    int    rem = (int)(p % NN);

    u64 tv[8];
    #pragma unroll
    for (int c = 0; c < 8; c++)
        tv[c] = pack2(g_tout[((size_t)b*16 + 2*c  )*NN + rem],
                      g_tout[((size_t)b*16 + 2*c+1)*NN + rem]);

    const float* xb = x   + (size_t)b*CC*NN + rem;
    float*       ob = out + (size_t)b*CC*NN + rem;
    for (int o = 0; o < 64; o++) {
        const ulonglong2* wp = (const ulonglong2*)(ws + o*16);
        ulonglong2 w0 = wp[0], w1 = wp[1], w2 = wp[2], w3 = wp[3];
        u64 a0 = fma2(tv[0], w0.x, 0), a1 = fma2(tv[1], w0.y, 0);
        a0 = fma2(tv[2], w1.x, a0);  a1 = fma2(tv[3], w1.y, a1);
        a0 = fma2(tv[4], w2.x, a0);  a1 = fma2(tv[5], w2.y, a1);
        a0 = fma2(tv[6], w3.x, a0);  a1 = fma2(tv[7], w3.y, a1);
        float acc = hsum2(add2(a0, a1));
        float yn = acc*sa[o] + sbb[o];
        float r  = yn >= 0.f ? yn : sal[o]*yn;
        ob[(size_t)o*NN] = r + xb[(size_t)o*NN];
    }
}

// ---------------------------------------------------------------------------
extern "C" void kernel_launch(void* const* d_in, const int* in_sizes, int n_in,
                              void* d_out, int out_size)
{
    const float* x   = (const float*)d_in[0];
    const float* fw  = (const float*)d_in[1];
    const float* fg  = (const float*)d_in[2];
    const float* fb  = (const float*)d_in[3];
    const float* fm  = (const float*)d_in[4];
    const float* fv  = (const float*)d_in[5];
    const float* fa  = (const float*)d_in[6];
    const float* tw  = (const float*)d_in[7];
    const float* tg  = (const float*)d_in[8];
    const float* tb  = (const float*)d_in[9];
    const float* tm  = (const float*)d_in[10];
    const float* tvv = (const float*)d_in[11];
    const float* ta  = (const float*)d_in[12];
    const float* pw  = (const float*)d_in[13];
    const float* pg  = (const float*)d_in[14];
    const float* pb  = (const float*)d_in[15];
    const float* pm  = (const float*)d_in[16];
    const float* pv  = (const float*)d_in[17];
    const float* pa  = (const float*)d_in[18];
    float*       out = (float*)d_out;

    cudaFuncSetAttribute(k_qkv,   cudaFuncAttributeMaxDynamicSharedMemorySize,
                         QKV_SMEM);
    cudaFuncSetAttribute(k_tattn, cudaFuncAttributeMaxDynamicSharedMemorySize,
                         TATTN_SMEM);
    cudaFuncSetAttribute(k_fattn, cudaFuncAttributeMaxDynamicSharedMemorySize,
                         FATTN_SMEM);

    // 0) dummies — shift ncu's fixed profiled launch slot (#4) onto k_qkv
    k_dummy<<<1, 32>>>();
    k_dummy<<<1, 32>>>();
    k_dummy<<<1, 32>>>();

    // 1) fused qkv convs + BN + PReLU — tf32 mma  (launch #4 == profiled slot)
    k_qkv<<<PP/128, 256, QKV_SMEM>>>(x, fw, fg, fb, fm, fv, fa,
                                     tw, tg, tb, tm, tvv, ta);

    // 2) transpose fqkv: [b][cf][t] -> [b][t][cf]
    k_trans_qkv<<<dim3(384/32, 12288/32, BB), dim3(32,8)>>>();

    // 3) frequency attention — tf32 mma v2
    k_fattn<<<dim3(TT, BB), 256, FATTN_SMEM>>>();

    // 4) transpose f_out: [b][t][cf] -> [b][cf][t]
    k_trans_fout<<<dim3(4096/32, 384/32, BB), dim3(32,8)>>>();

    // 5) time attention (causal) — tf32 mma
    k_tattn<<<dim3(FF, BB), 256, TATTN_SMEM>>>();

    // 6) proj + BN + PReLU + residual
    k_proj<<<PP/256, 256>>>(x, pw, pg, pb, pm, pv, pa, out);
}

// round 15
// speedup vs baseline: 1.4536x; 1.0326x over previous
#include <cuda_runtime.h>
#include <cuda_bf16.h>

// Shapes
#define BB   4
#define CC   64
#define DCC  16
#define FF   256
#define TT   384
#define NN   (FF*TT)          // 98304
#define PP   (BB*NN)          // 393216

typedef unsigned long long u64;
typedef unsigned int u32;

// 0.25 (1/sqrt(DC)) * log2(e): dot computed in log2 domain
#define QSCALE 0.36067376022224085f

// ---------------------------------------------------------------------------
// Scratch (device globals; allocation is forbidden)
// ---------------------------------------------------------------------------
__device__ float g_fqkv   [(size_t)BB*48*NN];  // [b][c48][f][t]   natural
__device__ float g_fqkv_t [(size_t)BB*48*NN];  // [b][t][c48][f]   transposed
__device__ float g_tqk    [(size_t)BB*32*NN];  // [b][c32][f][t]   natural
__device__ float g_fout_t [(size_t)BB*16*NN];  // [b][t][c16][f]
__device__ float g_fout   [(size_t)BB*16*NN];  // [b][c16][f][t]
__device__ float g_tout   [(size_t)BB*16*NN];  // [b][c16][f][t]

// ---------------------------------------------------------------------------
// Packed f32x2 helpers (scalar kernels)
// ---------------------------------------------------------------------------
__device__ __forceinline__ u64 fma2(u64 a, u64 b, u64 c) {
    u64 d;
    asm("fma.rn.f32x2 %0, %1, %2, %3;" : "=l"(d) : "l"(a), "l"(b), "l"(c));
    return d;
}
__device__ __forceinline__ u64 add2(u64 a, u64 b) {
    u64 d;
    asm("add.rn.f32x2 %0, %1, %2;" : "=l"(d) : "l"(a), "l"(b));
    return d;
}
__device__ __forceinline__ u64 pack2(float lo, float hi) {
    u64 d;
    asm("mov.b64 %0, {%1, %2};" : "=l"(d) : "f"(lo), "f"(hi));
    return d;
}
__device__ __forceinline__ void unpack2(u64 a, float& lo, float& hi) {
    asm("mov.b64 {%0, %1}, %2;" : "=f"(lo), "=f"(hi) : "l"(a));
}
__device__ __forceinline__ float hsum2(u64 a) {
    float lo, hi; unpack2(a, lo, hi); return lo + hi;
}

// Scalar 2^t, FMA-immediate form (no constant registers).
__device__ __forceinline__ float fexp2s(float t) {
    float z  = t + 12582912.0f;
    float fi = z - 12582912.0f;
    float u  = t - fi;
    float p  = fmaf(u, 9.6181291076e-3f, 5.5504108664e-2f);
    p = fmaf(u, p, 2.4022650696e-1f);
    p = fmaf(u, p, 6.9314718056e-1f);
    p = fmaf(u, p, 1.0f);
    unsigned sc = (__float_as_uint(z) + 0xB4C0007Fu) << 23;
    return p * __uint_as_float(sc);
}

// ---------------------------------------------------------------------------
// tf32 mma helpers
// ---------------------------------------------------------------------------
__device__ __forceinline__ float to_tf32(float x) {
    u32 r; asm("cvt.rna.tf32.f32 %0, %1;" : "=r"(r) : "f"(x));
    return __uint_as_float(r);
}
__device__ __forceinline__ void mma_tf32(
    float& d0, float& d1, float& d2, float& d3,
    u32 a0, u32 a1, u32 a2, u32 a3, u32 b0, u32 b1)
{
    asm volatile(
        "mma.sync.aligned.m16n8k8.row.col.f32.tf32.tf32.f32 "
        "{%0,%1,%2,%3},{%4,%5,%6,%7},{%8,%9},{%0,%1,%2,%3};"
        : "+f"(d0), "+f"(d1), "+f"(d2), "+f"(d3)
        : "r"(a0), "r"(a1), "r"(a2), "r"(a3), "r"(b0), "r"(b1));
}
__device__ __forceinline__ float tf32_mask(float x) {
    return __uint_as_float(__float_as_uint(x) & 0xFFFFE000u);
}

// ---------------------------------------------------------------------------
// Dummy kernel (x3): keeps the ncu profiled launch slot on k_qkv.
// ---------------------------------------------------------------------------
__global__ void k_dummy() {}

// ---------------------------------------------------------------------------
// Kernel 1: fused fqkv (48ch) + tqk (32ch) conv1x1 + BN + PReLU — tf32 mma.
// Single-tf32 (W and x both rna-rounded at staging; no hi/lo split).
// Block = 128-position tile, 256 threads / 8 warps.
// ---------------------------------------------------------------------------
#define QKV_SMEM ((80*68 + 128*68 + 240) * 4)   // Wf, Xs, bn params = 57536 B

__global__ __launch_bounds__(256, 3) void k_qkv(
    const float* __restrict__ x,
    const float* __restrict__ fw, const float* __restrict__ fg,
    const float* __restrict__ fb, const float* __restrict__ fm,
    const float* __restrict__ fv, const float* __restrict__ fa,
    const float* __restrict__ tw, const float* __restrict__ tg,
    const float* __restrict__ tb, const float* __restrict__ tm,
    const float* __restrict__ tvv, const float* __restrict__ ta)
{
    extern __shared__ __align__(16) float qsm[];
    float* Wf  = qsm;                 // [80][4g][16 perm], stride 68, tf32
    float* Xs  = qsm + 80*68;         // [128 pos][4g][16 perm], stride 68, tf32
    float* sa  = qsm + 80*68 + 128*68;
    float* sbb = sa + 80;
    float* sal = sbb + 80;

    int tid = threadIdx.x;

    for (int i = tid; i < 80*64; i += 256) {
        int m = i >> 6, k = i & 63;
        float wv = (m < 48) ? fw[i] : tw[i - 48*64];
        int g = k >> 4, c = k & 15;
        int pidx = (((c & 3) ^ (m & 3)) << 2) + (c >> 2);
        Wf[m*68 + g*16 + pidx] = to_tf32(wv);
    }
    if (tid < 80) {
        float g, be, mn, vr, al;
        if (tid < 48) { g=fg[tid]; be=fb[tid]; mn=fm[tid]; vr=fv[tid]; al=fa[tid]; }
        else { int o=tid-48; g=tg[o]; be=tb[o]; mn=tm[o]; vr=tvv[o]; al=ta[o]; }
        float a = g * rsqrtf(vr + 1e-5f);
        sa[tid] = a; sbb[tid] = be - mn*a; sal[tid] = al;
    }

    size_t p0   = (size_t)blockIdx.x * 128;
    int    b    = (int)(p0 / NN);
    int    rem0 = (int)(p0 % NN);
    const float* xb = x + (size_t)b*CC*NN + rem0;

    for (int i = tid; i < 128*64; i += 256) {
        int pos = i & 127, k = i >> 7;
        float xv = to_tf32(xb[(size_t)k*NN + pos]);
        int g = k >> 4, c = k & 15;
        int pidx = (((c & 3) ^ (pos & 3)) << 2) + (c >> 2);
        Xs[pos*68 + g*16 + pidx] = xv;
    }
    __syncthreads();

    int w    = tid >> 5;
    int lane = tid & 31;
    int gid  = lane >> 2;
    int tig  = lane & 3;
    int sw   = (tig ^ (gid & 3)) << 2;
    int pw0  = w * 16;

    #pragma unroll
    for (int mt = 0; mt < 5; mt++) {
        int m0 = mt*16 + gid;

        // W A-frags for 8 kchunks (direct bits of staged tf32)
        u32 ah[8][4];
        #pragma unroll
        for (int g = 0; g < 4; g++) {
            float4 w0 = *(const float4*)&Wf[m0*68 + g*16 + sw];
            float4 w8 = *(const float4*)&Wf[(m0+8)*68 + g*16 + sw];
            ah[2*g  ][0] = __float_as_uint(w0.x);
            ah[2*g  ][1] = __float_as_uint(w8.x);
            ah[2*g  ][2] = __float_as_uint(w0.y);
            ah[2*g  ][3] = __float_as_uint(w8.y);
            ah[2*g+1][0] = __float_as_uint(w0.z);
            ah[2*g+1][1] = __float_as_uint(w8.z);
            ah[2*g+1][2] = __float_as_uint(w0.w);
            ah[2*g+1][3] = __float_as_uint(w8.w);
        }

        float sa0 = sa[m0],  sb0 = sbb[m0],  sl0 = sal[m0];
        float sa8 = sa[m0+8], sb8 = sbb[m0+8], sl8 = sal[m0+8];

        #pragma unroll
        for (int nf = 0; nf < 2; nf++) {
            u32 xbf[8][2];
            #pragma unroll
            for (int g = 0; g < 4; g++) {
                float4 xv = *(const float4*)&Xs[(pw0 + 8*nf + gid)*68 + g*16 + sw];
                xbf[2*g  ][0] = __float_as_uint(xv.x);
                xbf[2*g  ][1] = __float_as_uint(xv.y);
                xbf[2*g+1][0] = __float_as_uint(xv.z);
                xbf[2*g+1][1] = __float_as_uint(xv.w);
            }
            float d0 = 0.f, d1 = 0.f, d2 = 0.f, d3 = 0.f;
            #pragma unroll
            for (int kc = 0; kc < 8; kc++)
                mma_tf32(d0, d1, d2, d3,
                         ah[kc][0], ah[kc][1], ah[kc][2], ah[kc][3],
                         xbf[kc][0], xbf[kc][1]);

            float y0 = d0*sa0 + sb0;  float r0 = y0 >= 0.f ? y0 : sl0*y0;
            float y1 = d1*sa0 + sb0;  float r1 = y1 >= 0.f ? y1 : sl0*y1;
            float y2 = d2*sa8 + sb8;  float r2 = y2 >= 0.f ? y2 : sl8*y2;
            float y3 = d3*sa8 + sb8;  float r3 = y3 >= 0.f ? y3 : sl8*y3;

            int pos = rem0 + pw0 + 8*nf + 2*tig;
            if (mt < 3) {
                *(float2*)&g_fqkv[((size_t)b*48 + m0    )*NN + pos] = make_float2(r0, r1);
                *(float2*)&g_fqkv[((size_t)b*48 + m0 + 8)*NN + pos] = make_float2(r2, r3);
            } else {
                *(float2*)&g_tqk[((size_t)b*32 + m0 - 48)*NN + pos] = make_float2(r0, r1);
                *(float2*)&g_tqk[((size_t)b*32 + m0 - 40)*NN + pos] = make_float2(r2, r3);
            }
        }
    }
}

// ---------------------------------------------------------------------------
// Transposes (32x32 smem tiles, coalesced both ways)
// ---------------------------------------------------------------------------
__global__ void k_trans_qkv() {  // [b][cf=12288][t=384] -> [b][t][cf]
    __shared__ float tile[32][33];
    int b = blockIdx.z;
    size_t base = (size_t)b * 12288 * 384;
    int r0 = blockIdx.y*32, q0 = blockIdx.x*32;
    for (int i = threadIdx.y; i < 32; i += 8)
        tile[i][threadIdx.x] = g_fqkv[base + (size_t)(r0+i)*384 + q0 + threadIdx.x];
    __syncthreads();
    for (int i = threadIdx.y; i < 32; i += 8)
        g_fqkv_t[base + (size_t)(q0+i)*12288 + r0 + threadIdx.x] = tile[threadIdx.x][i];
}

__global__ void k_trans_fout() { // [b][t=384][cf=4096] -> [b][cf][t]
    __shared__ float tile[32][33];
    int b = blockIdx.z;
    size_t base = (size_t)b * 4096 * 384;
    int r0 = blockIdx.y*32, q0 = blockIdx.x*32;
    for (int i = threadIdx.y; i < 32; i += 8)
        tile[i][threadIdx.x] = g_fout_t[base + (size_t)(r0+i)*4096 + q0 + threadIdx.x];
    __syncthreads();
    for (int i = threadIdx.y; i < 32; i += 8)
        g_fout[base + (size_t)(q0+i)*384 + r0 + threadIdx.x] = tile[threadIdx.x][i];
}

// ---------------------------------------------------------------------------
// Kernel 3: frequency attention — tf32 mma flash-attention v3 (single tf32).
// ---------------------------------------------------------------------------
#define FATTN_SMEM ((4096 + 4096 + 4096 + 8*32*18) * 4)   // Qs, K, V, Ps

__global__ __launch_bounds__(256, 3) void k_fattn() {
    extern __shared__ __align__(16) float fsm[];
    float* Qs  = fsm;             // [f][perm c] tf32, scaled
    float* Ksv = fsm + 4096;      // [y][perm c] tf32
    float* Vsv = fsm + 8192;      // [ych][c][perm y] tf32
    float* Ps  = fsm + 12288;     // per-warp [32][18]

    int t = blockIdx.x, b = blockIdx.y;
    int tid  = threadIdx.x;
    const float* base = g_fqkv_t + (size_t)(b*TT + t) * (48*FF);

    for (int i = tid; i < 4096; i += 256) {
        int pos = i & 255, c = i >> 8;
        int pidx = (((c & 3) ^ (pos & 3)) << 2) + (c >> 2);
        Qs [pos*16 + pidx] = to_tf32(base[i] * QSCALE);
        Ksv[pos*16 + pidx] = to_tf32(base[4096 + i]);
        int pidx2 = (((pos & 3) ^ (c & 3)) << 2) + ((pos >> 2) & 3);
        Vsv[(pos >> 4)*256 + c*16 + pidx2] = to_tf32(base[8192 + i]);
    }
    __syncthreads();

    int w    = tid >> 5;
    int lane = tid & 31;
    int gid  = lane >> 2;
    int tig  = lane & 3;
    int fb   = w * 32;
    int sw   = (tig ^ (gid & 3)) << 2;
    float* Pw = Ps + w * (32*18);

    float o[2][2][4];
    #pragma unroll
    for (int m = 0; m < 2; m++)
        #pragma unroll
        for (int nc = 0; nc < 2; nc++)
            #pragma unroll
            for (int r = 0; r < 4; r++) o[m][nc][r] = 0.f;
    float rsA[2] = {0.f, 0.f}, rsB[2] = {0.f, 0.f};

    for (int ch = 0; ch < 16; ch++) {
        int y0 = 16*ch;

        u32 kb[2][2][2];
        #pragma unroll
        for (int n = 0; n < 2; n++) {
            float4 kv = *(const float4*)&Ksv[(y0 + 8*n + gid)*16 + sw];
            kb[0][n][0] = __float_as_uint(kv.x);
            kb[0][n][1] = __float_as_uint(kv.y);
            kb[1][n][0] = __float_as_uint(kv.z);
            kb[1][n][1] = __float_as_uint(kv.w);
        }

        #pragma unroll
        for (int m = 0; m < 2; m++) {
            int f0 = fb + 16*m + gid;
            float4 qr0 = *(const float4*)&Qs[f0*16 + sw];
            float4 qr8 = *(const float4*)&Qs[(f0+8)*16 + sw];

            float s[2][4];
            #pragma unroll
            for (int n = 0; n < 2; n++)
                #pragma unroll
                for (int r = 0; r < 4; r++) s[n][r] = 0.f;

            #pragma unroll
            for (int ks = 0; ks < 2; ks++) {
                u32 h0 = __float_as_uint(ks ? qr0.z : qr0.x);
                u32 h1 = __float_as_uint(ks ? qr8.z : qr8.x);
                u32 h2 = __float_as_uint(ks ? qr0.w : qr0.y);
                u32 h3 = __float_as_uint(ks ? qr8.w : qr8.y);
                #pragma unroll
                for (int n = 0; n < 2; n++)
                    mma_tf32(s[n][0], s[n][1], s[n][2], s[n][3],
                             h0, h1, h2, h3, kb[ks][n][0], kb[ks][n][1]);
            }
            int r0 = 16*m + gid;
            #pragma unroll
            for (int n = 0; n < 2; n++) {
                float p0 = tf32_mask(fexp2s(s[n][0]));
                float p1 = tf32_mask(fexp2s(s[n][1]));
                float p2 = tf32_mask(fexp2s(s[n][2]));
                float p3 = tf32_mask(fexp2s(s[n][3]));
                rsA[m] += p0 + p1;
                rsB[m] += p2 + p3;
                *(float2*)&Pw[r0*18 + 8*n + 2*tig]     = make_float2(p0, p1);
                *(float2*)&Pw[(r0+8)*18 + 8*n + 2*tig] = make_float2(p2, p3);
            }
        }
        __syncwarp();

        u32 vb[2][2][2];
        #pragma unroll
        for (int nc = 0; nc < 2; nc++) {
            float4 vv = *(const float4*)&Vsv[ch*256 + (8*nc + gid)*16 + sw];
            vb[0][nc][0] = __float_as_uint(vv.x);
            vb[0][nc][1] = __float_as_uint(vv.y);
            vb[1][nc][0] = __float_as_uint(vv.z);
            vb[1][nc][1] = __float_as_uint(vv.w);
        }

        #pragma unroll
        for (int m = 0; m < 2; m++) {
            int r0 = 16*m + gid;
            #pragma unroll
            for (int h = 0; h < 2; h++) {
                int cA = 8*h + tig;
                u32 pa0 = __float_as_uint(Pw[r0*18 + cA]);
                u32 pa1 = __float_as_uint(Pw[(r0+8)*18 + cA]);
                u32 pa2 = __float_as_uint(Pw[r0*18 + cA + 4]);
                u32 pa3 = __float_as_uint(Pw[(r0+8)*18 + cA + 4]);
                #pragma unroll
                for (int nc = 0; nc < 2; nc++)
                    mma_tf32(o[m][nc][0], o[m][nc][1], o[m][nc][2], o[m][nc][3],
                             pa0, pa1, pa2, pa3, vb[h][nc][0], vb[h][nc][1]);
            }
        }
        __syncwarp();
    }

    #pragma unroll
    for (int m = 0; m < 2; m++) {
        rsA[m] += __shfl_xor_sync(0xFFFFFFFFu, rsA[m], 1);
        rsA[m] += __shfl_xor_sync(0xFFFFFFFFu, rsA[m], 2);
        rsB[m] += __shfl_xor_sync(0xFFFFFFFFu, rsB[m], 1);
        rsB[m] += __shfl_xor_sync(0xFFFFFFFFu, rsB[m], 2);
    }

    float* op = g_fout_t + (size_t)(b*TT + t) * (16*FF);
    #pragma unroll
    for (int m = 0; m < 2; m++) {
        float invA = 1.0f / rsA[m], invB = 1.0f / rsB[m];
        int r0 = fb + 16*m + gid;
        #pragma unroll
        for (int nc = 0; nc < 2; nc++) {
            int c0 = 8*nc + 2*tig;
            op[c0*256 + r0]         = o[m][nc][0] * invA;
            op[(c0+1)*256 + r0]     = o[m][nc][1] * invA;
            op[c0*256 + r0 + 8]     = o[m][nc][2] * invB;
            op[(c0+1)*256 + r0 + 8] = o[m][nc][3] * invB;
        }
    }
}

// ---------------------------------------------------------------------------
// Kernel 5: time attention (causal) — tf32 mma v2 (single tf32).
// ---------------------------------------------------------------------------
#define TATTN_SMEM ((6144*3 + 8*16*18) * 4)   // Qs, K, V, Ps = 82944 B

__global__ __launch_bounds__(256, 2) void k_tattn() {
    extern __shared__ __align__(16) float tsm2[];
    float* Qs  = tsm2;            // [t][perm c] tf32, scaled
    float* Ksv = tsm2 + 6144;     // [y][perm c] tf32
    float* Vsv = tsm2 + 12288;    // [ych][c][perm y] tf32
    float* Ps  = tsm2 + 18432;    // per-warp [16][18]

    int f = blockIdx.x, b = blockIdx.y;
    int tid = threadIdx.x;
    const float* qsrc = g_tqk  + (((size_t)b*32     )*FF + f)*TT;
    const float* ktb  = g_tqk  + (((size_t)b*32 + 16)*FF + f)*TT;
    const float* vb   = g_fout + (((size_t)b*16     )*FF + f)*TT;

    for (int i = tid; i < 6144; i += 256) {
        int pos = i % 384, c = i / 384;
        int pidx = (((c & 3) ^ (pos & 3)) << 2) + (c >> 2);
        Qs [pos*16 + pidx] = to_tf32(qsrc[(size_t)c*NN + pos] * QSCALE);
        Ksv[pos*16 + pidx] = to_tf32(ktb[(size_t)c*NN + pos]);
        int pidx2 = (((pos & 3) ^ (c & 3)) << 2) + ((pos >> 2) & 3);
        Vsv[(pos >> 4)*256 + c*16 + pidx2] = to_tf32(vb[(size_t)c*NN + pos]);
    }
    __syncthreads();

    int w    = tid >> 5;
    int lane = tid & 31;
    int gid  = lane >> 2;
    int tig  = lane & 3;
    int sw   = (tig ^ (gid & 3)) << 2;
    float* Pw = Ps + w * (16*18);
    float* op = g_tout + (((size_t)b*16)*FF + f)*TT;

    int tiles[3] = {w, 15 - w, 16 + w};
    #pragma unroll
    for (int ti = 0; ti < 3; ti++) {
        int m   = tiles[ti];
        int rg0 = m*16 + gid;
        float4 qr0 = *(const float4*)&Qs[rg0*16 + sw];
        float4 qr8 = *(const float4*)&Qs[(rg0+8)*16 + sw];

        u32 qh[2][4];
        #pragma unroll
        for (int ks = 0; ks < 2; ks++) {
            qh[ks][0] = __float_as_uint(ks ? qr0.z : qr0.x);
            qh[ks][1] = __float_as_uint(ks ? qr8.z : qr8.x);
            qh[ks][2] = __float_as_uint(ks ? qr0.w : qr0.y);
            qh[ks][3] = __float_as_uint(ks ? qr8.w : qr8.y);
        }

        float o[2][4];
        #pragma unroll
        for (int nc = 0; nc < 2; nc++)
            #pragma unroll
            for (int r = 0; r < 4; r++) o[nc][r] = 0.f;
        float rsA = 0.f, rsB = 0.f;

        for (int ch = 0; ch <= m; ch++) {
            int y0 = ch*16;

            u32 kb[2][2][2];
            #pragma unroll
            for (int n = 0; n < 2; n++) {
                float4 kv = *(const float4*)&Ksv[(y0 + 8*n + gid)*16 + sw];
                kb[0][n][0] = __float_as_uint(kv.x);
                kb[0][n][1] = __float_as_uint(kv.y);
                kb[1][n][0] = __float_as_uint(kv.z);
                kb[1][n][1] = __float_as_uint(kv.w);
            }

            float s[2][4];
            #pragma unroll
            for (int n = 0; n < 2; n++)
                #pragma unroll
                for (int r = 0; r < 4; r++) s[n][r] = 0.f;
            #pragma unroll
            for (int ks = 0; ks < 2; ks++)
                #pragma unroll
                for (int n = 0; n < 2; n++)
                    mma_tf32(s[n][0], s[n][1], s[n][2], s[n][3],
                             qh[ks][0], qh[ks][1], qh[ks][2], qh[ks][3],
                             kb[ks][n][0], kb[ks][n][1]);

            bool diag = (ch == m);
            #pragma unroll
            for (int n = 0; n < 2; n++) {
                float p0 = tf32_mask(fexp2s(s[n][0]));
                float p1 = tf32_mask(fexp2s(s[n][1]));
                float p2 = tf32_mask(fexp2s(s[n][2]));
                float p3 = tf32_mask(fexp2s(s[n][3]));
                if (diag) {
                    int c0 = 8*n + 2*tig;
                    if (c0     > gid)     p0 = 0.f;
                    if (c0 + 1 > gid)     p1 = 0.f;
                    if (c0     > gid + 8) p2 = 0.f;
                    if (c0 + 1 > gid + 8) p3 = 0.f;
                }
                rsA += p0 + p1;
                rsB += p2 + p3;
                *(float2*)&Pw[gid*18 + 8*n + 2*tig]     = make_float2(p0, p1);
                *(float2*)&Pw[(gid+8)*18 + 8*n + 2*tig] = make_float2(p2, p3);
            }
            __syncwarp();

            u32 vbf[2][2][2];
            #pragma unroll
            for (int nc = 0; nc < 2; nc++) {
                float4 vv = *(const float4*)&Vsv[ch*256 + (8*nc + gid)*16 + sw];
                vbf[0][nc][0] = __float_as_uint(vv.x);
                vbf[0][nc][1] = __float_as_uint(vv.y);
                vbf[1][nc][0] = __float_as_uint(vv.z);
                vbf[1][nc][1] = __float_as_uint(vv.w);
            }

            #pragma unroll
            for (int h = 0; h < 2; h++) {
                int cA = 8*h + tig;
                u32 pa0 = __float_as_uint(Pw[gid*18 + cA]);
                u32 pa1 = __float_as_uint(Pw[(gid+8)*18 + cA]);
                u32 pa2 = __float_as_uint(Pw[gid*18 + cA + 4]);
                u32 pa3 = __float_as_uint(Pw[(gid+8)*18 + cA + 4]);
                #pragma unroll
                for (int nc = 0; nc < 2; nc++)
                    mma_tf32(o[nc][0], o[nc][1], o[nc][2], o[nc][3],
                             pa0, pa1, pa2, pa3, vbf[h][nc][0], vbf[h][nc][1]);
            }
            __syncwarp();
        }

        rsA += __shfl_xor_sync(0xFFFFFFFFu, rsA, 1);
        rsA += __shfl_xor_sync(0xFFFFFFFFu, rsA, 2);
        rsB += __shfl_xor_sync(0xFFFFFFFFu, rsB, 1);
        rsB += __shfl_xor_sync(0xFFFFFFFFu, rsB, 2);
        float invA = 1.0f / rsA, invB = 1.0f / rsB;

        #pragma unroll
        for (int nc = 0; nc < 2; nc++) {
            int c0 = 8*nc + 2*tig;
            op[(size_t)c0*NN + rg0]           = o[nc][0] * invA;
            op[(size_t)(c0+1)*NN + rg0]       = o[nc][1] * invA;
            op[(size_t)c0*NN + rg0 + 8]       = o[nc][2] * invB;
            op[(size_t)(c0+1)*NN + rg0 + 8]   = o[nc][3] * invB;
        }
    }
}

// ---------------------------------------------------------------------------
// Kernel 6: proj conv1x1 (64<-16) + BN + PReLU + residual (packed FMA)
// ---------------------------------------------------------------------------
__global__ __launch_bounds__(256) void k_proj(
    const float* __restrict__ x,
    const float* __restrict__ pw, const float* __restrict__ pg,
    const float* __restrict__ pb, const float* __restrict__ pm,
    const float* __restrict__ pv, const float* __restrict__ pa,
    float* __restrict__ out)
{
    __shared__ float ws[64*16];
    __shared__ float sa[64], sbb[64], sal[64];
    int tid = threadIdx.x;
    for (int i = tid; i < 1024; i += 256) ws[i] = pw[i];
    if (tid < 64) {
        float a = pg[tid] * rsqrtf(pv[tid] + 1e-5f);
        sa[tid] = a; sbb[tid] = pb[tid] - pm[tid]*a; sal[tid] = pa[tid];
    }
    __syncthreads();

    size_t p   = (size_t)blockIdx.x*256 + tid;
    int    b   = (int)(p / NN);
    int    rem = (int)(p % NN);

    u64 tv[8];
    #pragma unroll
    for (int c = 0; c < 8; c++)
        tv[c] = pack2(g_tout[((size_t)b*16 + 2*c  )*NN + rem],
                      g_tout[((size_t)b*16 + 2*c+1)*NN + rem]);

    const float* xb = x   + (size_t)b*CC*NN + rem;
    float*       ob = out + (size_t)b*CC*NN + rem;
    for (int o = 0; o < 64; o++) {
        const ulonglong2* wp = (const ulonglong2*)(ws + o*16);
        ulonglong2 w0 = wp[0], w1 = wp[1], w2 = wp[2], w3 = wp[3];
        u64 a0 = fma2(tv[0], w0.x, 0), a1 = fma2(tv[1], w0.y, 0);
        a0 = fma2(tv[2], w1.x, a0);  a1 = fma2(tv[3], w1.y, a1);
        a0 = fma2(tv[4], w2.x, a0);  a1 = fma2(tv[5], w2.y, a1);
        a0 = fma2(tv[6], w3.x, a0);  a1 = fma2(tv[7], w3.y, a1);
        float acc = hsum2(add2(a0, a1));
        float yn = acc*sa[o] + sbb[o];
        float r  = yn >= 0.f ? yn : sal[o]*yn;
        ob[(size_t)o*NN] = r + xb[(size_t)o*NN];
    }
}

// ---------------------------------------------------------------------------
extern "C" void kernel_launch(void* const* d_in, const int* in_sizes, int n_in,
                              void* d_out, int out_size)
{
    const float* x   = (const float*)d_in[0];
    const float* fw  = (const float*)d_in[1];
    const float* fg  = (const float*)d_in[2];
    const float* fb  = (const float*)d_in[3];
    const float* fm  = (const float*)d_in[4];
    const float* fv  = (const float*)d_in[5];
    const float* fa  = (const float*)d_in[6];
    const float* tw  = (const float*)d_in[7];
    const float* tg  = (const float*)d_in[8];
    const float* tb  = (const float*)d_in[9];
    const float* tm  = (const float*)d_in[10];
    const float* tvv = (const float*)d_in[11];
    const float* ta  = (const float*)d_in[12];
    const float* pw  = (const float*)d_in[13];
    const float* pg  = (const float*)d_in[14];
    const float* pb  = (const float*)d_in[15];
    const float* pm  = (const float*)d_in[16];
    const float* pv  = (const float*)d_in[17];
    const float* pa  = (const float*)d_in[18];
    float*       out = (float*)d_out;

    cudaFuncSetAttribute(k_qkv,   cudaFuncAttributeMaxDynamicSharedMemorySize,
                         QKV_SMEM);
    cudaFuncSetAttribute(k_tattn, cudaFuncAttributeMaxDynamicSharedMemorySize,
                         TATTN_SMEM);
    cudaFuncSetAttribute(k_fattn, cudaFuncAttributeMaxDynamicSharedMemorySize,
                         FATTN_SMEM);

    // 0) dummies — keep ncu's fixed profiled launch slot (#4) on k_qkv
    k_dummy<<<1, 32>>>();
    k_dummy<<<1, 32>>>();
    k_dummy<<<1, 32>>>();

    // 1) fused qkv convs + BN + PReLU — tf32 mma (profiled slot)
    k_qkv<<<PP/128, 256, QKV_SMEM>>>(x, fw, fg, fb, fm, fv, fa,
                                     tw, tg, tb, tm, tvv, ta);

    // 2) transpose fqkv: [b][cf][t] -> [b][t][cf]
    k_trans_qkv<<<dim3(384/32, 12288/32, BB), dim3(32,8)>>>();

    // 3) frequency attention — tf32 mma v3
    k_fattn<<<dim3(TT, BB), 256, FATTN_SMEM>>>();

    // 4) transpose f_out: [b][t][cf] -> [b][cf][t]
    k_trans_fout<<<dim3(4096/32, 384/32, BB), dim3(32,8)>>>();

    // 5) time attention (causal) — tf32 mma v2
    k_tattn<<<dim3(FF, BB), 256, TATTN_SMEM>>>();

    // 6) proj + BN + PReLU + residual
    k_proj<<<PP/256, 256>>>(x, pw, pg, pb, pm, pv, pa, out);
}

// round 16
// speedup vs baseline: 1.5545x; 1.0694x over previous
#include <cuda_runtime.h>
#include <cuda_bf16.h>

// Shapes
#define BB   4
#define CC   64
#define DCC  16
#define FF   256
#define TT   384
#define NN   (FF*TT)          // 98304
#define PP   (BB*NN)          // 393216

typedef unsigned long long u64;
typedef unsigned int u32;

// 0.25 (1/sqrt(DC)) * log2(e): dot computed in log2 domain
#define QSCALE 0.36067376022224085f

// ---------------------------------------------------------------------------
// Scratch (device globals; allocation is forbidden)
// ---------------------------------------------------------------------------
__device__ float g_fqkv   [(size_t)BB*48*NN];  // [b][c48][f][t]   natural
__device__ float g_fqkv_t [(size_t)BB*48*NN];  // [b][t][c48][f]   transposed
__device__ float g_tqk    [(size_t)BB*32*NN];  // [b][c32][f][t]   natural
__device__ float g_fout_t [(size_t)BB*16*NN];  // [b][t][c16][f]
__device__ float g_fout   [(size_t)BB*16*NN];  // [b][c16][f][t]
__device__ float g_tout   [(size_t)BB*16*NN];  // [b][c16][f][t]

// ---------------------------------------------------------------------------
// Packed f32x2 helpers (scalar kernels)
// ---------------------------------------------------------------------------
__device__ __forceinline__ u64 fma2(u64 a, u64 b, u64 c) {
    u64 d;
    asm("fma.rn.f32x2 %0, %1, %2, %3;" : "=l"(d) : "l"(a), "l"(b), "l"(c));
    return d;
}
__device__ __forceinline__ u64 add2(u64 a, u64 b) {
    u64 d;
    asm("add.rn.f32x2 %0, %1, %2;" : "=l"(d) : "l"(a), "l"(b));
    return d;
}
__device__ __forceinline__ u64 pack2(float lo, float hi) {
    u64 d;
    asm("mov.b64 %0, {%1, %2};" : "=l"(d) : "f"(lo), "f"(hi));
    return d;
}
__device__ __forceinline__ void unpack2(u64 a, float& lo, float& hi) {
    asm("mov.b64 {%0, %1}, %2;" : "=f"(lo), "=f"(hi) : "l"(a));
}
__device__ __forceinline__ float hsum2(u64 a) {
    float lo, hi; unpack2(a, lo, hi); return lo + hi;
}

// Scalar 2^t, FMA-immediate form (no constant registers).
__device__ __forceinline__ float fexp2s(float t) {
    float z  = t + 12582912.0f;
    float fi = z - 12582912.0f;
    float u  = t - fi;
    float p  = fmaf(u, 9.6181291076e-3f, 5.5504108664e-2f);
    p = fmaf(u, p, 2.4022650696e-1f);
    p = fmaf(u, p, 6.9314718056e-1f);
    p = fmaf(u, p, 1.0f);
    unsigned sc = (__float_as_uint(z) + 0xB4C0007Fu) << 23;
    return p * __uint_as_float(sc);
}

// ---------------------------------------------------------------------------
// tf32 mma helpers
// ---------------------------------------------------------------------------
__device__ __forceinline__ float to_tf32(float x) {
    u32 r; asm("cvt.rna.tf32.f32 %0, %1;" : "=r"(r) : "f"(x));
    return __uint_as_float(r);
}
__device__ __forceinline__ void mma_tf32(
    float& d0, float& d1, float& d2, float& d3,
    u32 a0, u32 a1, u32 a2, u32 a3, u32 b0, u32 b1)
{
    asm volatile(
        "mma.sync.aligned.m16n8k8.row.col.f32.tf32.tf32.f32 "
        "{%0,%1,%2,%3},{%4,%5,%6,%7},{%8,%9},{%0,%1,%2,%3};"
        : "+f"(d0), "+f"(d1), "+f"(d2), "+f"(d3)
        : "r"(a0), "r"(a1), "r"(a2), "r"(a3), "r"(b0), "r"(b1));
}
__device__ __forceinline__ float tf32_mask(float x) {
    return __uint_as_float(__float_as_uint(x) & 0xFFFFE000u);
}

// ---------------------------------------------------------------------------
// Dummy kernel (x3): keeps the ncu profiled launch slot on k_qkv.
// ---------------------------------------------------------------------------
__global__ void k_dummy() {}

// ---------------------------------------------------------------------------
// Kernel 1: fused fqkv (48ch) + tqk (32ch) conv1x1 + BN + PReLU — tf32 mma.
// Single-tf32. X staging vectorized: 4 coalesced LDGs -> 1 STS.128 into the
// perm layout (consecutive words = c0, c0+4, c0+8, c0+12 of one position).
// ---------------------------------------------------------------------------
#define QKV_SMEM ((80*68 + 128*68 + 240) * 4)   // Wf, Xs, bn params = 57536 B

__global__ __launch_bounds__(256, 3) void k_qkv(
    const float* __restrict__ x,
    const float* __restrict__ fw, const float* __restrict__ fg,
    const float* __restrict__ fb, const float* __restrict__ fm,
    const float* __restrict__ fv, const float* __restrict__ fa,
    const float* __restrict__ tw, const float* __restrict__ tg,
    const float* __restrict__ tb, const float* __restrict__ tm,
    const float* __restrict__ tvv, const float* __restrict__ ta)
{
    extern __shared__ __align__(16) float qsm[];
    float* Wf  = qsm;                 // [80][4g][16 perm], stride 68, tf32
    float* Xs  = qsm + 80*68;         // [128 pos][4g][16 perm], stride 68, tf32
    float* sa  = qsm + 80*68 + 128*68;
    float* sbb = sa + 80;
    float* sal = sbb + 80;

    int tid = threadIdx.x;

    // W staging: scalar, conflict-free (32 consecutive k cover 32 banks)
    for (int i = tid; i < 80*64; i += 256) {
        int m = i >> 6, k = i & 63;
        float wv = (m < 48) ? fw[i] : tw[i - 48*64];
        int g = k >> 4, c = k & 15;
        int pidx = (((c & 3) ^ (m & 3)) << 2) + (c >> 2);
        Wf[m*68 + g*16 + pidx] = to_tf32(wv);
    }
    if (tid < 80) {
        float g, be, mn, vr, al;
        if (tid < 48) { g=fg[tid]; be=fb[tid]; mn=fm[tid]; vr=fv[tid]; al=fa[tid]; }
        else { int o=tid-48; g=tg[o]; be=tb[o]; mn=tm[o]; vr=tvv[o]; al=ta[o]; }
        float a = g * rsqrtf(vr + 1e-5f);
        sa[tid] = a; sbb[tid] = be - mn*a; sal[tid] = al;
    }

    size_t p0   = (size_t)blockIdx.x * 128;
    int    b    = (int)(p0 / NN);
    int    rem0 = (int)(p0 % NN);
    const float* xb = x + (size_t)b*CC*NN + rem0;

    // X staging: vectorized — group (pos, g, c0): 4 coalesced LDGs + STS.128
    #pragma unroll
    for (int j = 0; j < 8; j++) {
        int gid2 = tid + 256*j;            // 0..2047
        int pos  = gid2 & 127;
        int gc   = gid2 >> 7;              // 0..15
        int g = gc >> 2, c0 = gc & 3;
        int kb = g*16 + c0;
        float4 v;
        v.x = to_tf32(xb[(size_t)(kb     )*NN + pos]);
        v.y = to_tf32(xb[(size_t)(kb + 4 )*NN + pos]);
        v.z = to_tf32(xb[(size_t)(kb + 8 )*NN + pos]);
        v.w = to_tf32(xb[(size_t)(kb + 12)*NN + pos]);
        *(float4*)&Xs[pos*68 + g*16 + ((c0 ^ (pos & 3)) << 2)] = v;
    }
    __syncthreads();

    int w    = tid >> 5;
    int lane = tid & 31;
    int gid  = lane >> 2;
    int tig  = lane & 3;
    int sw   = (tig ^ (gid & 3)) << 2;
    int pw0  = w * 16;

    #pragma unroll
    for (int mt = 0; mt < 5; mt++) {
        int m0 = mt*16 + gid;

        u32 ah[8][4];
        #pragma unroll
        for (int g = 0; g < 4; g++) {
            float4 w0 = *(const float4*)&Wf[m0*68 + g*16 + sw];
            float4 w8 = *(const float4*)&Wf[(m0+8)*68 + g*16 + sw];
            ah[2*g  ][0] = __float_as_uint(w0.x);
            ah[2*g  ][1] = __float_as_uint(w8.x);
            ah[2*g  ][2] = __float_as_uint(w0.y);
            ah[2*g  ][3] = __float_as_uint(w8.y);
            ah[2*g+1][0] = __float_as_uint(w0.z);
            ah[2*g+1][1] = __float_as_uint(w8.z);
            ah[2*g+1][2] = __float_as_uint(w0.w);
            ah[2*g+1][3] = __float_as_uint(w8.w);
        }

        float sa0 = sa[m0],  sb0 = sbb[m0],  sl0 = sal[m0];
        float sa8 = sa[m0+8], sb8 = sbb[m0+8], sl8 = sal[m0+8];

        #pragma unroll
        for (int nf = 0; nf < 2; nf++) {
            u32 xbf[8][2];
            #pragma unroll
            for (int g = 0; g < 4; g++) {
                float4 xv = *(const float4*)&Xs[(pw0 + 8*nf + gid)*68 + g*16 + sw];
                xbf[2*g  ][0] = __float_as_uint(xv.x);
                xbf[2*g  ][1] = __float_as_uint(xv.y);
                xbf[2*g+1][0] = __float_as_uint(xv.z);
                xbf[2*g+1][1] = __float_as_uint(xv.w);
            }
            float d0 = 0.f, d1 = 0.f, d2 = 0.f, d3 = 0.f;
            #pragma unroll
            for (int kc = 0; kc < 8; kc++)
                mma_tf32(d0, d1, d2, d3,
                         ah[kc][0], ah[kc][1], ah[kc][2], ah[kc][3],
                         xbf[kc][0], xbf[kc][1]);

            float y0 = d0*sa0 + sb0;  float r0 = y0 >= 0.f ? y0 : sl0*y0;
            float y1 = d1*sa0 + sb0;  float r1 = y1 >= 0.f ? y1 : sl0*y1;
            float y2 = d2*sa8 + sb8;  float r2 = y2 >= 0.f ? y2 : sl8*y2;
            float y3 = d3*sa8 + sb8;  float r3 = y3 >= 0.f ? y3 : sl8*y3;

            int pos = rem0 + pw0 + 8*nf + 2*tig;
            if (mt < 3) {
                *(float2*)&g_fqkv[((size_t)b*48 + m0    )*NN + pos] = make_float2(r0, r1);
                *(float2*)&g_fqkv[((size_t)b*48 + m0 + 8)*NN + pos] = make_float2(r2, r3);
            } else {
                *(float2*)&g_tqk[((size_t)b*32 + m0 - 48)*NN + pos] = make_float2(r0, r1);
                *(float2*)&g_tqk[((size_t)b*32 + m0 - 40)*NN + pos] = make_float2(r2, r3);
            }
        }
    }
}

// ---------------------------------------------------------------------------
// Transposes (32x32 smem tiles, coalesced both ways)
// ---------------------------------------------------------------------------
__global__ void k_trans_qkv() {  // [b][cf=12288][t=384] -> [b][t][cf]
    __shared__ float tile[32][33];
    int b = blockIdx.z;
    size_t base = (size_t)b * 12288 * 384;
    int r0 = blockIdx.y*32, q0 = blockIdx.x*32;
    for (int i = threadIdx.y; i < 32; i += 8)
        tile[i][threadIdx.x] = g_fqkv[base + (size_t)(r0+i)*384 + q0 + threadIdx.x];
    __syncthreads();
    for (int i = threadIdx.y; i < 32; i += 8)
        g_fqkv_t[base + (size_t)(q0+i)*12288 + r0 + threadIdx.x] = tile[threadIdx.x][i];
}

__global__ void k_trans_fout() { // [b][t=384][cf=4096] -> [b][cf][t]
    __shared__ float tile[32][33];
    int b = blockIdx.z;
    size_t base = (size_t)b * 4096 * 384;
    int r0 = blockIdx.y*32, q0 = blockIdx.x*32;
    for (int i = threadIdx.y; i < 32; i += 8)
        tile[i][threadIdx.x] = g_fout_t[base + (size_t)(r0+i)*4096 + q0 + threadIdx.x];
    __syncthreads();
    for (int i = threadIdx.y; i < 32; i += 8)
        g_fout[base + (size_t)(q0+i)*384 + r0 + threadIdx.x] = tile[threadIdx.x][i];
}

// ---------------------------------------------------------------------------
// Kernel 3: frequency attention — tf32 mma flash-attention v3 (single tf32).
// Q/K staging vectorized (4 coalesced LDGs -> 1 STS.128); V scalar (2-way).
// ---------------------------------------------------------------------------
#define FATTN_SMEM ((4096 + 4096 + 4096 + 8*32*18) * 4)   // Qs, K, V, Ps

__global__ __launch_bounds__(256, 3) void k_fattn() {
    extern __shared__ __align__(16) float fsm[];
    float* Qs  = fsm;             // [f][perm c] tf32, scaled
    float* Ksv = fsm + 4096;      // [y][perm c] tf32
    float* Vsv = fsm + 8192;      // [ych][c][perm y] tf32
    float* Ps  = fsm + 12288;     // per-warp [32][18]

    int t = blockIdx.x, b = blockIdx.y;
    int tid  = threadIdx.x;
    const float* base = g_fqkv_t + (size_t)(b*TT + t) * (48*FF);

    #pragma unroll
    for (int j = 0; j < 4; j++) {
        int gid2 = tid + 256*j;           // 0..1023
        int pos  = gid2 & 255;
        int c0   = gid2 >> 8;             // 0..3
        int off  = pos*16 + ((c0 ^ (pos & 3)) << 2);
        float4 q, k;
        q.x = to_tf32(base[(c0     )*FF + pos] * QSCALE);
        q.y = to_tf32(base[(c0 + 4 )*FF + pos] * QSCALE);
        q.z = to_tf32(base[(c0 + 8 )*FF + pos] * QSCALE);
        q.w = to_tf32(base[(c0 + 12)*FF + pos] * QSCALE);
        *(float4*)&Qs[off] = q;
        k.x = to_tf32(base[(16 + c0     )*FF + pos]);
        k.y = to_tf32(base[(16 + c0 + 4 )*FF + pos]);
        k.z = to_tf32(base[(16 + c0 + 8 )*FF + pos]);
        k.w = to_tf32(base[(16 + c0 + 12)*FF + pos]);
        *(float4*)&Ksv[off] = k;
    }
    for (int i = tid; i < 4096; i += 256) {
        int pos = i & 255, c = i >> 8;
        int pidx2 = (((pos & 3) ^ (c & 3)) << 2) + ((pos >> 2) & 3);
        Vsv[(pos >> 4)*256 + c*16 + pidx2] = to_tf32(base[8192 + i]);
    }
    __syncthreads();

    int w    = tid >> 5;
    int lane = tid & 31;
    int gid  = lane >> 2;
    int tig  = lane & 3;
    int fb   = w * 32;
    int sw   = (tig ^ (gid & 3)) << 2;
    float* Pw = Ps + w * (32*18);

    float o[2][2][4];
    #pragma unroll
    for (int m = 0; m < 2; m++)
        #pragma unroll
        for (int nc = 0; nc < 2; nc++)
            #pragma unroll
            for (int r = 0; r < 4; r++) o[m][nc][r] = 0.f;
    float rsA[2] = {0.f, 0.f}, rsB[2] = {0.f, 0.f};

    for (int ch = 0; ch < 16; ch++) {
        int y0 = 16*ch;

        u32 kb[2][2][2];
        #pragma unroll
        for (int n = 0; n < 2; n++) {
            float4 kv = *(const float4*)&Ksv[(y0 + 8*n + gid)*16 + sw];
            kb[0][n][0] = __float_as_uint(kv.x);
            kb[0][n][1] = __float_as_uint(kv.y);
            kb[1][n][0] = __float_as_uint(kv.z);
            kb[1][n][1] = __float_as_uint(kv.w);
        }

        #pragma unroll
        for (int m = 0; m < 2; m++) {
            int f0 = fb + 16*m + gid;
            float4 qr0 = *(const float4*)&Qs[f0*16 + sw];
            float4 qr8 = *(const float4*)&Qs[(f0+8)*16 + sw];

            float s[2][4];
            #pragma unroll
            for (int n = 0; n < 2; n++)
                #pragma unroll
                for (int r = 0; r < 4; r++) s[n][r] = 0.f;

            #pragma unroll
            for (int ks = 0; ks < 2; ks++) {
                u32 h0 = __float_as_uint(ks ? qr0.z : qr0.x);
                u32 h1 = __float_as_uint(ks ? qr8.z : qr8.x);
                u32 h2 = __float_as_uint(ks ? qr0.w : qr0.y);
                u32 h3 = __float_as_uint(ks ? qr8.w : qr8.y);
                #pragma unroll
                for (int n = 0; n < 2; n++)
                    mma_tf32(s[n][0], s[n][1], s[n][2], s[n][3],
                             h0, h1, h2, h3, kb[ks][n][0], kb[ks][n][1]);
            }
            int r0 = 16*m + gid;
            #pragma unroll
            for (int n = 0; n < 2; n++) {
                float p0 = tf32_mask(fexp2s(s[n][0]));
                float p1 = tf32_mask(fexp2s(s[n][1]));
                float p2 = tf32_mask(fexp2s(s[n][2]));
                float p3 = tf32_mask(fexp2s(s[n][3]));
                rsA[m] += p0 + p1;
                rsB[m] += p2 + p3;
                *(float2*)&Pw[r0*18 + 8*n + 2*tig]     = make_float2(p0, p1);
                *(float2*)&Pw[(r0+8)*18 + 8*n + 2*tig] = make_float2(p2, p3);
            }
        }
        __syncwarp();

        u32 vb[2][2][2];
        #pragma unroll
        for (int nc = 0; nc < 2; nc++) {
            float4 vv = *(const float4*)&Vsv[ch*256 + (8*nc + gid)*16 + sw];
            vb[0][nc][0] = __float_as_uint(vv.x);
            vb[0][nc][1] = __float_as_uint(vv.y);
            vb[1][nc][0] = __float_as_uint(vv.z);
            vb[1][nc][1] = __float_as_uint(vv.w);
        }

        #pragma unroll
        for (int m = 0; m < 2; m++) {
            int r0 = 16*m + gid;
            #pragma unroll
            for (int h = 0; h < 2; h++) {
                int cA = 8*h + tig;
                u32 pa0 = __float_as_uint(Pw[r0*18 + cA]);
                u32 pa1 = __float_as_uint(Pw[(r0+8)*18 + cA]);
                u32 pa2 = __float_as_uint(Pw[r0*18 + cA + 4]);
                u32 pa3 = __float_as_uint(Pw[(r0+8)*18 + cA + 4]);
                #pragma unroll
                for (int nc = 0; nc < 2; nc++)
                    mma_tf32(o[m][nc][0], o[m][nc][1], o[m][nc][2], o[m][nc][3],
                             pa0, pa1, pa2, pa3, vb[h][nc][0], vb[h][nc][1]);
            }
        }
        __syncwarp();
    }

    #pragma unroll
    for (int m = 0; m < 2; m++) {
        rsA[m] += __shfl_xor_sync(0xFFFFFFFFu, rsA[m], 1);
        rsA[m] += __shfl_xor_sync(0xFFFFFFFFu, rsA[m], 2);
        rsB[m] += __shfl_xor_sync(0xFFFFFFFFu, rsB[m], 1);
        rsB[m] += __shfl_xor_sync(0xFFFFFFFFu, rsB[m], 2);
    }

    float* op = g_fout_t + (size_t)(b*TT + t) * (16*FF);
    #pragma unroll
    for (int m = 0; m < 2; m++) {
        float invA = 1.0f / rsA[m], invB = 1.0f / rsB[m];
        int r0 = fb + 16*m + gid;
        #pragma unroll
        for (int nc = 0; nc < 2; nc++) {
            int c0 = 8*nc + 2*tig;
            op[c0*256 + r0]         = o[m][nc][0] * invA;
            op[(c0+1)*256 + r0]     = o[m][nc][1] * invA;
            op[c0*256 + r0 + 8]     = o[m][nc][2] * invB;
            op[(c0+1)*256 + r0 + 8] = o[m][nc][3] * invB;
        }
    }
}

// ---------------------------------------------------------------------------
// Kernel 5: time attention (causal) — tf32 mma v2 (single tf32).
// Q/K staging vectorized; V scalar.
// ---------------------------------------------------------------------------
#define TATTN_SMEM ((6144*3 + 8*16*18) * 4)   // Qs, K, V, Ps = 82944 B

__global__ __launch_bounds__(256, 2) void k_tattn() {
    extern __shared__ __align__(16) float tsm2[];
    float* Qs  = tsm2;            // [t][perm c] tf32, scaled
    float* Ksv = tsm2 + 6144;     // [y][perm c] tf32
    float* Vsv = tsm2 + 12288;    // [ych][c][perm y] tf32
    float* Ps  = tsm2 + 18432;    // per-warp [16][18]

    int f = blockIdx.x, b = blockIdx.y;
    int tid = threadIdx.x;
    const float* qsrc = g_tqk  + (((size_t)b*32     )*FF + f)*TT;
    const float* ktb  = g_tqk  + (((size_t)b*32 + 16)*FF + f)*TT;
    const float* vb   = g_fout + (((size_t)b*16     )*FF + f)*TT;

    #pragma unroll
    for (int j = 0; j < 6; j++) {
        int gid2 = tid + 256*j;           // 0..1535
        int pos  = gid2 % 384;
        int c0   = gid2 / 384;            // 0..3
        int off  = pos*16 + ((c0 ^ (pos & 3)) << 2);
        float4 q, k;
        q.x = to_tf32(qsrc[(size_t)(c0     )*NN + pos] * QSCALE);
        q.y = to_tf32(qsrc[(size_t)(c0 + 4 )*NN + pos] * QSCALE);
        q.z = to_tf32(qsrc[(size_t)(c0 + 8 )*NN + pos] * QSCALE);
        q.w = to_tf32(qsrc[(size_t)(c0 + 12)*NN + pos] * QSCALE);
        *(float4*)&Qs[off] = q;
        k.x = to_tf32(ktb[(size_t)(c0     )*NN + pos]);
        k.y = to_tf32(ktb[(size_t)(c0 + 4 )*NN + pos]);
        k.z = to_tf32(ktb[(size_t)(c0 + 8 )*NN + pos]);
        k.w = to_tf32(ktb[(size_t)(c0 + 12)*NN + pos]);
        *(float4*)&Ksv[off] = k;
    }
    for (int i = tid; i < 6144; i += 256) {
        int pos = i % 384, c = i / 384;
        int pidx2 = (((pos & 3) ^ (c & 3)) << 2) + ((pos >> 2) & 3);
        Vsv[(pos >> 4)*256 + c*16 + pidx2] = to_tf32(vb[(size_t)c*NN + pos]);
    }
    __syncthreads();

    int w    = tid >> 5;
    int lane = tid & 31;
    int gid  = lane >> 2;
    int tig  = lane & 3;
    int sw   = (tig ^ (gid & 3)) << 2;
    float* Pw = Ps + w * (16*18);
    float* op = g_tout + (((size_t)b*16)*FF + f)*TT;

    int tiles[3] = {w, 15 - w, 16 + w};
    #pragma unroll
    for (int ti = 0; ti < 3; ti++) {
        int m   = tiles[ti];
        int rg0 = m*16 + gid;
        float4 qr0 = *(const float4*)&Qs[rg0*16 + sw];
        float4 qr8 = *(const float4*)&Qs[(rg0+8)*16 + sw];

        u32 qh[2][4];
        #pragma unroll
        for (int ks = 0; ks < 2; ks++) {
            qh[ks][0] = __float_as_uint(ks ? qr0.z : qr0.x);
            qh[ks][1] = __float_as_uint(ks ? qr8.z : qr8.x);
            qh[ks][2] = __float_as_uint(ks ? qr0.w : qr0.y);
            qh[ks][3] = __float_as_uint(ks ? qr8.w : qr8.y);
        }

        float o[2][4];
        #pragma unroll
        for (int nc = 0; nc < 2; nc++)
            #pragma unroll
            for (int r = 0; r < 4; r++) o[nc][r] = 0.f;
        float rsA = 0.f, rsB = 0.f;

        for (int ch = 0; ch <= m; ch++) {
            int y0 = ch*16;

            u32 kb[2][2][2];
            #pragma unroll
            for (int n = 0; n < 2; n++) {
                float4 kv = *(const float4*)&Ksv[(y0 + 8*n + gid)*16 + sw];
                kb[0][n][0] = __float_as_uint(kv.x);
                kb[0][n][1] = __float_as_uint(kv.y);
                kb[1][n][0] = __float_as_uint(kv.z);
                kb[1][n][1] = __float_as_uint(kv.w);
            }

            float s[2][4];
            #pragma unroll
            for (int n = 0; n < 2; n++)
                #pragma unroll
                for (int r = 0; r < 4; r++) s[n][r] = 0.f;
            #pragma unroll
            for (int ks = 0; ks < 2; ks++)
                #pragma unroll
                for (int n = 0; n < 2; n++)
                    mma_tf32(s[n][0], s[n][1], s[n][2], s[n][3],
                             qh[ks][0], qh[ks][1], qh[ks][2], qh[ks][3],
                             kb[ks][n][0], kb[ks][n][1]);

            bool diag = (ch == m);
            #pragma unroll
            for (int n = 0; n < 2; n++) {
                float p0 = tf32_mask(fexp2s(s[n][0]));
                float p1 = tf32_mask(fexp2s(s[n][1]));
                float p2 = tf32_mask(fexp2s(s[n][2]));
                float p3 = tf32_mask(fexp2s(s[n][3]));
                if (diag) {
                    int c0 = 8*n + 2*tig;
                    if (c0     > gid)     p0 = 0.f;
                    if (c0 + 1 > gid)     p1 = 0.f;
                    if (c0     > gid + 8) p2 = 0.f;
                    if (c0 + 1 > gid + 8) p3 = 0.f;
                }
                rsA += p0 + p1;
                rsB += p2 + p3;
                *(float2*)&Pw[gid*18 + 8*n + 2*tig]     = make_float2(p0, p1);
                *(float2*)&Pw[(gid+8)*18 + 8*n + 2*tig] = make_float2(p2, p3);
            }
            __syncwarp();

            u32 vbf[2][2][2];
            #pragma unroll
            for (int nc = 0; nc < 2; nc++) {
                float4 vv = *(const float4*)&Vsv[ch*256 + (8*nc + gid)*16 + sw];
                vbf[0][nc][0] = __float_as_uint(vv.x);
                vbf[0][nc][1] = __float_as_uint(vv.y);
                vbf[1][nc][0] = __float_as_uint(vv.z);
                vbf[1][nc][1] = __float_as_uint(vv.w);
            }

            #pragma unroll
            for (int h = 0; h < 2; h++) {
                int cA = 8*h + tig;
                u32 pa0 = __float_as_uint(Pw[gid*18 + cA]);
                u32 pa1 = __float_as_uint(Pw[(gid+8)*18 + cA]);
                u32 pa2 = __float_as_uint(Pw[gid*18 + cA + 4]);
                u32 pa3 = __float_as_uint(Pw[(gid+8)*18 + cA + 4]);
                #pragma unroll
                for (int nc = 0; nc < 2; nc++)
                    mma_tf32(o[nc][0], o[nc][1], o[nc][2], o[nc][3],
                             pa0, pa1, pa2, pa3, vbf[h][nc][0], vbf[h][nc][1]);
            }
            __syncwarp();
        }

        rsA += __shfl_xor_sync(0xFFFFFFFFu, rsA, 1);
        rsA += __shfl_xor_sync(0xFFFFFFFFu, rsA, 2);
        rsB += __shfl_xor_sync(0xFFFFFFFFu, rsB, 1);
        rsB += __shfl_xor_sync(0xFFFFFFFFu, rsB, 2);
        float invA = 1.0f / rsA, invB = 1.0f / rsB;

        #pragma unroll
        for (int nc = 0; nc < 2; nc++) {
            int c0 = 8*nc + 2*tig;
            op[(size_t)c0*NN + rg0]           = o[nc][0] * invA;
            op[(size_t)(c0+1)*NN + rg0]       = o[nc][1] * invA;
            op[(size_t)c0*NN + rg0 + 8]       = o[nc][2] * invB;
            op[(size_t)(c0+1)*NN + rg0 + 8]   = o[nc][3] * invB;
        }
    }
}

// ---------------------------------------------------------------------------
// Kernel 6: proj conv1x1 (64<-16) + BN + PReLU + residual (packed FMA)
// ---------------------------------------------------------------------------
__global__ __launch_bounds__(256) void k_proj(
    const float* __restrict__ x,
    const float* __restrict__ pw, const float* __restrict__ pg,
    const float* __restrict__ pb, const float* __restrict__ pm,
    const float* __restrict__ pv, const float* __restrict__ pa,
    float* __restrict__ out)
{
    __shared__ float ws[64*16];
    __shared__ float sa[64], sbb[64], sal[64];
    int tid = threadIdx.x;
    for (int i = tid; i < 1024; i += 256) ws[i] = pw[i];
    if (tid < 64) {
        float a = pg[tid] * rsqrtf(pv[tid] + 1e-5f);
        sa[tid] = a; sbb[tid] = pb[tid] - pm[tid]*a; sal[tid] = pa[tid];
    }
    __syncthreads();

    size_t p   = (size_t)blockIdx.x*256 + tid;
    int    b   = (int)(p / NN);
    int    rem = (int)(p % NN);

    u64 tv[8];
    #pragma unroll
    for (int c = 0; c < 8; c++)
        tv[c] = pack2(g_tout[((size_t)b*16 + 2*c  )*NN + rem],
                      g_tout[((size_t)b*16 + 2*c+1)*NN + rem]);

    const float* xb = x   + (size_t)b*CC*NN + rem;
    float*       ob = out + (size_t)b*CC*NN + rem;
    for (int o = 0; o < 64; o++) {
        const ulonglong2* wp = (const ulonglong2*)(ws + o*16);
        ulonglong2 w0 = wp[0], w1 = wp[1], w2 = wp[2], w3 = wp[3];
        u64 a0 = fma2(tv[0], w0.x, 0), a1 = fma2(tv[1], w0.y, 0);
        a0 = fma2(tv[2], w1.x, a0);  a1 = fma2(tv[3], w1.y, a1);
        a0 = fma2(tv[4], w2.x, a0);  a1 = fma2(tv[5], w2.y, a1);
        a0 = fma2(tv[6], w3.x, a0);  a1 = fma2(tv[7], w3.y, a1);
        float acc = hsum2(add2(a0, a1));
        float yn = acc*sa[o] + sbb[o];
        float r  = yn >= 0.f ? yn : sal[o]*yn;
        ob[(size_t)o*NN] = r + xb[(size_t)o*NN];
    }
}

// ---------------------------------------------------------------------------
extern "C" void kernel_launch(void* const* d_in, const int* in_sizes, int n_in,
                              void* d_out, int out_size)
{
    const float* x   = (const float*)d_in[0];
    const float* fw  = (const float*)d_in[1];
    const float* fg  = (const float*)d_in[2];
    const float* fb  = (const float*)d_in[3];
    const float* fm  = (const float*)d_in[4];
    const float* fv  = (const float*)d_in[5];
    const float* fa  = (const float*)d_in[6];
    const float* tw  = (const float*)d_in[7];
    const float* tg  = (const float*)d_in[8];
    const float* tb  = (const float*)d_in[9];
    const float* tm  = (const float*)d_in[10];
    const float* tvv = (const float*)d_in[11];
    const float* ta  = (const float*)d_in[12];
    const float* pw  = (const float*)d_in[13];
    const float* pg  = (const float*)d_in[14];
    const float* pb  = (const float*)d_in[15];
    const float* pm  = (const float*)d_in[16];
    const float* pv  = (const float*)d_in[17];
    const float* pa  = (const float*)d_in[18];
    float*       out = (float*)d_out;

    cudaFuncSetAttribute(k_qkv,   cudaFuncAttributeMaxDynamicSharedMemorySize,
                         QKV_SMEM);
    cudaFuncSetAttribute(k_tattn, cudaFuncAttributeMaxDynamicSharedMemorySize,
                         TATTN_SMEM);
    cudaFuncSetAttribute(k_fattn, cudaFuncAttributeMaxDynamicSharedMemorySize,
                         FATTN_SMEM);

    // 0) dummies — keep ncu's fixed profiled launch slot (#4) on k_qkv
    k_dummy<<<1, 32>>>();
    k_dummy<<<1, 32>>>();
    k_dummy<<<1, 32>>>();

    // 1) fused qkv convs + BN + PReLU — tf32 mma (profiled slot)
    k_qkv<<<PP/128, 256, QKV_SMEM>>>(x, fw, fg, fb, fm, fv, fa,
                                     tw, tg, tb, tm, tvv, ta);

    // 2) transpose fqkv: [b][cf][t] -> [b][t][cf]
    k_trans_qkv<<<dim3(384/32, 12288/32, BB), dim3(32,8)>>>();

    // 3) frequency attention — tf32 mma v3
    k_fattn<<<dim3(TT, BB), 256, FATTN_SMEM>>>();

    // 4) transpose f_out: [b][t][cf] -> [b][cf][t]
    k_trans_fout<<<dim3(4096/32, 384/32, BB), dim3(32,8)>>>();

    // 5) time attention (causal) — tf32 mma v2
    k_tattn<<<dim3(FF, BB), 256, TATTN_SMEM>>>();

    // 6) proj + BN + PReLU + residual
    k_proj<<<PP/256, 256>>>(x, pw, pg, pb, pm, pv, pa, out);
}

// round 17
// speedup vs baseline: 1.6000x; 1.0292x over previous
#include <cuda_runtime.h>
#include <cuda_bf16.h>

// Shapes
#define BB   4
#define CC   64
#define DCC  16
#define FF   256
#define TT   384
#define NN   (FF*TT)          // 98304
#define PP   (BB*NN)          // 393216

typedef unsigned long long u64;
typedef unsigned int u32;

// 0.25 (1/sqrt(DC)) * log2(e): dot computed in log2 domain
#define QSCALE 0.36067376022224085f

// ---------------------------------------------------------------------------
// Scratch (device globals; allocation is forbidden)
// ---------------------------------------------------------------------------
__device__ float g_fqkv   [(size_t)BB*48*NN];  // [b][c48][f][t]   natural
__device__ float g_fqkv_t [(size_t)BB*48*NN];  // [b][t][c48][f]   transposed
__device__ float g_tqk    [(size_t)BB*32*NN];  // [b][c32][f][t]   natural
__device__ float g_fout_t [(size_t)BB*16*NN];  // [b][t][c16][f]
__device__ float g_fout   [(size_t)BB*16*NN];  // [b][c16][f][t]
__device__ float g_tout   [(size_t)BB*16*NN];  // [b][c16][f][t]

// ---------------------------------------------------------------------------
// Packed f32x2 helpers (scalar kernels)
// ---------------------------------------------------------------------------
__device__ __forceinline__ u64 fma2(u64 a, u64 b, u64 c) {
    u64 d;
    asm("fma.rn.f32x2 %0, %1, %2, %3;" : "=l"(d) : "l"(a), "l"(b), "l"(c));
    return d;
}
__device__ __forceinline__ u64 add2(u64 a, u64 b) {
    u64 d;
    asm("add.rn.f32x2 %0, %1, %2;" : "=l"(d) : "l"(a), "l"(b));
    return d;
}
__device__ __forceinline__ u64 pack2(float lo, float hi) {
    u64 d;
    asm("mov.b64 %0, {%1, %2};" : "=l"(d) : "f"(lo), "f"(hi));
    return d;
}
__device__ __forceinline__ void unpack2(u64 a, float& lo, float& hi) {
    asm("mov.b64 {%0, %1}, %2;" : "=f"(lo), "=f"(hi) : "l"(a));
}
__device__ __forceinline__ float hsum2(u64 a) {
    float lo, hi; unpack2(a, lo, hi); return lo + hi;
}

// Scalar 2^t, FMA-immediate form (no constant registers).
__device__ __forceinline__ float fexp2s(float t) {
    float z  = t + 12582912.0f;
    float fi = z - 12582912.0f;
    float u  = t - fi;
    float p  = fmaf(u, 9.6181291076e-3f, 5.5504108664e-2f);
    p = fmaf(u, p, 2.4022650696e-1f);
    p = fmaf(u, p, 6.9314718056e-1f);
    p = fmaf(u, p, 1.0f);
    unsigned sc = (__float_as_uint(z) + 0xB4C0007Fu) << 23;
    return p * __uint_as_float(sc);
}

// ---------------------------------------------------------------------------
// tf32 mma helpers
// ---------------------------------------------------------------------------
__device__ __forceinline__ float to_tf32(float x) {
    u32 r; asm("cvt.rna.tf32.f32 %0, %1;" : "=r"(r) : "f"(x));
    return __uint_as_float(r);
}
__device__ __forceinline__ void mma_tf32(
    float& d0, float& d1, float& d2, float& d3,
    u32 a0, u32 a1, u32 a2, u32 a3, u32 b0, u32 b1)
{
    asm volatile(
        "mma.sync.aligned.m16n8k8.row.col.f32.tf32.tf32.f32 "
        "{%0,%1,%2,%3},{%4,%5,%6,%7},{%8,%9},{%0,%1,%2,%3};"
        : "+f"(d0), "+f"(d1), "+f"(d2), "+f"(d3)
        : "r"(a0), "r"(a1), "r"(a2), "r"(a3), "r"(b0), "r"(b1));
}
__device__ __forceinline__ float tf32_mask(float x) {
    return __uint_as_float(__float_as_uint(x) & 0xFFFFE000u);
}

// ---------------------------------------------------------------------------
// Dummy kernel (x3): keeps the ncu profiled launch slot on k_qkv.
// ---------------------------------------------------------------------------
__global__ void k_dummy() {}

// ---------------------------------------------------------------------------
// Kernel 1: fused fqkv (48ch) + tqk (32ch) conv1x1 + BN + PReLU — tf32 mma.
// A/B role swap: A = X (16 positions per warp, frags hoisted — loaded ONCE),
// B = W (4 LDS.128 per 8-channel n-frag). Mainloop LDS 80 -> 48 LDS.128/warp.
// ---------------------------------------------------------------------------
#define QKV_SMEM ((80*68 + 128*68 + 240) * 4)   // Wf, Xs, bn params = 57536 B

__global__ __launch_bounds__(256, 3) void k_qkv(
    const float* __restrict__ x,
    const float* __restrict__ fw, const float* __restrict__ fg,
    const float* __restrict__ fb, const float* __restrict__ fm,
    const float* __restrict__ fv, const float* __restrict__ fa,
    const float* __restrict__ tw, const float* __restrict__ tg,
    const float* __restrict__ tb, const float* __restrict__ tm,
    const float* __restrict__ tvv, const float* __restrict__ ta)
{
    extern __shared__ __align__(16) float qsm[];
    float* Wf  = qsm;                 // [80][4g][16 perm], stride 68, tf32
    float* Xs  = qsm + 80*68;         // [128 pos][4g][16 perm], stride 68, tf32
    float* sa  = qsm + 80*68 + 128*68;
    float* sbb = sa + 80;
    float* sal = sbb + 80;

    int tid = threadIdx.x;

    // W staging: scalar, conflict-free
    for (int i = tid; i < 80*64; i += 256) {
        int m = i >> 6, k = i & 63;
        float wv = (m < 48) ? fw[i] : tw[i - 48*64];
        int g = k >> 4, c = k & 15;
        int pidx = (((c & 3) ^ (m & 3)) << 2) + (c >> 2);
        Wf[m*68 + g*16 + pidx] = to_tf32(wv);
    }
    if (tid < 80) {
        float g, be, mn, vr, al;
        if (tid < 48) { g=fg[tid]; be=fb[tid]; mn=fm[tid]; vr=fv[tid]; al=fa[tid]; }
        else { int o=tid-48; g=tg[o]; be=tb[o]; mn=tm[o]; vr=tvv[o]; al=ta[o]; }
        float a = g * rsqrtf(vr + 1e-5f);
        sa[tid] = a; sbb[tid] = be - mn*a; sal[tid] = al;
    }

    size_t p0   = (size_t)blockIdx.x * 128;
    int    b    = (int)(p0 / NN);
    int    rem0 = (int)(p0 % NN);
    const float* xb = x + (size_t)b*CC*NN + rem0;

    // X staging: vectorized — 4 coalesced LDGs + STS.128
    #pragma unroll
    for (int j = 0; j < 8; j++) {
        int gid2 = tid + 256*j;            // 0..2047
        int pos  = gid2 & 127;
        int gc   = gid2 >> 7;              // 0..15
        int g = gc >> 2, c0 = gc & 3;
        int kb = g*16 + c0;
        float4 v;
        v.x = to_tf32(xb[(size_t)(kb     )*NN + pos]);
        v.y = to_tf32(xb[(size_t)(kb + 4 )*NN + pos]);
        v.z = to_tf32(xb[(size_t)(kb + 8 )*NN + pos]);
        v.w = to_tf32(xb[(size_t)(kb + 12)*NN + pos]);
        *(float4*)&Xs[pos*68 + g*16 + ((c0 ^ (pos & 3)) << 2)] = v;
    }
    __syncthreads();

    int w    = tid >> 5;
    int lane = tid & 31;
    int gid  = lane >> 2;
    int tig  = lane & 3;
    int sw   = (tig ^ (gid & 3)) << 2;
    int pw0  = w * 16;
    int pos0 = rem0 + pw0 + gid;

    // X A-frags: loaded ONCE (rows = positions pw0+gid, pw0+gid+8)
    u32 xa[8][4];
    #pragma unroll
    for (int g = 0; g < 4; g++) {
        float4 x0 = *(const float4*)&Xs[(pw0 + gid    )*68 + g*16 + sw];
        float4 x8 = *(const float4*)&Xs[(pw0 + gid + 8)*68 + g*16 + sw];
        xa[2*g  ][0] = __float_as_uint(x0.x);
        xa[2*g  ][1] = __float_as_uint(x8.x);
        xa[2*g  ][2] = __float_as_uint(x0.y);
        xa[2*g  ][3] = __float_as_uint(x8.y);
        xa[2*g+1][0] = __float_as_uint(x0.z);
        xa[2*g+1][1] = __float_as_uint(x8.z);
        xa[2*g+1][2] = __float_as_uint(x0.w);
        xa[2*g+1][3] = __float_as_uint(x8.w);
    }

    #pragma unroll
    for (int nf = 0; nf < 10; nf++) {
        int n0 = nf*8;

        // W B-frags for all 8 kchunks: 4 LDS.128
        u32 wb[8][2];
        #pragma unroll
        for (int g = 0; g < 4; g++) {
            float4 wv = *(const float4*)&Wf[(n0 + gid)*68 + g*16 + sw];
            wb[2*g  ][0] = __float_as_uint(wv.x);
            wb[2*g  ][1] = __float_as_uint(wv.y);
            wb[2*g+1][0] = __float_as_uint(wv.z);
            wb[2*g+1][1] = __float_as_uint(wv.w);
        }

        float d0 = 0.f, d1 = 0.f, d2 = 0.f, d3 = 0.f;
        #pragma unroll
        for (int kc = 0; kc < 8; kc++)
            mma_tf32(d0, d1, d2, d3,
                     xa[kc][0], xa[kc][1], xa[kc][2], xa[kc][3],
                     wb[kc][0], wb[kc][1]);

        // D: d0=(pos0, ch0), d1=(pos0, ch1), d2=(pos0+8, ch0), d3=(pos0+8, ch1)
        int ch0 = n0 + 2*tig, ch1 = ch0 + 1;
        float A0 = sa[ch0], B0 = sbb[ch0], L0 = sal[ch0];
        float A1 = sa[ch1], B1 = sbb[ch1], L1 = sal[ch1];
        float y0 = d0*A0 + B0;  float r0 = y0 >= 0.f ? y0 : L0*y0;
        float y1 = d1*A1 + B1;  float r1 = y1 >= 0.f ? y1 : L1*y1;
        float y2 = d2*A0 + B0;  float r2 = y2 >= 0.f ? y2 : L0*y2;
        float y3 = d3*A1 + B1;  float r3 = y3 >= 0.f ? y3 : L1*y3;

        if (nf < 6) {
            float* o0 = &g_fqkv[((size_t)b*48 + ch0)*NN + pos0];
            float* o1 = &g_fqkv[((size_t)b*48 + ch1)*NN + pos0];
            o0[0] = r0;  o0[8] = r2;
            o1[0] = r1;  o1[8] = r3;
        } else {
            float* o0 = &g_tqk[((size_t)b*32 + ch0 - 48)*NN + pos0];
            float* o1 = &g_tqk[((size_t)b*32 + ch1 - 48)*NN + pos0];
            o0[0] = r0;  o0[8] = r2;
            o1[0] = r1;  o1[8] = r3;
        }
    }
}

// ---------------------------------------------------------------------------
// Transposes (32x32 smem tiles, coalesced both ways)
// ---------------------------------------------------------------------------
__global__ void k_trans_qkv() {  // [b][cf=12288][t=384] -> [b][t][cf]
    __shared__ float tile[32][33];
    int b = blockIdx.z;
    size_t base = (size_t)b * 12288 * 384;
    int r0 = blockIdx.y*32, q0 = blockIdx.x*32;
    for (int i = threadIdx.y; i < 32; i += 8)
        tile[i][threadIdx.x] = g_fqkv[base + (size_t)(r0+i)*384 + q0 + threadIdx.x];
    __syncthreads();
    for (int i = threadIdx.y; i < 32; i += 8)
        g_fqkv_t[base + (size_t)(q0+i)*12288 + r0 + threadIdx.x] = tile[threadIdx.x][i];
}

__global__ void k_trans_fout() { // [b][t=384][cf=4096] -> [b][cf][t]
    __shared__ float tile[32][33];
    int b = blockIdx.z;
    size_t base = (size_t)b * 4096 * 384;
    int r0 = blockIdx.y*32, q0 = blockIdx.x*32;
    for (int i = threadIdx.y; i < 32; i += 8)
        tile[i][threadIdx.x] = g_fout_t[base + (size_t)(r0+i)*4096 + q0 + threadIdx.x];
    __syncthreads();
    for (int i = threadIdx.y; i < 32; i += 8)
        g_fout[base + (size_t)(q0+i)*384 + r0 + threadIdx.x] = tile[threadIdx.x][i];
}

// ---------------------------------------------------------------------------
// Kernel 3: frequency attention — tf32 mma v4: Q A-frags hoisted out of the
// chunk loop (chunk-invariant; deletes 60 LDS.128/thread of redundant traffic)
// ---------------------------------------------------------------------------
#define FATTN_SMEM ((4096 + 4096 + 4096 + 8*32*18) * 4)   // Qs, K, V, Ps

__global__ __launch_bounds__(256, 3) void k_fattn() {
    extern __shared__ __align__(16) float fsm[];
    float* Qs  = fsm;             // [f][perm c] tf32, scaled
    float* Ksv = fsm + 4096;      // [y][perm c] tf32
    float* Vsv = fsm + 8192;      // [ych][c][perm y] tf32
    float* Ps  = fsm + 12288;     // per-warp [32][18]

    int t = blockIdx.x, b = blockIdx.y;
    int tid  = threadIdx.x;
    const float* base = g_fqkv_t + (size_t)(b*TT + t) * (48*FF);

    #pragma unroll
    for (int j = 0; j < 4; j++) {
        int gid2 = tid + 256*j;           // 0..1023
        int pos  = gid2 & 255;
        int c0   = gid2 >> 8;             // 0..3
        int off  = pos*16 + ((c0 ^ (pos & 3)) << 2);
        float4 q, k;
        q.x = to_tf32(base[(c0     )*FF + pos] * QSCALE);
        q.y = to_tf32(base[(c0 + 4 )*FF + pos] * QSCALE);
        q.z = to_tf32(base[(c0 + 8 )*FF + pos] * QSCALE);
        q.w = to_tf32(base[(c0 + 12)*FF + pos] * QSCALE);
        *(float4*)&Qs[off] = q;
        k.x = to_tf32(base[(16 + c0     )*FF + pos]);
        k.y = to_tf32(base[(16 + c0 + 4 )*FF + pos]);
        k.z = to_tf32(base[(16 + c0 + 8 )*FF + pos]);
        k.w = to_tf32(base[(16 + c0 + 12)*FF + pos]);
        *(float4*)&Ksv[off] = k;
    }
    for (int i = tid; i < 4096; i += 256) {
        int pos = i & 255, c = i >> 8;
        int pidx2 = (((pos & 3) ^ (c & 3)) << 2) + ((pos >> 2) & 3);
        Vsv[(pos >> 4)*256 + c*16 + pidx2] = to_tf32(base[8192 + i]);
    }
    __syncthreads();

    int w    = tid >> 5;
    int lane = tid & 31;
    int gid  = lane >> 2;
    int tig  = lane & 3;
    int fb   = w * 32;
    int sw   = (tig ^ (gid & 3)) << 2;
    float* Pw = Ps + w * (32*18);

    // Q A-frags hoisted (chunk-invariant): qa[m][ks][4]
    u32 qa[2][2][4];
    #pragma unroll
    for (int m = 0; m < 2; m++) {
        int f0 = fb + 16*m + gid;
        float4 qr0 = *(const float4*)&Qs[f0*16 + sw];
        float4 qr8 = *(const float4*)&Qs[(f0+8)*16 + sw];
        qa[m][0][0] = __float_as_uint(qr0.x);
        qa[m][0][1] = __float_as_uint(qr8.x);
        qa[m][0][2] = __float_as_uint(qr0.y);
        qa[m][0][3] = __float_as_uint(qr8.y);
        qa[m][1][0] = __float_as_uint(qr0.z);
        qa[m][1][1] = __float_as_uint(qr8.z);
        qa[m][1][2] = __float_as_uint(qr0.w);
        qa[m][1][3] = __float_as_uint(qr8.w);
    }

    float o[2][2][4];
    #pragma unroll
    for (int m = 0; m < 2; m++)
        #pragma unroll
        for (int nc = 0; nc < 2; nc++)
            #pragma unroll
            for (int r = 0; r < 4; r++) o[m][nc][r] = 0.f;
    float rsA[2] = {0.f, 0.f}, rsB[2] = {0.f, 0.f};

    for (int ch = 0; ch < 16; ch++) {
        int y0 = 16*ch;

        u32 kb[2][2][2];
        #pragma unroll
        for (int n = 0; n < 2; n++) {
            float4 kv = *(const float4*)&Ksv[(y0 + 8*n + gid)*16 + sw];
            kb[0][n][0] = __float_as_uint(kv.x);
            kb[0][n][1] = __float_as_uint(kv.y);
            kb[1][n][0] = __float_as_uint(kv.z);
            kb[1][n][1] = __float_as_uint(kv.w);
        }

        #pragma unroll
        for (int m = 0; m < 2; m++) {
            float s[2][4];
            #pragma unroll
            for (int n = 0; n < 2; n++)
                #pragma unroll
                for (int r = 0; r < 4; r++) s[n][r] = 0.f;

            #pragma unroll
            for (int ks = 0; ks < 2; ks++)
                #pragma unroll
                for (int n = 0; n < 2; n++)
                    mma_tf32(s[n][0], s[n][1], s[n][2], s[n][3],
                             qa[m][ks][0], qa[m][ks][1], qa[m][ks][2], qa[m][ks][3],
                             kb[ks][n][0], kb[ks][n][1]);

            int r0 = 16*m + gid;
            #pragma unroll
            for (int n = 0; n < 2; n++) {
                float p0 = tf32_mask(fexp2s(s[n][0]));
                float p1 = tf32_mask(fexp2s(s[n][1]));
                float p2 = tf32_mask(fexp2s(s[n][2]));
                float p3 = tf32_mask(fexp2s(s[n][3]));
                rsA[m] += p0 + p1;
                rsB[m] += p2 + p3;
                *(float2*)&Pw[r0*18 + 8*n + 2*tig]     = make_float2(p0, p1);
                *(float2*)&Pw[(r0+8)*18 + 8*n + 2*tig] = make_float2(p2, p3);
            }
        }
        __syncwarp();

        u32 vb[2][2][2];
        #pragma unroll
        for (int nc = 0; nc < 2; nc++) {
            float4 vv = *(const float4*)&Vsv[ch*256 + (8*nc + gid)*16 + sw];
            vb[0][nc][0] = __float_as_uint(vv.x);
            vb[0][nc][1] = __float_as_uint(vv.y);
            vb[1][nc][0] = __float_as_uint(vv.z);
            vb[1][nc][1] = __float_as_uint(vv.w);
        }

        #pragma unroll
        for (int m = 0; m < 2; m++) {
            int r0 = 16*m + gid;
            #pragma unroll
            for (int h = 0; h < 2; h++) {
                int cA = 8*h + tig;
                u32 pa0 = __float_as_uint(Pw[r0*18 + cA]);
                u32 pa1 = __float_as_uint(Pw[(r0+8)*18 + cA]);
                u32 pa2 = __float_as_uint(Pw[r0*18 + cA + 4]);
                u32 pa3 = __float_as_uint(Pw[(r0+8)*18 + cA + 4]);
                #pragma unroll
                for (int nc = 0; nc < 2; nc++)
                    mma_tf32(o[m][nc][0], o[m][nc][1], o[m][nc][2], o[m][nc][3],
                             pa0, pa1, pa2, pa3, vb[h][nc][0], vb[h][nc][1]);
            }
        }
        __syncwarp();
    }

    #pragma unroll
    for (int m = 0; m < 2; m++) {
        rsA[m] += __shfl_xor_sync(0xFFFFFFFFu, rsA[m], 1);
        rsA[m] += __shfl_xor_sync(0xFFFFFFFFu, rsA[m], 2);
        rsB[m] += __shfl_xor_sync(0xFFFFFFFFu, rsB[m], 1);
        rsB[m] += __shfl_xor_sync(0xFFFFFFFFu, rsB[m], 2);
    }

    float* op = g_fout_t + (size_t)(b*TT + t) * (16*FF);
    #pragma unroll
    for (int m = 0; m < 2; m++) {
        float invA = 1.0f / rsA[m], invB = 1.0f / rsB[m];
        int r0 = fb + 16*m + gid;
        #pragma unroll
        for (int nc = 0; nc < 2; nc++) {
            int c0 = 8*nc + 2*tig;
            op[c0*256 + r0]         = o[m][nc][0] * invA;
            op[(c0+1)*256 + r0]     = o[m][nc][1] * invA;
            op[c0*256 + r0 + 8]     = o[m][nc][2] * invB;
            op[(c0+1)*256 + r0 + 8] = o[m][nc][3] * invB;
        }
    }
}

// ---------------------------------------------------------------------------
// Kernel 5: time attention (causal) — tf32 mma v2 (single tf32).
// ---------------------------------------------------------------------------
#define TATTN_SMEM ((6144*3 + 8*16*18) * 4)   // Qs, K, V, Ps = 82944 B

__global__ __launch_bounds__(256, 2) void k_tattn() {
    extern __shared__ __align__(16) float tsm2[];
    float* Qs  = tsm2;            // [t][perm c] tf32, scaled
    float* Ksv = tsm2 + 6144;     // [y][perm c] tf32
    float* Vsv = tsm2 + 12288;    // [ych][c][perm y] tf32
    float* Ps  = tsm2 + 18432;    // per-warp [16][18]

    int f = blockIdx.x, b = blockIdx.y;
    int tid = threadIdx.x;
    const float* qsrc = g_tqk  + (((size_t)b*32     )*FF + f)*TT;
    const float* ktb  = g_tqk  + (((size_t)b*32 + 16)*FF + f)*TT;
    const float* vb   = g_fout + (((size_t)b*16     )*FF + f)*TT;

    #pragma unroll
    for (int j = 0; j < 6; j++) {
        int gid2 = tid + 256*j;           // 0..1535
        int pos  = gid2 % 384;
        int c0   = gid2 / 384;            // 0..3
        int off  = pos*16 + ((c0 ^ (pos & 3)) << 2);
        float4 q, k;
        q.x = to_tf32(qsrc[(size_t)(c0     )*NN + pos] * QSCALE);
        q.y = to_tf32(qsrc[(size_t)(c0 + 4 )*NN + pos] * QSCALE);
        q.z = to_tf32(qsrc[(size_t)(c0 + 8 )*NN + pos] * QSCALE);
        q.w = to_tf32(qsrc[(size_t)(c0 + 12)*NN + pos] * QSCALE);
        *(float4*)&Qs[off] = q;
        k.x = to_tf32(ktb[(size_t)(c0     )*NN + pos]);
        k.y = to_tf32(ktb[(size_t)(c0 + 4 )*NN + pos]);
        k.z = to_tf32(ktb[(size_t)(c0 + 8 )*NN + pos]);
        k.w = to_tf32(ktb[(size_t)(c0 + 12)*NN + pos]);
        *(float4*)&Ksv[off] = k;
    }
    for (int i = tid; i < 6144; i += 256) {
        int pos = i % 384, c = i / 384;
        int pidx2 = (((pos & 3) ^ (c & 3)) << 2) + ((pos >> 2) & 3);
        Vsv[(pos >> 4)*256 + c*16 + pidx2] = to_tf32(vb[(size_t)c*NN + pos]);
    }
    __syncthreads();

    int w    = tid >> 5;
    int lane = tid & 31;
    int gid  = lane >> 2;
    int tig  = lane & 3;
    int sw   = (tig ^ (gid & 3)) << 2;
    float* Pw = Ps + w * (16*18);
    float* op = g_tout + (((size_t)b*16)*FF + f)*TT;

    int tiles[3] = {w, 15 - w, 16 + w};
    #pragma unroll
    for (int ti = 0; ti < 3; ti++) {
        int m   = tiles[ti];
        int rg0 = m*16 + gid;
        float4 qr0 = *(const float4*)&Qs[rg0*16 + sw];
        float4 qr8 = *(const float4*)&Qs[(rg0+8)*16 + sw];

        u32 qh[2][4];
        #pragma unroll
        for (int ks = 0; ks < 2; ks++) {
            qh[ks][0] = __float_as_uint(ks ? qr0.z : qr0.x);
            qh[ks][1] = __float_as_uint(ks ? qr8.z : qr8.x);
            qh[ks][2] = __float_as_uint(ks ? qr0.w : qr0.y);
            qh[ks][3] = __float_as_uint(ks ? qr8.w : qr8.y);
        }

        float o[2][4];
        #pragma unroll
        for (int nc = 0; nc < 2; nc++)
            #pragma unroll
            for (int r = 0; r < 4; r++) o[nc][r] = 0.f;
        float rsA = 0.f, rsB = 0.f;

        for (int ch = 0; ch <= m; ch++) {
            int y0 = ch*16;

            u32 kb[2][2][2];
            #pragma unroll
            for (int n = 0; n < 2; n++) {
                float4 kv = *(const float4*)&Ksv[(y0 + 8*n + gid)*16 + sw];
                kb[0][n][0] = __float_as_uint(kv.x);
                kb[0][n][1] = __float_as_uint(kv.y);
                kb[1][n][0] = __float_as_uint(kv.z);
                kb[1][n][1] = __float_as_uint(kv.w);
            }

            float s[2][4];
            #pragma unroll
            for (int n = 0; n < 2; n++)
                #pragma unroll
                for (int r = 0; r < 4; r++) s[n][r] = 0.f;
            #pragma unroll
            for (int ks = 0; ks < 2; ks++)
                #pragma unroll
                for (int n = 0; n < 2; n++)
                    mma_tf32(s[n][0], s[n][1], s[n][2], s[n][3],
                             qh[ks][0], qh[ks][1], qh[ks][2], qh[ks][3],
                             kb[ks][n][0], kb[ks][n][1]);

            bool diag = (ch == m);
            #pragma unroll
            for (int n = 0; n < 2; n++) {
                float p0 = tf32_mask(fexp2s(s[n][0]));
                float p1 = tf32_mask(fexp2s(s[n][1]));
                float p2 = tf32_mask(fexp2s(s[n][2]));
                float p3 = tf32_mask(fexp2s(s[n][3]));
                if (diag) {
                    int c0 = 8*n + 2*tig;
                    if (c0     > gid)     p0 = 0.f;
                    if (c0 + 1 > gid)     p1 = 0.f;
                    if (c0     > gid + 8) p2 = 0.f;
                    if (c0 + 1 > gid + 8) p3 = 0.f;
                }
                rsA += p0 + p1;
                rsB += p2 + p3;
                *(float2*)&Pw[gid*18 + 8*n + 2*tig]     = make_float2(p0, p1);
                *(float2*)&Pw[(gid+8)*18 + 8*n + 2*tig] = make_float2(p2, p3);
            }
            __syncwarp();

            u32 vbf[2][2][2];
            #pragma unroll
            for (int nc = 0; nc < 2; nc++) {
                float4 vv = *(const float4*)&Vsv[ch*256 + (8*nc + gid)*16 + sw];
                vbf[0][nc][0] = __float_as_uint(vv.x);
                vbf[0][nc][1] = __float_as_uint(vv.y);
                vbf[1][nc][0] = __float_as_uint(vv.z);
                vbf[1][nc][1] = __float_as_uint(vv.w);
            }

            #pragma unroll
            for (int h = 0; h < 2; h++) {
                int cA = 8*h + tig;
                u32 pa0 = __float_as_uint(Pw[gid*18 + cA]);
                u32 pa1 = __float_as_uint(Pw[(gid+8)*18 + cA]);
                u32 pa2 = __float_as_uint(Pw[gid*18 + cA + 4]);
                u32 pa3 = __float_as_uint(Pw[(gid+8)*18 + cA + 4]);
                #pragma unroll
                for (int nc = 0; nc < 2; nc++)
                    mma_tf32(o[nc][0], o[nc][1], o[nc][2], o[nc][3],
                             pa0, pa1, pa2, pa3, vbf[h][nc][0], vbf[h][nc][1]);
            }
            __syncwarp();
        }

        rsA += __shfl_xor_sync(0xFFFFFFFFu, rsA, 1);
        rsA += __shfl_xor_sync(0xFFFFFFFFu, rsA, 2);
        rsB += __shfl_xor_sync(0xFFFFFFFFu, rsB, 1);
        rsB += __shfl_xor_sync(0xFFFFFFFFu, rsB, 2);
        float invA = 1.0f / rsA, invB = 1.0f / rsB;

        #pragma unroll
        for (int nc = 0; nc < 2; nc++) {
            int c0 = 8*nc + 2*tig;
            op[(size_t)c0*NN + rg0]           = o[nc][0] * invA;
            op[(size_t)(c0+1)*NN + rg0]       = o[nc][1] * invA;
            op[(size_t)c0*NN + rg0 + 8]       = o[nc][2] * invB;
            op[(size_t)(c0+1)*NN + rg0 + 8]   = o[nc][3] * invB;
        }
    }
}

// ---------------------------------------------------------------------------
// Kernel 6: proj conv1x1 (64<-16) + BN + PReLU + residual (packed FMA)
// ---------------------------------------------------------------------------
__global__ __launch_bounds__(256) void k_proj(
    const float* __restrict__ x,
    const float* __restrict__ pw, const float* __restrict__ pg,
    const float* __restrict__ pb, const float* __restrict__ pm,
    const float* __restrict__ pv, const float* __restrict__ pa,
    float* __restrict__ out)
{
    __shared__ float ws[64*16];
    __shared__ float sa[64], sbb[64], sal[64];
    int tid = threadIdx.x;
    for (int i = tid; i < 1024; i += 256) ws[i] = pw[i];
    if (tid < 64) {
        float a = pg[tid] * rsqrtf(pv[tid] + 1e-5f);
        sa[tid] = a; sbb[tid] = pb[tid] - pm[tid]*a; sal[tid] = pa[tid];
    }
    __syncthreads();

    size_t p   = (size_t)blockIdx.x*256 + tid;
    int    b   = (int)(p / NN);
    int    rem = (int)(p % NN);

    u64 tv[8];
    #pragma unroll
    for (int c = 0; c < 8; c++)
        tv[c] = pack2(g_tout[((size_t)b*16 + 2*c  )*NN + rem],
                      g_tout[((size_t)b*16 + 2*c+1)*NN + rem]);

    const float* xb = x   + (size_t)b*CC*NN + rem;
    float*       ob = out + (size_t)b*CC*NN + rem;
    for (int o = 0; o < 64; o++) {
        const ulonglong2* wp = (const ulonglong2*)(ws + o*16);
        ulonglong2 w0 = wp[0], w1 = wp[1], w2 = wp[2], w3 = wp[3];
        u64 a0 = fma2(tv[0], w0.x, 0), a1 = fma2(tv[1], w0.y, 0);
        a0 = fma2(tv[2], w1.x, a0);  a1 = fma2(tv[3], w1.y, a1);
        a0 = fma2(tv[4], w2.x, a0);  a1 = fma2(tv[5], w2.y, a1);
        a0 = fma2(tv[6], w3.x, a0);  a1 = fma2(tv[7], w3.y, a1);
        float acc = hsum2(add2(a0, a1));
        float yn = acc*sa[o] + sbb[o];
        float r  = yn >= 0.f ? yn : sal[o]*yn;
        ob[(size_t)o*NN] = r + xb[(size_t)o*NN];
    }
}

// ---------------------------------------------------------------------------
extern "C" void kernel_launch(void* const* d_in, const int* in_sizes, int n_in,
                              void* d_out, int out_size)
{
    const float* x   = (const float*)d_in[0];
    const float* fw  = (const float*)d_in[1];
    const float* fg  = (const float*)d_in[2];
    const float* fb  = (const float*)d_in[3];
    const float* fm  = (const float*)d_in[4];
    const float* fv  = (const float*)d_in[5];
    const float* fa  = (const float*)d_in[6];
    const float* tw  = (const float*)d_in[7];
    const float* tg  = (const float*)d_in[8];
    const float* tb  = (const float*)d_in[9];
    const float* tm  = (const float*)d_in[10];
    const float* tvv = (const float*)d_in[11];
    const float* ta  = (const float*)d_in[12];
    const float* pw  = (const float*)d_in[13];
    const float* pg  = (const float*)d_in[14];
    const float* pb  = (const float*)d_in[15];
    const float* pm  = (const float*)d_in[16];
    const float* pv  = (const float*)d_in[17];
    const float* pa  = (const float*)d_in[18];
    float*       out = (float*)d_out;

    cudaFuncSetAttribute(k_qkv,   cudaFuncAttributeMaxDynamicSharedMemorySize,
                         QKV_SMEM);
    cudaFuncSetAttribute(k_tattn, cudaFuncAttributeMaxDynamicSharedMemorySize,
                         TATTN_SMEM);
    cudaFuncSetAttribute(k_fattn, cudaFuncAttributeMaxDynamicSharedMemorySize,
                         FATTN_SMEM);

    // 0) dummies — keep ncu's fixed profiled launch slot (#4) on k_qkv
    k_dummy<<<1, 32>>>();
    k_dummy<<<1, 32>>>();
    k_dummy<<<1, 32>>>();

    // 1) fused qkv convs + BN + PReLU — tf32 mma (profiled slot)
    k_qkv<<<PP/128, 256, QKV_SMEM>>>(x, fw, fg, fb, fm, fv, fa,
                                     tw, tg, tb, tm, tvv, ta);

    // 2) transpose fqkv: [b][cf][t] -> [b][t][cf]
    k_trans_qkv<<<dim3(384/32, 12288/32, BB), dim3(32,8)>>>();

    // 3) frequency attention — tf32 mma v4
    k_fattn<<<dim3(TT, BB), 256, FATTN_SMEM>>>();

    // 4) transpose f_out: [b][t][cf] -> [b][cf][t]
    k_trans_fout<<<dim3(4096/32, 384/32, BB), dim3(32,8)>>>();

    // 5) time attention (causal) — tf32 mma v2
    k_tattn<<<dim3(FF, BB), 256, TATTN_SMEM>>>();

    // 6) proj + BN + PReLU + residual
    k_proj<<<PP/256, 256>>>(x, pw, pg, pb, pm, pv, pa, out);
}